// round 1
// baseline (speedup 1.0000x reference)
#include <cuda_runtime.h>
#include <math.h>

#define N_NODES 20000
#define N_EDGES 60000
#define N_GRAPH 512
#define F_INP   7
#define HC      1024
#define NH      4
#define CH      256

// ---------------- scratch (static device globals; no allocation) -------------
__device__ float g_X[(size_t)N_NODES * HC];   // layer input / output
__device__ float g_T[(size_t)N_NODES * HC];   // transformed h = X @ W
__device__ float g_asrc[N_NODES * NH];
__device__ float g_adst[N_NODES * NH];
__device__ float g_ae_all[4 * N_EDGES * NH];  // per-layer edge attention term
__device__ float g_ve[48];                    // [l][d][h] = l*12 + d*4 + h
__device__ float g_ae_self[16];               // [l][h]
__device__ float g_eamean[3];
__device__ int   g_cnt[N_NODES];
__device__ int   g_rowptr[N_NODES + 1];
__device__ int   g_cursor[N_NODES];
__device__ int   g_eid[N_EDGES];
__device__ int   g_esrc[N_EDGES];
__device__ float g_gate[N_NODES];
__device__ float g_graph[N_GRAPH * CH];

__device__ __forceinline__ float lrelu(float a) { return a > 0.f ? a : 0.2f * a; }

// ---------------- edge_attr mean --------------------------------------------
__global__ void k_edge_mean(const float* __restrict__ ea) {
    __shared__ float red[3][256];
    int tid = threadIdx.x;
    float a0 = 0.f, a1 = 0.f, a2 = 0.f;
    for (int e = tid; e < N_EDGES; e += 256) {
        a0 += ea[e * 3 + 0];
        a1 += ea[e * 3 + 1];
        a2 += ea[e * 3 + 2];
    }
    red[0][tid] = a0; red[1][tid] = a1; red[2][tid] = a2;
    __syncthreads();
    for (int s = 128; s > 0; s >>= 1) {
        if (tid < s) {
            red[0][tid] += red[0][tid + s];
            red[1][tid] += red[1][tid + s];
            red[2][tid] += red[2][tid + s];
        }
        __syncthreads();
    }
    if (tid < 3) g_eamean[tid] = red[tid][0] * (1.f / (float)N_EDGES);
}

// ---------------- ve[l][d][h] = We[l][d, h*C:(h+1)*C] . a_e[l][h] -----------
__global__ void k_ve(const float* __restrict__ w_edge, const float* __restrict__ att_edge) {
    int tid = threadIdx.x;
    int warp = tid >> 5, lane = tid & 31;
    for (int idx = warp; idx < 48; idx += 8) {
        int l = idx / 12, r = idx % 12, d = r / 4, h = r % 4;
        const float* w = w_edge + (size_t)l * 3 * HC + (size_t)d * HC + h * CH;
        const float* a = att_edge + (size_t)l * HC + h * CH;
        float s = 0.f;
        for (int c = lane; c < CH; c += 32) s += w[c] * a[c];
        #pragma unroll
        for (int o = 16; o > 0; o >>= 1) s += __shfl_down_sync(0xffffffffu, s, o);
        if (lane == 0) g_ve[idx] = s;
    }
    __syncthreads();
    if (tid < 16) {
        int l = tid >> 2, h = tid & 3;
        float s = 0.f;
        for (int d = 0; d < 3; d++) s += g_eamean[d] * g_ve[l * 12 + d * 4 + h];
        g_ae_self[tid] = s;
    }
}

// ---------------- alpha_e for all layers / edges -----------------------------
__global__ void k_ae_all(const float* __restrict__ ea) {
    int e = blockIdx.x * blockDim.x + threadIdx.x;
    if (e >= N_EDGES) return;
    float a0 = ea[e * 3 + 0], a1 = ea[e * 3 + 1], a2 = ea[e * 3 + 2];
    #pragma unroll
    for (int l = 0; l < 4; l++) {
        #pragma unroll
        for (int h = 0; h < 4; h++) {
            float v = a0 * g_ve[l * 12 + 0 + h] + a1 * g_ve[l * 12 + 4 + h] + a2 * g_ve[l * 12 + 8 + h];
            g_ae_all[(size_t)l * N_EDGES * 4 + e * 4 + h] = v;
        }
    }
}

// ---------------- CSR build (counting sort by dst) ---------------------------
__global__ void k_zero_cnt() {
    int n = blockIdx.x * blockDim.x + threadIdx.x;
    if (n < N_NODES) g_cnt[n] = 0;
}
__global__ void k_count(const int* __restrict__ ei) {
    int e = blockIdx.x * blockDim.x + threadIdx.x;
    if (e >= N_EDGES) return;
    atomicAdd(&g_cnt[ei[N_EDGES + e]], 1);
}
__global__ void k_scan() {
    __shared__ int ssum[1024];
    const int SEG = 20;
    int tid = threadIdx.x;
    int base = tid * SEG;
    int cnts[SEG];
    int tot = 0;
    #pragma unroll
    for (int j = 0; j < SEG; j++) {
        int idx = base + j;
        cnts[j] = (idx < N_NODES) ? g_cnt[idx] : 0;
        tot += cnts[j];
    }
    ssum[tid] = tot;
    __syncthreads();
    for (int off = 1; off < 1024; off <<= 1) {
        int v = (tid >= off) ? ssum[tid - off] : 0;
        __syncthreads();
        ssum[tid] += v;
        __syncthreads();
    }
    int run = ssum[tid] - tot;  // exclusive prefix
    #pragma unroll
    for (int j = 0; j < SEG; j++) {
        int idx = base + j;
        if (idx < N_NODES) {
            g_rowptr[idx] = run;
            g_cursor[idx] = run;
            run += cnts[j];
        } else if (idx == N_NODES) {
            g_rowptr[N_NODES] = run;
        }
    }
}
__global__ void k_scatter(const int* __restrict__ ei) {
    int e = blockIdx.x * blockDim.x + threadIdx.x;
    if (e >= N_EDGES) return;
    int src = ei[e];
    int dst = ei[N_EDGES + e];
    int pos = atomicAdd(&g_cursor[dst], 1);
    g_eid[pos] = e;
    g_esrc[pos] = src;
}

// ---------------- layer-0 GEMM: T = x(N,7) @ w0(7,1024) ----------------------
__global__ void k_gemm0(const float* __restrict__ x, const float* __restrict__ w0) {
    __shared__ float xr[F_INP];
    int n = blockIdx.x, tid = threadIdx.x;
    if (tid < F_INP) xr[tid] = x[n * F_INP + tid];
    __syncthreads();
    #pragma unroll
    for (int j = 0; j < 4; j++) {
        int f = tid + j * 256;
        float acc = 0.f;
        #pragma unroll
        for (int d = 0; d < F_INP; d++) acc += xr[d] * w0[d * HC + f];
        g_T[(size_t)n * HC + f] = acc;
    }
}

// ---------------- SGEMM: T = X(N,1024) @ W(1024,1024) ------------------------
__global__ __launch_bounds__(256) void k_sgemm(const float* __restrict__ B) {
    const int K = 1024, LDN = 1024;
    __shared__ float As[8][128];
    __shared__ float Bs[8][128];
    int tid = threadIdx.x;
    int bx = blockIdx.x;  // N tile
    int by = blockIdx.y;  // M tile
    int tx = tid & 15, ty = tid >> 4;
    int aRow = tid >> 1;
    int aCol = (tid & 1) * 4;
    int bRow = tid >> 5;
    int bCol = (tid & 31) * 4;
    int gRowA = by * 128 + aRow;
    bool aValid = gRowA < N_NODES;
    const float* Aptr = g_X + (size_t)gRowA * K + aCol;
    const float* Bptr = B + (size_t)bRow * LDN + bx * 128 + bCol;
    float acc[8][8];
    #pragma unroll
    for (int i = 0; i < 8; i++)
        #pragma unroll
        for (int j = 0; j < 8; j++) acc[i][j] = 0.f;

    for (int k0 = 0; k0 < K; k0 += 8) {
        float4 av = aValid ? *(const float4*)(Aptr + k0) : make_float4(0.f, 0.f, 0.f, 0.f);
        float4 bv = *(const float4*)(Bptr + (size_t)k0 * LDN);
        As[aCol + 0][aRow] = av.x;
        As[aCol + 1][aRow] = av.y;
        As[aCol + 2][aRow] = av.z;
        As[aCol + 3][aRow] = av.w;
        *(float4*)&Bs[bRow][bCol] = bv;
        __syncthreads();
        #pragma unroll
        for (int k = 0; k < 8; k++) {
            float ra[8], rb[8];
            #pragma unroll
            for (int i = 0; i < 8; i++) ra[i] = As[k][ty * 8 + i];
            #pragma unroll
            for (int j = 0; j < 8; j++) rb[j] = Bs[k][tx * 8 + j];
            #pragma unroll
            for (int i = 0; i < 8; i++)
                #pragma unroll
                for (int j = 0; j < 8; j++) acc[i][j] += ra[i] * rb[j];
        }
        __syncthreads();
    }
    #pragma unroll
    for (int i = 0; i < 8; i++) {
        int row = by * 128 + ty * 8 + i;
        if (row < N_NODES) {
            float* Cp = g_T + (size_t)row * LDN + bx * 128 + tx * 8;
            *(float4*)Cp = make_float4(acc[i][0], acc[i][1], acc[i][2], acc[i][3]);
            *(float4*)(Cp + 4) = make_float4(acc[i][4], acc[i][5], acc[i][6], acc[i][7]);
        }
    }
}

// ---------------- per-node alpha_src / alpha_dst ------------------------------
__global__ void k_alpha(const float* __restrict__ att_src, const float* __restrict__ att_dst, int l) {
    int n = blockIdx.x;
    int warp = threadIdx.x >> 5, lane = threadIdx.x & 31;  // warp = head
    const float* hr = g_T + (size_t)n * HC + warp * CH;
    const float* as = att_src + (size_t)l * HC + warp * CH;
    const float* ad = att_dst + (size_t)l * HC + warp * CH;
    float s1 = 0.f, s2 = 0.f;
    for (int c = lane; c < CH; c += 32) {
        float v = hr[c];
        s1 += v * as[c];
        s2 += v * ad[c];
    }
    #pragma unroll
    for (int o = 16; o > 0; o >>= 1) {
        s1 += __shfl_down_sync(0xffffffffu, s1, o);
        s2 += __shfl_down_sync(0xffffffffu, s2, o);
    }
    if (lane == 0) {
        g_asrc[n * 4 + warp] = s1;
        g_adst[n * 4 + warp] = s2;
    }
}

// ---------------- fused softmax + aggregate + bias (+BN+ReLU) ----------------
__global__ __launch_bounds__(256) void k_agg(
    int l, int concat,
    const float* __restrict__ bias012, const float* __restrict__ bias3,
    const float* __restrict__ gamma, const float* __restrict__ beta,
    const float* __restrict__ mean, const float* __restrict__ var) {
    int n = blockIdx.x;
    int c = threadIdx.x;
    int s = g_rowptr[n], t = g_rowptr[n + 1];
    const float* ae = g_ae_all + (size_t)l * N_EDGES * 4;

    float ad[4], aself[4], m[4];
    #pragma unroll
    for (int h = 0; h < 4; h++) ad[h] = g_adst[n * 4 + h];
    #pragma unroll
    for (int h = 0; h < 4; h++) {
        float a = lrelu(g_asrc[n * 4 + h] + ad[h] + g_ae_self[l * 4 + h]);
        aself[h] = a;
        m[h] = a;
    }
    // pass 1: max
    for (int i = s; i < t; i++) {
        int e = g_eid[i], src = g_esrc[i];
        #pragma unroll
        for (int h = 0; h < 4; h++) {
            float a = lrelu(g_asrc[src * 4 + h] + ad[h] + ae[e * 4 + h]);
            m[h] = fmaxf(m[h], a);
        }
    }
    // pass 2: sum of exp
    float ssum[4];
    #pragma unroll
    for (int h = 0; h < 4; h++) ssum[h] = expf(aself[h] - m[h]);
    for (int i = s; i < t; i++) {
        int e = g_eid[i], src = g_esrc[i];
        #pragma unroll
        for (int h = 0; h < 4; h++) {
            float a = lrelu(g_asrc[src * 4 + h] + ad[h] + ae[e * 4 + h]);
            ssum[h] += expf(a - m[h]);
        }
    }
    float inv[4];
    #pragma unroll
    for (int h = 0; h < 4; h++) inv[h] = 1.f / (ssum[h] + 1e-16f);

    // pass 3: aggregate
    float acc[4];
    const float* hn = g_T + (size_t)n * HC;
    #pragma unroll
    for (int h = 0; h < 4; h++)
        acc[h] = expf(aself[h] - m[h]) * inv[h] * hn[h * CH + c];
    for (int i = s; i < t; i++) {
        int e = g_eid[i], src = g_esrc[i];
        const float* hs = g_T + (size_t)src * HC;
        #pragma unroll
        for (int h = 0; h < 4; h++) {
            float a = lrelu(g_asrc[src * 4 + h] + ad[h] + ae[e * 4 + h]);
            float w = expf(a - m[h]) * inv[h];
            acc[h] += w * hs[h * CH + c];
        }
    }

    if (concat) {
        #pragma unroll
        for (int h = 0; h < 4; h++) {
            int f = h * CH + c;
            size_t pf = (size_t)l * HC + f;
            float v = acc[h] + bias012[pf];
            float sc = gamma[pf] / sqrtf(var[pf] + 1e-5f);
            v = (v - mean[pf]) * sc + beta[pf];
            g_X[(size_t)n * HC + f] = fmaxf(v, 0.f);
        }
    } else {
        float v = 0.25f * (acc[0] + acc[1] + acc[2] + acc[3]) + bias3[c];
        g_X[(size_t)n * CH + c] = v;
    }
}

// ---------------- gate scores -------------------------------------------------
__global__ void k_gate(const float* __restrict__ gate_w, const float* __restrict__ gate_b) {
    int warp = threadIdx.x >> 5, lane = threadIdx.x & 31;
    int n = blockIdx.x * 8 + warp;
    if (n >= N_NODES) return;
    const float* hr = g_X + (size_t)n * CH;
    float s = 0.f;
    for (int c = lane; c < CH; c += 32) s += hr[c] * gate_w[c];
    #pragma unroll
    for (int o = 16; o > 0; o >>= 1) s += __shfl_down_sync(0xffffffffu, s, o);
    if (lane == 0) g_gate[n] = s + gate_b[0];
}

// ---------------- per-graph softmax pooling ------------------------------------
__device__ __forceinline__ int lb_batch(const int* __restrict__ batch, int target) {
    int lo = 0, hi = N_NODES;
    while (lo < hi) {
        int mid = (lo + hi) >> 1;
        if (batch[mid] < target) lo = mid + 1; else hi = mid;
    }
    return lo;
}
__global__ void k_pool(const int* __restrict__ batch) {
    int b = blockIdx.x;
    int c = threadIdx.x;
    int s = lb_batch(batch, b);
    int e = lb_batch(batch, b + 1);
    if (s == e) { g_graph[b * CH + c] = 0.f; return; }
    float mx = -1e30f;
    for (int n = s; n < e; n++) mx = fmaxf(mx, g_gate[n]);
    float sum = 0.f;
    for (int n = s; n < e; n++) sum += expf(g_gate[n] - mx);
    float inv = 1.f / (sum + 1e-16f);
    float acc = 0.f;
    for (int n = s; n < e; n++)
        acc += expf(g_gate[n] - mx) * inv * g_X[(size_t)n * CH + c];
    g_graph[b * CH + c] = acc;
}

// ---------------- final projection: out = graph @ proj_w + proj_b -------------
__global__ __launch_bounds__(256) void k_proj(const float* __restrict__ proj_w,
                                              const float* __restrict__ proj_b,
                                              float* __restrict__ out) {
    __shared__ float sg[8][CH];
    int b0 = blockIdx.x * 8;
    int tid = threadIdx.x;
    #pragma unroll
    for (int g = 0; g < 8; g++) sg[g][tid] = g_graph[(b0 + g) * CH + tid];
    __syncthreads();
    float acc[8][4];
    #pragma unroll
    for (int g = 0; g < 8; g++)
        #pragma unroll
        for (int j = 0; j < 4; j++) acc[g][j] = 0.f;
    for (int cIt = 0; cIt < CH; cIt++) {
        float w0 = proj_w[cIt * 1024 + tid];
        float w1 = proj_w[cIt * 1024 + tid + 256];
        float w2 = proj_w[cIt * 1024 + tid + 512];
        float w3 = proj_w[cIt * 1024 + tid + 768];
        #pragma unroll
        for (int g = 0; g < 8; g++) {
            float sv = sg[g][cIt];
            acc[g][0] += sv * w0;
            acc[g][1] += sv * w1;
            acc[g][2] += sv * w2;
            acc[g][3] += sv * w3;
        }
    }
    #pragma unroll
    for (int g = 0; g < 8; g++)
        #pragma unroll
        for (int j = 0; j < 4; j++)
            out[(size_t)(b0 + g) * 1024 + tid + j * 256] = acc[g][j] + proj_b[tid + j * 256];
}

// ---------------- host orchestration ------------------------------------------
extern "C" void kernel_launch(void* const* d_in, const int* in_sizes, int n_in,
                              void* d_out, int out_size) {
    (void)in_sizes; (void)n_in; (void)out_size;
    const float* x        = (const float*)d_in[0];
    const int*   ei       = (const int*)d_in[1];
    const float* ea       = (const float*)d_in[2];
    const int*   batch    = (const int*)d_in[3];
    const float* w0       = (const float*)d_in[4];
    const float* w_rest   = (const float*)d_in[5];
    const float* w_edge   = (const float*)d_in[6];
    const float* att_src  = (const float*)d_in[7];
    const float* att_dst  = (const float*)d_in[8];
    const float* att_edge = (const float*)d_in[9];
    const float* bias012  = (const float*)d_in[10];
    const float* bias3    = (const float*)d_in[11];
    const float* bn_gamma = (const float*)d_in[12];
    const float* bn_beta  = (const float*)d_in[13];
    const float* bn_mean  = (const float*)d_in[14];
    const float* bn_var   = (const float*)d_in[15];
    const float* gate_w   = (const float*)d_in[16];
    const float* gate_b   = (const float*)d_in[17];
    const float* proj_w   = (const float*)d_in[18];
    const float* proj_b   = (const float*)d_in[19];
    float* out = (float*)d_out;

    k_edge_mean<<<1, 256>>>(ea);
    k_ve<<<1, 256>>>(w_edge, att_edge);
    k_ae_all<<<(N_EDGES + 127) / 128, 128>>>(ea);
    k_zero_cnt<<<(N_NODES + 255) / 256, 256>>>();
    k_count<<<(N_EDGES + 255) / 256, 256>>>(ei);
    k_scan<<<1, 1024>>>();
    k_scatter<<<(N_EDGES + 255) / 256, 256>>>(ei);

    for (int l = 0; l < 4; l++) {
        if (l == 0) {
            k_gemm0<<<N_NODES, 256>>>(x, w0);
        } else {
            k_sgemm<<<dim3(8, (N_NODES + 127) / 128), 256>>>(w_rest + (size_t)(l - 1) * HC * HC);
        }
        k_alpha<<<N_NODES, 128>>>(att_src, att_dst, l);
        k_agg<<<N_NODES, 256>>>(l, l < 3 ? 1 : 0, bias012, bias3,
                                bn_gamma, bn_beta, bn_mean, bn_var);
    }

    k_gate<<<(N_NODES + 7) / 8, 256>>>(gate_w, gate_b);
    k_pool<<<N_GRAPH, 256>>>(batch);
    k_proj<<<N_GRAPH / 8, 256>>>(proj_w, proj_b, out);
}

// round 3
// speedup vs baseline: 1.4534x; 1.4534x over previous
#include <cuda_runtime.h>
#include <cuda_bf16.h>
#include <cstdint>
#include <math.h>

#define N_NODES 20000
#define N_EDGES 60000
#define N_GRAPH 512
#define F_INP   7
#define HC      1024
#define NH      4
#define CH      256

// ---------------- scratch (static device globals; no allocation) -------------
__device__ float g_X[(size_t)N_NODES * HC];   // layer input
__device__ float g_T[(size_t)N_NODES * HC];   // transformed h = X @ W
__device__ float g_WT[3 * 1024 * 1024];       // transposed weights [l][n][k]
__device__ float g_asrc[N_NODES * NH];
__device__ float g_adst[N_NODES * NH];
__device__ float g_ae_all[4 * N_EDGES * NH];
__device__ float g_ve[48];
__device__ float g_ae_self[16];
__device__ float g_eamean[3];
__device__ int   g_cnt[N_NODES];
__device__ int   g_rowptr[N_NODES + 1];
__device__ int   g_cursor[N_NODES];
__device__ int   g_eid[N_EDGES];
__device__ int   g_esrc[N_EDGES];
__device__ float g_gate[N_NODES];
__device__ float g_graph[N_GRAPH * CH];

__device__ __forceinline__ float lrelu(float a) { return a > 0.f ? a : 0.2f * a; }

// ---------------- edge_attr mean --------------------------------------------
__global__ void k_edge_mean(const float* __restrict__ ea) {
    __shared__ float red[3][256];
    int tid = threadIdx.x;
    float a0 = 0.f, a1 = 0.f, a2 = 0.f;
    for (int e = tid; e < N_EDGES; e += 256) {
        a0 += ea[e * 3 + 0]; a1 += ea[e * 3 + 1]; a2 += ea[e * 3 + 2];
    }
    red[0][tid] = a0; red[1][tid] = a1; red[2][tid] = a2;
    __syncthreads();
    for (int s = 128; s > 0; s >>= 1) {
        if (tid < s) {
            red[0][tid] += red[0][tid + s];
            red[1][tid] += red[1][tid + s];
            red[2][tid] += red[2][tid + s];
        }
        __syncthreads();
    }
    if (tid < 3) g_eamean[tid] = red[tid][0] * (1.f / (float)N_EDGES);
}

// ---------------- ve + self-loop edge attention ------------------------------
__global__ void k_ve(const float* __restrict__ w_edge, const float* __restrict__ att_edge) {
    int tid = threadIdx.x;
    int warp = tid >> 5, lane = tid & 31;
    for (int idx = warp; idx < 48; idx += 8) {
        int l = idx / 12, r = idx % 12, d = r / 4, h = r % 4;
        const float* w = w_edge + (size_t)l * 3 * HC + (size_t)d * HC + h * CH;
        const float* a = att_edge + (size_t)l * HC + h * CH;
        float s = 0.f;
        for (int c = lane; c < CH; c += 32) s += w[c] * a[c];
        #pragma unroll
        for (int o = 16; o > 0; o >>= 1) s += __shfl_down_sync(0xffffffffu, s, o);
        if (lane == 0) g_ve[idx] = s;
    }
    __syncthreads();
    if (tid < 16) {
        int l = tid >> 2, h = tid & 3;
        float s = 0.f;
        for (int d = 0; d < 3; d++) s += g_eamean[d] * g_ve[l * 12 + d * 4 + h];
        g_ae_self[tid] = s;
    }
}

__global__ void k_ae_all(const float* __restrict__ ea) {
    int e = blockIdx.x * blockDim.x + threadIdx.x;
    if (e >= N_EDGES) return;
    float a0 = ea[e * 3 + 0], a1 = ea[e * 3 + 1], a2 = ea[e * 3 + 2];
    #pragma unroll
    for (int l = 0; l < 4; l++) {
        #pragma unroll
        for (int h = 0; h < 4; h++) {
            float v = a0 * g_ve[l * 12 + 0 + h] + a1 * g_ve[l * 12 + 4 + h] + a2 * g_ve[l * 12 + 8 + h];
            g_ae_all[(size_t)l * N_EDGES * 4 + e * 4 + h] = v;
        }
    }
}

// ---------------- CSR build ---------------------------------------------------
__global__ void k_zero_cnt() {
    int n = blockIdx.x * blockDim.x + threadIdx.x;
    if (n < N_NODES) g_cnt[n] = 0;
}
__global__ void k_count(const int* __restrict__ ei) {
    int e = blockIdx.x * blockDim.x + threadIdx.x;
    if (e >= N_EDGES) return;
    atomicAdd(&g_cnt[ei[N_EDGES + e]], 1);
}
__global__ void k_scan() {
    __shared__ int ssum[1024];
    const int SEG = 20;
    int tid = threadIdx.x;
    int base = tid * SEG;
    int cnts[SEG];
    int tot = 0;
    #pragma unroll
    for (int j = 0; j < SEG; j++) {
        int idx = base + j;
        cnts[j] = (idx < N_NODES) ? g_cnt[idx] : 0;
        tot += cnts[j];
    }
    ssum[tid] = tot;
    __syncthreads();
    for (int off = 1; off < 1024; off <<= 1) {
        int v = (tid >= off) ? ssum[tid - off] : 0;
        __syncthreads();
        ssum[tid] += v;
        __syncthreads();
    }
    int run = ssum[tid] - tot;
    #pragma unroll
    for (int j = 0; j < SEG; j++) {
        int idx = base + j;
        if (idx < N_NODES) {
            g_rowptr[idx] = run;
            g_cursor[idx] = run;
            run += cnts[j];
        } else if (idx == N_NODES) {
            g_rowptr[N_NODES] = run;
        }
    }
}
__global__ void k_scatter(const int* __restrict__ ei) {
    int e = blockIdx.x * blockDim.x + threadIdx.x;
    if (e >= N_EDGES) return;
    int src = ei[e];
    int dst = ei[N_EDGES + e];
    int pos = atomicAdd(&g_cursor[dst], 1);
    g_eid[pos] = e;
    g_esrc[pos] = src;
}

// ---------------- weight transpose: WT[l][n][k] = W[l][k][n] ------------------
__global__ void k_transpose(const float* __restrict__ W) {
    __shared__ float t[32][33];
    int l = blockIdx.z;
    int k0 = blockIdx.y * 32, n0 = blockIdx.x * 32;
    int tx = threadIdx.x, ty = threadIdx.y;
    const float* Wl = W + (size_t)l * 1024 * 1024;
    #pragma unroll
    for (int i = 0; i < 4; i++)
        t[ty + i * 8][tx] = Wl[(size_t)(k0 + ty + i * 8) * 1024 + n0 + tx];
    __syncthreads();
    float* WTl = g_WT + (size_t)l * 1024 * 1024;
    #pragma unroll
    for (int i = 0; i < 4; i++)
        WTl[(size_t)(n0 + ty + i * 8) * 1024 + k0 + tx] = t[tx][ty + i * 8];
}

// ---------------- layer-0 GEMM: T = x(N,7) @ w0(7,1024) ----------------------
__global__ void k_gemm0(const float* __restrict__ x, const float* __restrict__ w0) {
    __shared__ float xr[F_INP];
    int n = blockIdx.x, tid = threadIdx.x;
    if (tid < F_INP) xr[tid] = x[n * F_INP + tid];
    __syncthreads();
    #pragma unroll
    for (int j = 0; j < 4; j++) {
        int f = tid + j * 256;
        float acc = 0.f;
        #pragma unroll
        for (int d = 0; d < F_INP; d++) acc += xr[d] * w0[d * HC + f];
        g_T[(size_t)n * HC + f] = acc;
    }
}

// =============== mma.sync bf16x3 GEMM: T = X(20000,1024) @ W ==================
// Block 128x128, warps 2x4 (warp tile 64x32), K chunk 32, double-buffered.
// Each fp32 value split x = hi + mid (bf16 each); D = hi*hi + hi*mid + mid*hi.
#define BK 32
#define NCHUNK (HC / BK)
#define PADU 136                       // uint32 row stride for [k/2][dim] arrays
#define STG_AHI 0
#define STG_AMID 8704
#define STG_BHI 17408
#define STG_BMID 26112
#define STG_BYTES 34816
#define GEMM_SMEM (2 * STG_BYTES)      // 69632 B

__device__ __forceinline__ void mma_bf16(float* c, uint32_t a0, uint32_t a1,
                                         uint32_t a2, uint32_t a3,
                                         uint32_t b0, uint32_t b1) {
    asm volatile(
        "mma.sync.aligned.m16n8k16.row.col.f32.bf16.bf16.f32 "
        "{%0,%1,%2,%3}, {%4,%5,%6,%7}, {%8,%9}, {%0,%1,%2,%3};"
        : "+f"(c[0]), "+f"(c[1]), "+f"(c[2]), "+f"(c[3])
        : "r"(a0), "r"(a1), "r"(a2), "r"(a3), "r"(b0), "r"(b1));
}

__device__ __forceinline__ void split2(float x, float y, uint32_t& hi, uint32_t& mid) {
    __nv_bfloat16 hx = __float2bfloat16_rn(x);
    __nv_bfloat16 hy = __float2bfloat16_rn(y);
    __nv_bfloat16 mx = __float2bfloat16_rn(x - __bfloat162float(hx));
    __nv_bfloat16 my = __float2bfloat16_rn(y - __bfloat162float(hy));
    hi  = (uint32_t)__bfloat16_as_ushort(hx) | ((uint32_t)__bfloat16_as_ushort(hy) << 16);
    mid = (uint32_t)__bfloat16_as_ushort(mx) | ((uint32_t)__bfloat16_as_ushort(my) << 16);
}

__global__ void __launch_bounds__(256, 1) k_mmagemm(int layer) {
    extern __shared__ char smem[];
    const float* WT = g_WT + (size_t)(layer - 1) * 1024 * 1024;
    int tid = threadIdx.x;
    int wid = tid >> 5;
    int lane = tid & 31;
    int g = lane >> 2, tig = lane & 3;
    int wm = wid >> 2;   // 0..1
    int wn = wid & 3;    // 0..3
    int m0 = blockIdx.y * 128;
    int n0 = blockIdx.x * 128;

    // loader geometry: 2 threads per row, 16 k each
    int lm = tid >> 1;
    int lks = (tid & 1) * 16;
    bool aval = (m0 + lm) < N_NODES;
    const float* Abase = g_X + (size_t)(m0 + lm) * HC + lks;
    const float* Bbase = WT + (size_t)(n0 + lm) * HC + lks;

    float acc[4][4][4];
    #pragma unroll
    for (int i = 0; i < 4; i++)
        #pragma unroll
        for (int j = 0; j < 4; j++)
            #pragma unroll
            for (int q = 0; q < 4; q++) acc[i][j][q] = 0.f;

    float aR[16], bR[16];

    // prologue: load chunk 0
    #pragma unroll
    for (int j = 0; j < 4; j++) {
        float4 v = aval ? *(const float4*)(Abase + j * 4) : make_float4(0.f, 0.f, 0.f, 0.f);
        aR[j * 4 + 0] = v.x; aR[j * 4 + 1] = v.y; aR[j * 4 + 2] = v.z; aR[j * 4 + 3] = v.w;
        float4 w = *(const float4*)(Bbase + j * 4);
        bR[j * 4 + 0] = w.x; bR[j * 4 + 1] = w.y; bR[j * 4 + 2] = w.z; bR[j * 4 + 3] = w.w;
    }
    // store chunk 0 into stage 0
    {
        uint32_t* Ah = (uint32_t*)(smem + STG_AHI);
        uint32_t* Am = (uint32_t*)(smem + STG_AMID);
        uint32_t* Bh = (uint32_t*)(smem + STG_BHI);
        uint32_t* Bm = (uint32_t*)(smem + STG_BMID);
        #pragma unroll
        for (int p = 0; p < 8; p++) {
            int kk = (lks >> 1) + p;
            uint32_t hi, mid;
            split2(aR[p * 2], aR[p * 2 + 1], hi, mid);
            Ah[kk * PADU + lm] = hi; Am[kk * PADU + lm] = mid;
            split2(bR[p * 2], bR[p * 2 + 1], hi, mid);
            Bh[kk * PADU + lm] = hi; Bm[kk * PADU + lm] = mid;
        }
    }
    __syncthreads();

    for (int c = 0; c < NCHUNK; c++) {
        // prefetch next chunk into regs
        if (c + 1 < NCHUNK) {
            const float* Ap = Abase + (c + 1) * BK;
            const float* Bp = Bbase + (c + 1) * BK;
            #pragma unroll
            for (int j = 0; j < 4; j++) {
                float4 v = aval ? *(const float4*)(Ap + j * 4) : make_float4(0.f, 0.f, 0.f, 0.f);
                aR[j * 4 + 0] = v.x; aR[j * 4 + 1] = v.y; aR[j * 4 + 2] = v.z; aR[j * 4 + 3] = v.w;
                float4 w = *(const float4*)(Bp + j * 4);
                bR[j * 4 + 0] = w.x; bR[j * 4 + 1] = w.y; bR[j * 4 + 2] = w.z; bR[j * 4 + 3] = w.w;
            }
        }
        // compute on stage c&1
        {
            char* stg = smem + (c & 1) * STG_BYTES;
            const uint32_t* Ah = (const uint32_t*)(stg + STG_AHI);
            const uint32_t* Am = (const uint32_t*)(stg + STG_AMID);
            const uint32_t* Bh = (const uint32_t*)(stg + STG_BHI);
            const uint32_t* Bm = (const uint32_t*)(stg + STG_BMID);
            #pragma unroll
            for (int ks = 0; ks < 2; ks++) {
                int kb = ks * 8 + tig;
                uint32_t ah[4][4], am[4][4];
                #pragma unroll
                for (int mt = 0; mt < 4; mt++) {
                    int mb = wm * 64 + mt * 16 + g;
                    ah[mt][0] = Ah[kb * PADU + mb];
                    ah[mt][1] = Ah[kb * PADU + mb + 8];
                    ah[mt][2] = Ah[(kb + 4) * PADU + mb];
                    ah[mt][3] = Ah[(kb + 4) * PADU + mb + 8];
                    am[mt][0] = Am[kb * PADU + mb];
                    am[mt][1] = Am[kb * PADU + mb + 8];
                    am[mt][2] = Am[(kb + 4) * PADU + mb];
                    am[mt][3] = Am[(kb + 4) * PADU + mb + 8];
                }
                #pragma unroll
                for (int nt = 0; nt < 4; nt++) {
                    int nb = wn * 32 + nt * 8 + g;
                    uint32_t bh0 = Bh[kb * PADU + nb];
                    uint32_t bh1 = Bh[(kb + 4) * PADU + nb];
                    uint32_t bm0 = Bm[kb * PADU + nb];
                    uint32_t bm1 = Bm[(kb + 4) * PADU + nb];
                    #pragma unroll
                    for (int mt = 0; mt < 4; mt++) {
                        mma_bf16(acc[mt][nt], ah[mt][0], ah[mt][1], ah[mt][2], ah[mt][3], bh0, bh1);
                        mma_bf16(acc[mt][nt], ah[mt][0], ah[mt][1], ah[mt][2], ah[mt][3], bm0, bm1);
                        mma_bf16(acc[mt][nt], am[mt][0], am[mt][1], am[mt][2], am[mt][3], bh0, bh1);
                    }
                }
            }
        }
        // store next chunk into other stage
        if (c + 1 < NCHUNK) {
            char* stg = smem + ((c + 1) & 1) * STG_BYTES;
            uint32_t* Ah = (uint32_t*)(stg + STG_AHI);
            uint32_t* Am = (uint32_t*)(stg + STG_AMID);
            uint32_t* Bh = (uint32_t*)(stg + STG_BHI);
            uint32_t* Bm = (uint32_t*)(stg + STG_BMID);
            #pragma unroll
            for (int p = 0; p < 8; p++) {
                int kk = (lks >> 1) + p;
                uint32_t hi, mid;
                split2(aR[p * 2], aR[p * 2 + 1], hi, mid);
                Ah[kk * PADU + lm] = hi; Am[kk * PADU + lm] = mid;
                split2(bR[p * 2], bR[p * 2 + 1], hi, mid);
                Bh[kk * PADU + lm] = hi; Bm[kk * PADU + lm] = mid;
            }
        }
        __syncthreads();
    }

    // epilogue
    #pragma unroll
    for (int mt = 0; mt < 4; mt++) {
        int row0 = m0 + wm * 64 + mt * 16 + g;
        #pragma unroll
        for (int nt = 0; nt < 4; nt++) {
            int col = n0 + wn * 32 + nt * 8 + tig * 2;
            if (row0 < N_NODES)
                *(float2*)(g_T + (size_t)row0 * HC + col) = make_float2(acc[mt][nt][0], acc[mt][nt][1]);
            if (row0 + 8 < N_NODES)
                *(float2*)(g_T + (size_t)(row0 + 8) * HC + col) = make_float2(acc[mt][nt][2], acc[mt][nt][3]);
        }
    }
}

// ---------------- per-node alpha_src / alpha_dst ------------------------------
__global__ void k_alpha(const float* __restrict__ att_src, const float* __restrict__ att_dst, int l) {
    int n = blockIdx.x;
    int warp = threadIdx.x >> 5, lane = threadIdx.x & 31;
    const float* hr = g_T + (size_t)n * HC + warp * CH;
    const float* as = att_src + (size_t)l * HC + warp * CH;
    const float* ad = att_dst + (size_t)l * HC + warp * CH;
    float s1 = 0.f, s2 = 0.f;
    for (int c = lane; c < CH; c += 32) {
        float v = hr[c];
        s1 += v * as[c];
        s2 += v * ad[c];
    }
    #pragma unroll
    for (int o = 16; o > 0; o >>= 1) {
        s1 += __shfl_down_sync(0xffffffffu, s1, o);
        s2 += __shfl_down_sync(0xffffffffu, s2, o);
    }
    if (lane == 0) {
        g_asrc[n * 4 + warp] = s1;
        g_adst[n * 4 + warp] = s2;
    }
}

// ---------------- fused softmax + aggregate + bias (+BN+ReLU) ----------------
__global__ __launch_bounds__(256) void k_agg(
    int l, int concat,
    const float* __restrict__ bias012, const float* __restrict__ bias3,
    const float* __restrict__ gamma, const float* __restrict__ beta,
    const float* __restrict__ mean, const float* __restrict__ var) {
    int n = blockIdx.x;
    int c = threadIdx.x;
    int s = g_rowptr[n], t = g_rowptr[n + 1];
    const float* ae = g_ae_all + (size_t)l * N_EDGES * 4;

    float ad[4], aself[4], m[4];
    #pragma unroll
    for (int h = 0; h < 4; h++) ad[h] = g_adst[n * 4 + h];
    #pragma unroll
    for (int h = 0; h < 4; h++) {
        float a = lrelu(g_asrc[n * 4 + h] + ad[h] + g_ae_self[l * 4 + h]);
        aself[h] = a;
        m[h] = a;
    }
    for (int i = s; i < t; i++) {
        int e = g_eid[i], src = g_esrc[i];
        #pragma unroll
        for (int h = 0; h < 4; h++) {
            float a = lrelu(g_asrc[src * 4 + h] + ad[h] + ae[e * 4 + h]);
            m[h] = fmaxf(m[h], a);
        }
    }
    float ssum[4];
    #pragma unroll
    for (int h = 0; h < 4; h++) ssum[h] = expf(aself[h] - m[h]);
    for (int i = s; i < t; i++) {
        int e = g_eid[i], src = g_esrc[i];
        #pragma unroll
        for (int h = 0; h < 4; h++) {
            float a = lrelu(g_asrc[src * 4 + h] + ad[h] + ae[e * 4 + h]);
            ssum[h] += expf(a - m[h]);
        }
    }
    float inv[4];
    #pragma unroll
    for (int h = 0; h < 4; h++) inv[h] = 1.f / (ssum[h] + 1e-16f);

    float acc[4];
    const float* hn = g_T + (size_t)n * HC;
    #pragma unroll
    for (int h = 0; h < 4; h++)
        acc[h] = expf(aself[h] - m[h]) * inv[h] * hn[h * CH + c];
    for (int i = s; i < t; i++) {
        int e = g_eid[i], src = g_esrc[i];
        const float* hs = g_T + (size_t)src * HC;
        #pragma unroll
        for (int h = 0; h < 4; h++) {
            float a = lrelu(g_asrc[src * 4 + h] + ad[h] + ae[e * 4 + h]);
            float w = expf(a - m[h]) * inv[h];
            acc[h] += w * hs[h * CH + c];
        }
    }

    if (concat) {
        #pragma unroll
        for (int h = 0; h < 4; h++) {
            int f = h * CH + c;
            size_t pf = (size_t)l * HC + f;
            float v = acc[h] + bias012[pf];
            float sc = gamma[pf] / sqrtf(var[pf] + 1e-5f);
            v = (v - mean[pf]) * sc + beta[pf];
            g_X[(size_t)n * HC + f] = fmaxf(v, 0.f);
        }
    } else {
        float v = 0.25f * (acc[0] + acc[1] + acc[2] + acc[3]) + bias3[c];
        g_X[(size_t)n * CH + c] = v;
    }
}

// ---------------- gate scores -------------------------------------------------
__global__ void k_gate(const float* __restrict__ gate_w, const float* __restrict__ gate_b) {
    int warp = threadIdx.x >> 5, lane = threadIdx.x & 31;
    int n = blockIdx.x * 8 + warp;
    if (n >= N_NODES) return;
    const float* hr = g_X + (size_t)n * CH;
    float s = 0.f;
    for (int c = lane; c < CH; c += 32) s += hr[c] * gate_w[c];
    #pragma unroll
    for (int o = 16; o > 0; o >>= 1) s += __shfl_down_sync(0xffffffffu, s, o);
    if (lane == 0) g_gate[n] = s + gate_b[0];
}

// ---------------- per-graph softmax pooling -----------------------------------
__device__ __forceinline__ int lb_batch(const int* __restrict__ batch, int target) {
    int lo = 0, hi = N_NODES;
    while (lo < hi) {
        int mid = (lo + hi) >> 1;
        if (batch[mid] < target) lo = mid + 1; else hi = mid;
    }
    return lo;
}
__global__ void k_pool(const int* __restrict__ batch) {
    int b = blockIdx.x;
    int c = threadIdx.x;
    int s = lb_batch(batch, b);
    int e = lb_batch(batch, b + 1);
    if (s == e) { g_graph[b * CH + c] = 0.f; return; }
    float mx = -1e30f;
    for (int n = s; n < e; n++) mx = fmaxf(mx, g_gate[n]);
    float sum = 0.f;
    for (int n = s; n < e; n++) sum += expf(g_gate[n] - mx);
    float inv = 1.f / (sum + 1e-16f);
    float acc = 0.f;
    for (int n = s; n < e; n++)
        acc += expf(g_gate[n] - mx) * inv * g_X[(size_t)n * CH + c];
    g_graph[b * CH + c] = acc;
}

// ---------------- final projection --------------------------------------------
__global__ __launch_bounds__(256) void k_proj(const float* __restrict__ proj_w,
                                              const float* __restrict__ proj_b,
                                              float* __restrict__ out) {
    __shared__ float sg[8][CH];
    int b0 = blockIdx.x * 8;
    int tid = threadIdx.x;
    #pragma unroll
    for (int g = 0; g < 8; g++) sg[g][tid] = g_graph[(b0 + g) * CH + tid];
    __syncthreads();
    float acc[8][4];
    #pragma unroll
    for (int g = 0; g < 8; g++)
        #pragma unroll
        for (int j = 0; j < 4; j++) acc[g][j] = 0.f;
    for (int cIt = 0; cIt < CH; cIt++) {
        float w0 = proj_w[cIt * 1024 + tid];
        float w1 = proj_w[cIt * 1024 + tid + 256];
        float w2 = proj_w[cIt * 1024 + tid + 512];
        float w3 = proj_w[cIt * 1024 + tid + 768];
        #pragma unroll
        for (int g = 0; g < 8; g++) {
            float sv = sg[g][cIt];
            acc[g][0] += sv * w0;
            acc[g][1] += sv * w1;
            acc[g][2] += sv * w2;
            acc[g][3] += sv * w3;
        }
    }
    #pragma unroll
    for (int g = 0; g < 8; g++)
        #pragma unroll
        for (int j = 0; j < 4; j++)
            out[(size_t)(b0 + g) * 1024 + tid + j * 256] = acc[g][j] + proj_b[tid + j * 256];
}

// ---------------- host orchestration ------------------------------------------
extern "C" void kernel_launch(void* const* d_in, const int* in_sizes, int n_in,
                              void* d_out, int out_size) {
    (void)in_sizes; (void)n_in; (void)out_size;
    const float* x        = (const float*)d_in[0];
    const int*   ei       = (const int*)d_in[1];
    const float* ea       = (const float*)d_in[2];
    const int*   batch    = (const int*)d_in[3];
    const float* w0       = (const float*)d_in[4];
    const float* w_rest   = (const float*)d_in[5];
    const float* w_edge   = (const float*)d_in[6];
    const float* att_src  = (const float*)d_in[7];
    const float* att_dst  = (const float*)d_in[8];
    const float* att_edge = (const float*)d_in[9];
    const float* bias012  = (const float*)d_in[10];
    const float* bias3    = (const float*)d_in[11];
    const float* bn_gamma = (const float*)d_in[12];
    const float* bn_beta  = (const float*)d_in[13];
    const float* bn_mean  = (const float*)d_in[14];
    const float* bn_var   = (const float*)d_in[15];
    const float* gate_w   = (const float*)d_in[16];
    const float* gate_b   = (const float*)d_in[17];
    const float* proj_w   = (const float*)d_in[18];
    const float* proj_b   = (const float*)d_in[19];
    float* out = (float*)d_out;

    cudaFuncSetAttribute(k_mmagemm, cudaFuncAttributeMaxDynamicSharedMemorySize, GEMM_SMEM);

    k_edge_mean<<<1, 256>>>(ea);
    k_ve<<<1, 256>>>(w_edge, att_edge);
    k_ae_all<<<(N_EDGES + 127) / 128, 128>>>(ea);
    k_zero_cnt<<<(N_NODES + 255) / 256, 256>>>();
    k_count<<<(N_EDGES + 255) / 256, 256>>>(ei);
    k_scan<<<1, 1024>>>();
    k_scatter<<<(N_EDGES + 255) / 256, 256>>>(ei);
    k_transpose<<<dim3(32, 32, 3), dim3(32, 8)>>>(w_rest);

    for (int l = 0; l < 4; l++) {
        if (l == 0) {
            k_gemm0<<<N_NODES, 256>>>(x, w0);
        } else {
            k_mmagemm<<<dim3(8, (N_NODES + 127) / 128), 256, GEMM_SMEM>>>(l);
        }
        k_alpha<<<N_NODES, 128>>>(att_src, att_dst, l);
        k_agg<<<N_NODES, 256>>>(l, l < 3 ? 1 : 0, bias012, bias3,
                                bn_gamma, bn_beta, bn_mean, bn_var);
    }

    k_gate<<<(N_NODES + 7) / 8, 256>>>(gate_w, gate_b);
    k_pool<<<N_GRAPH, 256>>>(batch);
    k_proj<<<N_GRAPH / 8, 256>>>(proj_w, proj_b, out);
}

// round 4
// speedup vs baseline: 1.7550x; 1.2075x over previous
#include <cuda_runtime.h>
#include <cuda_bf16.h>
#include <cstdint>
#include <math.h>

#define N_NODES 20000
#define N_EDGES 60000
#define N_GRAPH 512
#define F_INP   7
#define HC      1024
#define NH      4
#define CH      256

// ---------------- scratch (static device globals; no allocation) -------------
__device__ float g_X[(size_t)N_NODES * HC];   // layer input
__device__ float g_T[(size_t)N_NODES * HC];   // transformed h = X @ W
__device__ float g_WT[3 * 1024 * 1024];       // transposed weights [l][n][k]
__device__ float g_asrc[N_NODES * NH];
__device__ float g_adst[N_NODES * NH];
__device__ float g_ae_all[4 * N_EDGES * NH];
__device__ float g_ve[48];
__device__ float g_ae_self[16];
__device__ float g_eamean[3];
__device__ int   g_cnt[N_NODES];
__device__ int   g_rowptr[N_NODES + 1];
__device__ int   g_cursor[N_NODES];
__device__ int   g_eid[N_EDGES];
__device__ int   g_esrc[N_EDGES];
__device__ float g_wedge[N_EDGES * NH];       // normalized attention weight per CSR slot
__device__ float g_wself[N_NODES * NH];       // normalized self-loop weight
__device__ float g_gate[N_NODES];
__device__ float g_graph[N_GRAPH * CH];

__device__ __forceinline__ float lrelu(float a) { return a > 0.f ? a : 0.2f * a; }

// ---------------- edge_attr mean + ve + self-loop attention (fused) ----------
__global__ void k_meanve(const float* __restrict__ ea,
                         const float* __restrict__ w_edge,
                         const float* __restrict__ att_edge) {
    __shared__ float red[3][256];
    int tid = threadIdx.x;
    float a0 = 0.f, a1 = 0.f, a2 = 0.f;
    for (int e = tid; e < N_EDGES; e += 256) {
        a0 += ea[e * 3 + 0]; a1 += ea[e * 3 + 1]; a2 += ea[e * 3 + 2];
    }
    red[0][tid] = a0; red[1][tid] = a1; red[2][tid] = a2;
    __syncthreads();
    for (int s = 128; s > 0; s >>= 1) {
        if (tid < s) {
            red[0][tid] += red[0][tid + s];
            red[1][tid] += red[1][tid + s];
            red[2][tid] += red[2][tid + s];
        }
        __syncthreads();
    }
    if (tid < 3) g_eamean[tid] = red[tid][0] * (1.f / (float)N_EDGES);
    __syncthreads();

    int warp = tid >> 5, lane = tid & 31;
    for (int idx = warp; idx < 48; idx += 8) {
        int l = idx / 12, r = idx % 12, d = r / 4, h = r % 4;
        const float* w = w_edge + (size_t)l * 3 * HC + (size_t)d * HC + h * CH;
        const float* a = att_edge + (size_t)l * HC + h * CH;
        float s = 0.f;
        for (int c = lane; c < CH; c += 32) s += w[c] * a[c];
        #pragma unroll
        for (int o = 16; o > 0; o >>= 1) s += __shfl_down_sync(0xffffffffu, s, o);
        if (lane == 0) g_ve[idx] = s;
    }
    __syncthreads();
    if (tid < 16) {
        int l = tid >> 2, h = tid & 3;
        float s = 0.f;
        for (int d = 0; d < 3; d++) s += g_eamean[d] * g_ve[l * 12 + d * 4 + h];
        g_ae_self[tid] = s;
    }
}

__global__ void k_ae_all(const float* __restrict__ ea) {
    int e = blockIdx.x * blockDim.x + threadIdx.x;
    if (e >= N_EDGES) return;
    float a0 = ea[e * 3 + 0], a1 = ea[e * 3 + 1], a2 = ea[e * 3 + 2];
    #pragma unroll
    for (int l = 0; l < 4; l++) {
        float4 v;
        v.x = a0 * g_ve[l * 12 + 0] + a1 * g_ve[l * 12 + 4] + a2 * g_ve[l * 12 + 8];
        v.y = a0 * g_ve[l * 12 + 1] + a1 * g_ve[l * 12 + 5] + a2 * g_ve[l * 12 + 9];
        v.z = a0 * g_ve[l * 12 + 2] + a1 * g_ve[l * 12 + 6] + a2 * g_ve[l * 12 + 10];
        v.w = a0 * g_ve[l * 12 + 3] + a1 * g_ve[l * 12 + 7] + a2 * g_ve[l * 12 + 11];
        *(float4*)&g_ae_all[(size_t)l * N_EDGES * 4 + e * 4] = v;
    }
}

// ---------------- CSR build ---------------------------------------------------
__global__ void k_zero_cnt() {
    int n = blockIdx.x * blockDim.x + threadIdx.x;
    if (n < N_NODES) g_cnt[n] = 0;
}
__global__ void k_count(const int* __restrict__ ei) {
    int e = blockIdx.x * blockDim.x + threadIdx.x;
    if (e >= N_EDGES) return;
    atomicAdd(&g_cnt[ei[N_EDGES + e]], 1);
}
__global__ void k_scan() {
    __shared__ int ssum[1024];
    const int SEG = 20;
    int tid = threadIdx.x;
    int base = tid * SEG;
    int cnts[SEG];
    int tot = 0;
    #pragma unroll
    for (int j = 0; j < SEG; j++) {
        int idx = base + j;
        cnts[j] = (idx < N_NODES) ? g_cnt[idx] : 0;
        tot += cnts[j];
    }
    ssum[tid] = tot;
    __syncthreads();
    for (int off = 1; off < 1024; off <<= 1) {
        int v = (tid >= off) ? ssum[tid - off] : 0;
        __syncthreads();
        ssum[tid] += v;
        __syncthreads();
    }
    int run = ssum[tid] - tot;
    #pragma unroll
    for (int j = 0; j < SEG; j++) {
        int idx = base + j;
        if (idx < N_NODES) {
            g_rowptr[idx] = run;
            g_cursor[idx] = run;
            run += cnts[j];
        } else if (idx == N_NODES) {
            g_rowptr[N_NODES] = run;
        }
    }
}
__global__ void k_scatter(const int* __restrict__ ei) {
    int e = blockIdx.x * blockDim.x + threadIdx.x;
    if (e >= N_EDGES) return;
    int src = ei[e];
    int dst = ei[N_EDGES + e];
    int pos = atomicAdd(&g_cursor[dst], 1);
    g_eid[pos] = e;
    g_esrc[pos] = src;
}

// ---------------- weight transpose: WT[l][n][k] = W[l][k][n] ------------------
__global__ void k_transpose(const float* __restrict__ W) {
    __shared__ float t[32][33];
    int l = blockIdx.z;
    int k0 = blockIdx.y * 32, n0 = blockIdx.x * 32;
    int tx = threadIdx.x, ty = threadIdx.y;
    const float* Wl = W + (size_t)l * 1024 * 1024;
    #pragma unroll
    for (int i = 0; i < 4; i++)
        t[ty + i * 8][tx] = Wl[(size_t)(k0 + ty + i * 8) * 1024 + n0 + tx];
    __syncthreads();
    float* WTl = g_WT + (size_t)l * 1024 * 1024;
    #pragma unroll
    for (int i = 0; i < 4; i++)
        WTl[(size_t)(n0 + ty + i * 8) * 1024 + k0 + tx] = t[tx][ty + i * 8];
}

// ---------------- layer-0 GEMM: T = x(N,7) @ w0(7,1024) ----------------------
__global__ void k_gemm0(const float* __restrict__ x, const float* __restrict__ w0) {
    __shared__ float xr[F_INP];
    int n = blockIdx.x, tid = threadIdx.x;
    if (tid < F_INP) xr[tid] = x[n * F_INP + tid];
    __syncthreads();
    #pragma unroll
    for (int j = 0; j < 4; j++) {
        int f = tid + j * 256;
        float acc = 0.f;
        #pragma unroll
        for (int d = 0; d < F_INP; d++) acc += xr[d] * w0[d * HC + f];
        g_T[(size_t)n * HC + f] = acc;
    }
}

// =============== mma.sync bf16x3 GEMM: T = X(20000,1024) @ W ==================
#define BK 32
#define NCHUNK (HC / BK)
#define PADU 136
#define STG_AHI 0
#define STG_AMID 8704
#define STG_BHI 17408
#define STG_BMID 26112
#define STG_BYTES 34816
#define GEMM_SMEM (2 * STG_BYTES)

__device__ __forceinline__ void mma_bf16(float* c, uint32_t a0, uint32_t a1,
                                         uint32_t a2, uint32_t a3,
                                         uint32_t b0, uint32_t b1) {
    asm volatile(
        "mma.sync.aligned.m16n8k16.row.col.f32.bf16.bf16.f32 "
        "{%0,%1,%2,%3}, {%4,%5,%6,%7}, {%8,%9}, {%0,%1,%2,%3};"
        : "+f"(c[0]), "+f"(c[1]), "+f"(c[2]), "+f"(c[3])
        : "r"(a0), "r"(a1), "r"(a2), "r"(a3), "r"(b0), "r"(b1));
}

__device__ __forceinline__ void split2(float x, float y, uint32_t& hi, uint32_t& mid) {
    __nv_bfloat16 hx = __float2bfloat16_rn(x);
    __nv_bfloat16 hy = __float2bfloat16_rn(y);
    __nv_bfloat16 mx = __float2bfloat16_rn(x - __bfloat162float(hx));
    __nv_bfloat16 my = __float2bfloat16_rn(y - __bfloat162float(hy));
    hi  = (uint32_t)__bfloat16_as_ushort(hx) | ((uint32_t)__bfloat16_as_ushort(hy) << 16);
    mid = (uint32_t)__bfloat16_as_ushort(mx) | ((uint32_t)__bfloat16_as_ushort(my) << 16);
}

__global__ void __launch_bounds__(256, 1) k_mmagemm(int layer) {
    extern __shared__ char smem[];
    const float* WT = g_WT + (size_t)(layer - 1) * 1024 * 1024;
    int tid = threadIdx.x;
    int wid = tid >> 5;
    int lane = tid & 31;
    int g = lane >> 2, tig = lane & 3;
    int wm = wid >> 2;
    int wn = wid & 3;
    int m0 = blockIdx.y * 128;
    int n0 = blockIdx.x * 128;

    int lm = tid >> 1;
    int lks = (tid & 1) * 16;
    bool aval = (m0 + lm) < N_NODES;
    const float* Abase = g_X + (size_t)(m0 + lm) * HC + lks;
    const float* Bbase = WT + (size_t)(n0 + lm) * HC + lks;

    float acc[4][4][4];
    #pragma unroll
    for (int i = 0; i < 4; i++)
        #pragma unroll
        for (int j = 0; j < 4; j++)
            #pragma unroll
            for (int q = 0; q < 4; q++) acc[i][j][q] = 0.f;

    float aR[16], bR[16];

    #pragma unroll
    for (int j = 0; j < 4; j++) {
        float4 v = aval ? *(const float4*)(Abase + j * 4) : make_float4(0.f, 0.f, 0.f, 0.f);
        aR[j * 4 + 0] = v.x; aR[j * 4 + 1] = v.y; aR[j * 4 + 2] = v.z; aR[j * 4 + 3] = v.w;
        float4 w = *(const float4*)(Bbase + j * 4);
        bR[j * 4 + 0] = w.x; bR[j * 4 + 1] = w.y; bR[j * 4 + 2] = w.z; bR[j * 4 + 3] = w.w;
    }
    {
        uint32_t* Ah = (uint32_t*)(smem + STG_AHI);
        uint32_t* Am = (uint32_t*)(smem + STG_AMID);
        uint32_t* Bh = (uint32_t*)(smem + STG_BHI);
        uint32_t* Bm = (uint32_t*)(smem + STG_BMID);
        #pragma unroll
        for (int p = 0; p < 8; p++) {
            int kk = (lks >> 1) + p;
            uint32_t hi, mid;
            split2(aR[p * 2], aR[p * 2 + 1], hi, mid);
            Ah[kk * PADU + lm] = hi; Am[kk * PADU + lm] = mid;
            split2(bR[p * 2], bR[p * 2 + 1], hi, mid);
            Bh[kk * PADU + lm] = hi; Bm[kk * PADU + lm] = mid;
        }
    }
    __syncthreads();

    for (int c = 0; c < NCHUNK; c++) {
        if (c + 1 < NCHUNK) {
            const float* Ap = Abase + (c + 1) * BK;
            const float* Bp = Bbase + (c + 1) * BK;
            #pragma unroll
            for (int j = 0; j < 4; j++) {
                float4 v = aval ? *(const float4*)(Ap + j * 4) : make_float4(0.f, 0.f, 0.f, 0.f);
                aR[j * 4 + 0] = v.x; aR[j * 4 + 1] = v.y; aR[j * 4 + 2] = v.z; aR[j * 4 + 3] = v.w;
                float4 w = *(const float4*)(Bp + j * 4);
                bR[j * 4 + 0] = w.x; bR[j * 4 + 1] = w.y; bR[j * 4 + 2] = w.z; bR[j * 4 + 3] = w.w;
            }
        }
        {
            char* stg = smem + (c & 1) * STG_BYTES;
            const uint32_t* Ah = (const uint32_t*)(stg + STG_AHI);
            const uint32_t* Am = (const uint32_t*)(stg + STG_AMID);
            const uint32_t* Bh = (const uint32_t*)(stg + STG_BHI);
            const uint32_t* Bm = (const uint32_t*)(stg + STG_BMID);
            #pragma unroll
            for (int ks = 0; ks < 2; ks++) {
                int kb = ks * 8 + tig;
                uint32_t ah[4][4], am[4][4];
                #pragma unroll
                for (int mt = 0; mt < 4; mt++) {
                    int mb = wm * 64 + mt * 16 + g;
                    ah[mt][0] = Ah[kb * PADU + mb];
                    ah[mt][1] = Ah[kb * PADU + mb + 8];
                    ah[mt][2] = Ah[(kb + 4) * PADU + mb];
                    ah[mt][3] = Ah[(kb + 4) * PADU + mb + 8];
                    am[mt][0] = Am[kb * PADU + mb];
                    am[mt][1] = Am[kb * PADU + mb + 8];
                    am[mt][2] = Am[(kb + 4) * PADU + mb];
                    am[mt][3] = Am[(kb + 4) * PADU + mb + 8];
                }
                #pragma unroll
                for (int nt = 0; nt < 4; nt++) {
                    int nb = wn * 32 + nt * 8 + g;
                    uint32_t bh0 = Bh[kb * PADU + nb];
                    uint32_t bh1 = Bh[(kb + 4) * PADU + nb];
                    uint32_t bm0 = Bm[kb * PADU + nb];
                    uint32_t bm1 = Bm[(kb + 4) * PADU + nb];
                    #pragma unroll
                    for (int mt = 0; mt < 4; mt++) {
                        mma_bf16(acc[mt][nt], ah[mt][0], ah[mt][1], ah[mt][2], ah[mt][3], bh0, bh1);
                        mma_bf16(acc[mt][nt], ah[mt][0], ah[mt][1], ah[mt][2], ah[mt][3], bm0, bm1);
                        mma_bf16(acc[mt][nt], am[mt][0], am[mt][1], am[mt][2], am[mt][3], bh0, bh1);
                    }
                }
            }
        }
        if (c + 1 < NCHUNK) {
            char* stg = smem + ((c + 1) & 1) * STG_BYTES;
            uint32_t* Ah = (uint32_t*)(stg + STG_AHI);
            uint32_t* Am = (uint32_t*)(stg + STG_AMID);
            uint32_t* Bh = (uint32_t*)(stg + STG_BHI);
            uint32_t* Bm = (uint32_t*)(stg + STG_BMID);
            #pragma unroll
            for (int p = 0; p < 8; p++) {
                int kk = (lks >> 1) + p;
                uint32_t hi, mid;
                split2(aR[p * 2], aR[p * 2 + 1], hi, mid);
                Ah[kk * PADU + lm] = hi; Am[kk * PADU + lm] = mid;
                split2(bR[p * 2], bR[p * 2 + 1], hi, mid);
                Bh[kk * PADU + lm] = hi; Bm[kk * PADU + lm] = mid;
            }
        }
        __syncthreads();
    }

    #pragma unroll
    for (int mt = 0; mt < 4; mt++) {
        int row0 = m0 + wm * 64 + mt * 16 + g;
        #pragma unroll
        for (int nt = 0; nt < 4; nt++) {
            int col = n0 + wn * 32 + nt * 8 + tig * 2;
            if (row0 < N_NODES)
                *(float2*)(g_T + (size_t)row0 * HC + col) = make_float2(acc[mt][nt][0], acc[mt][nt][1]);
            if (row0 + 8 < N_NODES)
                *(float2*)(g_T + (size_t)(row0 + 8) * HC + col) = make_float2(acc[mt][nt][2], acc[mt][nt][3]);
        }
    }
}

// ---------------- per-node alpha_src / alpha_dst (float4) ---------------------
__global__ void k_alpha(const float* __restrict__ att_src, const float* __restrict__ att_dst, int l) {
    int n = blockIdx.x;
    int warp = threadIdx.x >> 5, lane = threadIdx.x & 31;
    const float* hr = g_T + (size_t)n * HC + warp * CH;
    const float* as = att_src + (size_t)l * HC + warp * CH;
    const float* ad = att_dst + (size_t)l * HC + warp * CH;
    float s1 = 0.f, s2 = 0.f;
    #pragma unroll
    for (int it = 0; it < 2; it++) {
        int c = (lane + it * 32) * 4;
        float4 v = *(const float4*)(hr + c);
        float4 a = *(const float4*)(as + c);
        float4 d = *(const float4*)(ad + c);
        s1 += v.x * a.x + v.y * a.y + v.z * a.z + v.w * a.w;
        s2 += v.x * d.x + v.y * d.y + v.z * d.z + v.w * d.w;
    }
    #pragma unroll
    for (int o = 16; o > 0; o >>= 1) {
        s1 += __shfl_down_sync(0xffffffffu, s1, o);
        s2 += __shfl_down_sync(0xffffffffu, s2, o);
    }
    if (lane == 0) {
        g_asrc[n * 4 + warp] = s1;
        g_adst[n * 4 + warp] = s2;
    }
}

// ---------------- precompute softmax attention weights ------------------------
__global__ void k_attw(int l) {
    int n = blockIdx.x * blockDim.x + threadIdx.x;
    if (n >= N_NODES) return;
    const float* ae = g_ae_all + (size_t)l * N_EDGES * 4;
    int s = g_rowptr[n], t = g_rowptr[n + 1];

    float4 ad4 = *(const float4*)&g_adst[n * 4];
    float4 as4 = *(const float4*)&g_asrc[n * 4];
    float ad[4] = {ad4.x, ad4.y, ad4.z, ad4.w};
    float aself[4], m[4];
    #pragma unroll
    for (int h = 0; h < 4; h++) {
        aself[h] = lrelu(((const float*)&as4)[h] + ad[h] + g_ae_self[l * 4 + h]);
        m[h] = aself[h];
    }
    for (int i = s; i < t; i++) {
        int e = g_eid[i], src = g_esrc[i];
        float4 av = *(const float4*)&g_asrc[src * 4];
        float4 ev = *(const float4*)&ae[e * 4];
        #pragma unroll
        for (int h = 0; h < 4; h++) {
            float a = lrelu(((const float*)&av)[h] + ad[h] + ((const float*)&ev)[h]);
            m[h] = fmaxf(m[h], a);
        }
    }
    float sum[4];
    #pragma unroll
    for (int h = 0; h < 4; h++) sum[h] = expf(aself[h] - m[h]);
    for (int i = s; i < t; i++) {
        int e = g_eid[i], src = g_esrc[i];
        float4 av = *(const float4*)&g_asrc[src * 4];
        float4 ev = *(const float4*)&ae[e * 4];
        #pragma unroll
        for (int h = 0; h < 4; h++) {
            float a = lrelu(((const float*)&av)[h] + ad[h] + ((const float*)&ev)[h]);
            sum[h] += expf(a - m[h]);
        }
    }
    float inv[4];
    #pragma unroll
    for (int h = 0; h < 4; h++) inv[h] = 1.f / (sum[h] + 1e-16f);

    float4 ws;
    ((float*)&ws)[0] = expf(aself[0] - m[0]) * inv[0];
    ((float*)&ws)[1] = expf(aself[1] - m[1]) * inv[1];
    ((float*)&ws)[2] = expf(aself[2] - m[2]) * inv[2];
    ((float*)&ws)[3] = expf(aself[3] - m[3]) * inv[3];
    *(float4*)&g_wself[n * 4] = ws;

    for (int i = s; i < t; i++) {
        int e = g_eid[i], src = g_esrc[i];
        float4 av = *(const float4*)&g_asrc[src * 4];
        float4 ev = *(const float4*)&ae[e * 4];
        float4 w;
        #pragma unroll
        for (int h = 0; h < 4; h++) {
            float a = lrelu(((const float*)&av)[h] + ad[h] + ((const float*)&ev)[h]);
            ((float*)&w)[h] = expf(a - m[h]) * inv[h];
        }
        *(float4*)&g_wedge[i * 4] = w;
    }
}

// ---------------- weighted gather + bias (+BN+ReLU) ---------------------------
__global__ __launch_bounds__(256) void k_agg(
    int l, int concat,
    const float* __restrict__ bias012, const float* __restrict__ bias3,
    const float* __restrict__ gamma, const float* __restrict__ beta,
    const float* __restrict__ mean, const float* __restrict__ var) {
    int n = blockIdx.x;
    int tid = threadIdx.x;
    int s = g_rowptr[n], t = g_rowptr[n + 1];

    if (concat) {
        int head = tid >> 6;
        int c4 = (tid & 63) << 2;
        int f = head * CH + c4;
        float wself = g_wself[n * 4 + head];
        float4 acc = *(const float4*)(g_T + (size_t)n * HC + f);
        acc.x *= wself; acc.y *= wself; acc.z *= wself; acc.w *= wself;
        for (int i = s; i < t; i++) {
            int src = g_esrc[i];
            float w = g_wedge[i * 4 + head];
            float4 v = *(const float4*)(g_T + (size_t)src * HC + f);
            acc.x += w * v.x; acc.y += w * v.y; acc.z += w * v.z; acc.w += w * v.w;
        }
        size_t pf = (size_t)l * HC + f;
        float4 bv = *(const float4*)(bias012 + pf);
        float4 gv = *(const float4*)(gamma + pf);
        float4 be = *(const float4*)(beta + pf);
        float4 mn = *(const float4*)(mean + pf);
        float4 vr = *(const float4*)(var + pf);
        float4 o;
        o.x = fmaxf((acc.x + bv.x - mn.x) * (gv.x * rsqrtf(vr.x + 1e-5f)) + be.x, 0.f);
        o.y = fmaxf((acc.y + bv.y - mn.y) * (gv.y * rsqrtf(vr.y + 1e-5f)) + be.y, 0.f);
        o.z = fmaxf((acc.z + bv.z - mn.z) * (gv.z * rsqrtf(vr.z + 1e-5f)) + be.z, 0.f);
        o.w = fmaxf((acc.w + bv.w - mn.w) * (gv.w * rsqrtf(vr.w + 1e-5f)) + be.w, 0.f);
        *(float4*)(g_X + (size_t)n * HC + f) = o;
    } else {
        int c = tid;
        float4 ws = *(const float4*)&g_wself[n * 4];
        const float* hn = g_T + (size_t)n * HC;
        float acc = ws.x * hn[c] + ws.y * hn[CH + c] + ws.z * hn[2 * CH + c] + ws.w * hn[3 * CH + c];
        for (int i = s; i < t; i++) {
            int src = g_esrc[i];
            float4 w = *(const float4*)&g_wedge[i * 4];
            const float* hs = g_T + (size_t)src * HC;
            acc += w.x * hs[c] + w.y * hs[CH + c] + w.z * hs[2 * CH + c] + w.w * hs[3 * CH + c];
        }
        g_X[(size_t)n * CH + c] = 0.25f * acc + bias3[c];
    }
}

// ---------------- gate scores -------------------------------------------------
__global__ void k_gate(const float* __restrict__ gate_w, const float* __restrict__ gate_b) {
    int warp = threadIdx.x >> 5, lane = threadIdx.x & 31;
    int n = blockIdx.x * 8 + warp;
    if (n >= N_NODES) return;
    const float* hr = g_X + (size_t)n * CH;
    float s = 0.f;
    #pragma unroll
    for (int it = 0; it < 2; it++) {
        int c = (lane + it * 32) * 4;
        float4 v = *(const float4*)(hr + c);
        float4 w = *(const float4*)(gate_w + c);
        s += v.x * w.x + v.y * w.y + v.z * w.z + v.w * w.w;
    }
    #pragma unroll
    for (int o = 16; o > 0; o >>= 1) s += __shfl_down_sync(0xffffffffu, s, o);
    if (lane == 0) g_gate[n] = s + gate_b[0];
}

// ---------------- per-graph softmax pooling -----------------------------------
__device__ __forceinline__ int lb_batch(const int* __restrict__ batch, int target) {
    int lo = 0, hi = N_NODES;
    while (lo < hi) {
        int mid = (lo + hi) >> 1;
        if (batch[mid] < target) lo = mid + 1; else hi = mid;
    }
    return lo;
}
__global__ void k_pool(const int* __restrict__ batch) {
    int b = blockIdx.x;
    int c = threadIdx.x;
    int s = lb_batch(batch, b);
    int e = lb_batch(batch, b + 1);
    if (s == e) { g_graph[b * CH + c] = 0.f; return; }
    float mx = -1e30f;
    for (int n = s; n < e; n++) mx = fmaxf(mx, g_gate[n]);
    float sum = 0.f;
    for (int n = s; n < e; n++) sum += expf(g_gate[n] - mx);
    float inv = 1.f / (sum + 1e-16f);
    float acc = 0.f;
    for (int n = s; n < e; n++)
        acc += expf(g_gate[n] - mx) * inv * g_X[(size_t)n * CH + c];
    g_graph[b * CH + c] = acc;
}

// ---------------- final projection --------------------------------------------
__global__ __launch_bounds__(256) void k_proj(const float* __restrict__ proj_w,
                                              const float* __restrict__ proj_b,
                                              float* __restrict__ out) {
    __shared__ float sg[8][CH];
    int b0 = blockIdx.x * 8;
    int tid = threadIdx.x;
    #pragma unroll
    for (int g = 0; g < 8; g++) sg[g][tid] = g_graph[(b0 + g) * CH + tid];
    __syncthreads();
    float acc[8][4];
    #pragma unroll
    for (int g = 0; g < 8; g++)
        #pragma unroll
        for (int j = 0; j < 4; j++) acc[g][j] = 0.f;
    for (int cIt = 0; cIt < CH; cIt++) {
        float w0 = proj_w[cIt * 1024 + tid];
        float w1 = proj_w[cIt * 1024 + tid + 256];
        float w2 = proj_w[cIt * 1024 + tid + 512];
        float w3 = proj_w[cIt * 1024 + tid + 768];
        #pragma unroll
        for (int g = 0; g < 8; g++) {
            float sv = sg[g][cIt];
            acc[g][0] += sv * w0;
            acc[g][1] += sv * w1;
            acc[g][2] += sv * w2;
            acc[g][3] += sv * w3;
        }
    }
    #pragma unroll
    for (int g = 0; g < 8; g++)
        #pragma unroll
        for (int j = 0; j < 4; j++)
            out[(size_t)(b0 + g) * 1024 + tid + j * 256] = acc[g][j] + proj_b[tid + j * 256];
}

// ---------------- host orchestration ------------------------------------------
extern "C" void kernel_launch(void* const* d_in, const int* in_sizes, int n_in,
                              void* d_out, int out_size) {
    (void)in_sizes; (void)n_in; (void)out_size;
    const float* x        = (const float*)d_in[0];
    const int*   ei       = (const int*)d_in[1];
    const float* ea       = (const float*)d_in[2];
    const int*   batch    = (const int*)d_in[3];
    const float* w0       = (const float*)d_in[4];
    const float* w_rest   = (const float*)d_in[5];
    const float* w_edge   = (const float*)d_in[6];
    const float* att_src  = (const float*)d_in[7];
    const float* att_dst  = (const float*)d_in[8];
    const float* att_edge = (const float*)d_in[9];
    const float* bias012  = (const float*)d_in[10];
    const float* bias3    = (const float*)d_in[11];
    const float* bn_gamma = (const float*)d_in[12];
    const float* bn_beta  = (const float*)d_in[13];
    const float* bn_mean  = (const float*)d_in[14];
    const float* bn_var   = (const float*)d_in[15];
    const float* gate_w   = (const float*)d_in[16];
    const float* gate_b   = (const float*)d_in[17];
    const float* proj_w   = (const float*)d_in[18];
    const float* proj_b   = (const float*)d_in[19];
    float* out = (float*)d_out;

    cudaFuncSetAttribute(k_mmagemm, cudaFuncAttributeMaxDynamicSharedMemorySize, GEMM_SMEM);

    k_zero_cnt<<<(N_NODES + 255) / 256, 256>>>();
    k_count<<<(N_EDGES + 255) / 256, 256>>>(ei);
    k_scan<<<1, 1024>>>();
    k_scatter<<<(N_EDGES + 255) / 256, 256>>>(ei);
    k_transpose<<<dim3(32, 32, 3), dim3(32, 8)>>>(w_rest);
    k_gemm0<<<N_NODES, 256>>>(x, w0);           // profiled slot (launch #6)
    k_meanve<<<1, 256>>>(ea, w_edge, att_edge);
    k_ae_all<<<(N_EDGES + 127) / 128, 128>>>(ea);

    for (int l = 0; l < 4; l++) {
        if (l > 0) {
            k_mmagemm<<<dim3(8, (N_NODES + 127) / 128), 256, GEMM_SMEM>>>(l);
        }
        k_alpha<<<N_NODES, 128>>>(att_src, att_dst, l);
        k_attw<<<(N_NODES + 255) / 256, 256>>>(l);
        k_agg<<<N_NODES, 256>>>(l, l < 3 ? 1 : 0, bias012, bias3,
                                bn_gamma, bn_beta, bn_mean, bn_var);
    }

    k_gate<<<(N_NODES + 7) / 8, 256>>>(gate_w, gate_b);
    k_pool<<<N_GRAPH, 256>>>(batch);
    k_proj<<<N_GRAPH / 8, 256>>>(proj_w, proj_b, out);
}

// round 5
// speedup vs baseline: 2.3765x; 1.3541x over previous
#include <cuda_runtime.h>
#include <cuda_bf16.h>
#include <cstdint>
#include <math.h>

#define N_NODES 20000
#define N_PAD   20096            // 157 * 128
#define N_EDGES 60000
#define N_GRAPH 512
#define F_INP   7
#define HC      1024
#define NH      4
#define CH      256

// ---------------- scratch (static device globals; no allocation) -------------
__device__ float    g_X[(size_t)N_NODES * CH];     // final-layer output (l=3)
__device__ float    g_T[(size_t)N_NODES * HC];     // transformed h = X @ W
__device__ uint32_t g_Xhi[(size_t)N_PAD * 512];    // activation bf16-hi packed pairs
__device__ uint32_t g_Xmid[(size_t)N_PAD * 512];   // activation bf16-mid packed pairs
__device__ uint32_t g_WThi[3 * 1024 * 512];        // weight^T bf16-hi packed
__device__ uint32_t g_WTmid[3 * 1024 * 512];       // weight^T bf16-mid packed
__device__ float    g_asrc[N_NODES * NH];
__device__ float    g_adst[N_NODES * NH];
__device__ float    g_ae_all[4 * N_EDGES * NH];
__device__ float    g_ve[48];
__device__ float    g_ae_self[16];
__device__ float    g_eamean[3];
__device__ int      g_cnt[N_NODES];
__device__ int      g_rowptr[N_NODES + 1];
__device__ int      g_cursor[N_NODES];
__device__ int      g_eid[N_EDGES];
__device__ int      g_esrc[N_EDGES];
__device__ float    g_wedge[N_EDGES * NH];
__device__ float    g_wself[N_NODES * NH];
__device__ float    g_gate[N_NODES];
__device__ float    g_graph[N_GRAPH * CH];

__device__ __forceinline__ float lrelu(float a) { return a > 0.f ? a : 0.2f * a; }

__device__ __forceinline__ void split2(float x, float y, uint32_t& hi, uint32_t& mid) {
    __nv_bfloat16 hx = __float2bfloat16_rn(x);
    __nv_bfloat16 hy = __float2bfloat16_rn(y);
    __nv_bfloat16 mx = __float2bfloat16_rn(x - __bfloat162float(hx));
    __nv_bfloat16 my = __float2bfloat16_rn(y - __bfloat162float(hy));
    hi  = (uint32_t)__bfloat16_as_ushort(hx) | ((uint32_t)__bfloat16_as_ushort(hy) << 16);
    mid = (uint32_t)__bfloat16_as_ushort(mx) | ((uint32_t)__bfloat16_as_ushort(my) << 16);
}

__device__ __forceinline__ uint32_t smem_u32(const void* p) {
    uint32_t a;
    asm("{ .reg .u64 t; cvta.to.shared.u64 t, %1; cvt.u32.u64 %0, t; }" : "=r"(a) : "l"(p));
    return a;
}
__device__ __forceinline__ void cp16(uint32_t dst, const void* src) {
    asm volatile("cp.async.cg.shared.global [%0], [%1], 16;" :: "r"(dst), "l"(src));
}
__device__ __forceinline__ void mma_bf16(float* c, uint32_t a0, uint32_t a1,
                                         uint32_t a2, uint32_t a3,
                                         uint32_t b0, uint32_t b1) {
    asm volatile(
        "mma.sync.aligned.m16n8k16.row.col.f32.bf16.bf16.f32 "
        "{%0,%1,%2,%3}, {%4,%5,%6,%7}, {%8,%9}, {%0,%1,%2,%3};"
        : "+f"(c[0]), "+f"(c[1]), "+f"(c[2]), "+f"(c[3])
        : "r"(a0), "r"(a1), "r"(a2), "r"(a3), "r"(b0), "r"(b1));
}

// ---------------- edge_attr mean + ve + self-loop attention (fused) ----------
__global__ void k_meanve(const float* __restrict__ ea,
                         const float* __restrict__ w_edge,
                         const float* __restrict__ att_edge) {
    __shared__ float red[3][256];
    int tid = threadIdx.x;
    float a0 = 0.f, a1 = 0.f, a2 = 0.f;
    for (int e = tid; e < N_EDGES; e += 256) {
        a0 += ea[e * 3 + 0]; a1 += ea[e * 3 + 1]; a2 += ea[e * 3 + 2];
    }
    red[0][tid] = a0; red[1][tid] = a1; red[2][tid] = a2;
    __syncthreads();
    for (int s = 128; s > 0; s >>= 1) {
        if (tid < s) {
            red[0][tid] += red[0][tid + s];
            red[1][tid] += red[1][tid + s];
            red[2][tid] += red[2][tid + s];
        }
        __syncthreads();
    }
    if (tid < 3) g_eamean[tid] = red[tid][0] * (1.f / (float)N_EDGES);
    __syncthreads();

    int warp = tid >> 5, lane = tid & 31;
    for (int idx = warp; idx < 48; idx += 8) {
        int l = idx / 12, r = idx % 12, d = r / 4, h = r % 4;
        const float* w = w_edge + (size_t)l * 3 * HC + (size_t)d * HC + h * CH;
        const float* a = att_edge + (size_t)l * HC + h * CH;
        float s = 0.f;
        for (int c = lane; c < CH; c += 32) s += w[c] * a[c];
        #pragma unroll
        for (int o = 16; o > 0; o >>= 1) s += __shfl_down_sync(0xffffffffu, s, o);
        if (lane == 0) g_ve[idx] = s;
    }
    __syncthreads();
    if (tid < 16) {
        int l = tid >> 2, h = tid & 3;
        float s = 0.f;
        for (int d = 0; d < 3; d++) s += g_eamean[d] * g_ve[l * 12 + d * 4 + h];
        g_ae_self[tid] = s;
    }
}

__global__ void k_ae_all(const float* __restrict__ ea) {
    int e = blockIdx.x * blockDim.x + threadIdx.x;
    if (e >= N_EDGES) return;
    float a0 = ea[e * 3 + 0], a1 = ea[e * 3 + 1], a2 = ea[e * 3 + 2];
    #pragma unroll
    for (int l = 0; l < 4; l++) {
        float4 v;
        v.x = a0 * g_ve[l * 12 + 0] + a1 * g_ve[l * 12 + 4] + a2 * g_ve[l * 12 + 8];
        v.y = a0 * g_ve[l * 12 + 1] + a1 * g_ve[l * 12 + 5] + a2 * g_ve[l * 12 + 9];
        v.z = a0 * g_ve[l * 12 + 2] + a1 * g_ve[l * 12 + 6] + a2 * g_ve[l * 12 + 10];
        v.w = a0 * g_ve[l * 12 + 3] + a1 * g_ve[l * 12 + 7] + a2 * g_ve[l * 12 + 11];
        *(float4*)&g_ae_all[(size_t)l * N_EDGES * 4 + e * 4] = v;
    }
}

// ---------------- CSR build ---------------------------------------------------
__global__ void k_zero_cnt() {
    int n = blockIdx.x * blockDim.x + threadIdx.x;
    if (n < N_NODES) g_cnt[n] = 0;
}
__global__ void k_count(const int* __restrict__ ei) {
    int e = blockIdx.x * blockDim.x + threadIdx.x;
    if (e >= N_EDGES) return;
    atomicAdd(&g_cnt[ei[N_EDGES + e]], 1);
}
__global__ void k_scan() {
    __shared__ int ssum[1024];
    const int SEG = 20;
    int tid = threadIdx.x;
    int base = tid * SEG;
    int cnts[SEG];
    int tot = 0;
    #pragma unroll
    for (int j = 0; j < SEG; j++) {
        int idx = base + j;
        cnts[j] = (idx < N_NODES) ? g_cnt[idx] : 0;
        tot += cnts[j];
    }
    ssum[tid] = tot;
    __syncthreads();
    for (int off = 1; off < 1024; off <<= 1) {
        int v = (tid >= off) ? ssum[tid - off] : 0;
        __syncthreads();
        ssum[tid] += v;
        __syncthreads();
    }
    int run = ssum[tid] - tot;
    #pragma unroll
    for (int j = 0; j < SEG; j++) {
        int idx = base + j;
        if (idx < N_NODES) {
            g_rowptr[idx] = run;
            g_cursor[idx] = run;
            run += cnts[j];
        } else if (idx == N_NODES) {
            g_rowptr[N_NODES] = run;
        }
    }
}
__global__ void k_scatter(const int* __restrict__ ei) {
    int e = blockIdx.x * blockDim.x + threadIdx.x;
    if (e >= N_EDGES) return;
    int src = ei[e];
    int dst = ei[N_EDGES + e];
    int pos = atomicAdd(&g_cursor[dst], 1);
    g_eid[pos] = e;
    g_esrc[pos] = src;
}

// ------- weight transpose + bf16 hi/mid split: WT[l][n][k/2 packed] ----------
__global__ void k_transpose(const float* __restrict__ W) {
    __shared__ float t[32][33];
    int l = blockIdx.z;
    int k0 = blockIdx.y * 32, n0 = blockIdx.x * 32;
    int tx = threadIdx.x, ty = threadIdx.y;
    const float* Wl = W + (size_t)l * 1024 * 1024;
    #pragma unroll
    for (int i = 0; i < 4; i++)
        t[ty + i * 8][tx] = Wl[(size_t)(k0 + ty + i * 8) * 1024 + n0 + tx];
    __syncthreads();
    if (tx < 16) {
        uint32_t* Hi = g_WThi + (size_t)l * 1024 * 512;
        uint32_t* Mi = g_WTmid + (size_t)l * 1024 * 512;
        #pragma unroll
        for (int i = 0; i < 4; i++) {
            int nl = ty + i * 8;
            int n = n0 + nl;
            uint32_t hi, mid;
            split2(t[2 * tx][nl], t[2 * tx + 1][nl], hi, mid);
            Hi[(size_t)n * 512 + (k0 >> 1) + tx] = hi;
            Mi[(size_t)n * 512 + (k0 >> 1) + tx] = mid;
        }
    }
}

// ---------------- layer-0 GEMM: T = x(N,7) @ w0(7,1024) ----------------------
__global__ void k_gemm0(const float* __restrict__ x, const float* __restrict__ w0) {
    __shared__ float xr[F_INP];
    int n = blockIdx.x, tid = threadIdx.x;
    if (tid < F_INP) xr[tid] = x[n * F_INP + tid];
    __syncthreads();
    #pragma unroll
    for (int j = 0; j < 4; j++) {
        int f = tid + j * 256;
        float acc = 0.f;
        #pragma unroll
        for (int d = 0; d < F_INP; d++) acc += xr[d] * w0[d * HC + f];
        g_T[(size_t)n * HC + f] = acc;
    }
}

// =============== mma.sync bf16x3 GEMM (presplit inputs, cp.async) =============
// Block 128x128, warps 2x4, K chunk 32 (16 packed uint32), double-buffered.
#define NCHUNK 32
#define SROW 20                        // uint32 stride per m/n row in smem
#define OFF_AHI  0
#define OFF_AMID 10240
#define OFF_BHI  20480
#define OFF_BMID 30720
#define STG2     40960
#define GEMM_SMEM (2 * STG2)           // 81920 B

__global__ void __launch_bounds__(256, 2) k_mmagemm(int layer) {
    extern __shared__ char smem[];
    uint32_t sb = smem_u32(smem);
    int tid = threadIdx.x;
    int wid = tid >> 5;
    int lane = tid & 31;
    int g = lane >> 2, tig = lane & 3;
    int wm = wid >> 2;
    int wn = wid & 3;
    int m0 = blockIdx.y * 128;
    int n0 = blockIdx.x * 128;

    const uint32_t* Whi = g_WThi + (size_t)(layer - 1) * 1024 * 512;
    const uint32_t* Wmid = g_WTmid + (size_t)(layer - 1) * 1024 * 512;

    int lm = tid >> 1;
    int half = tid & 1;
    const uint32_t* gAh = g_Xhi + (size_t)(m0 + lm) * 512 + half * 8;
    const uint32_t* gAm = g_Xmid + (size_t)(m0 + lm) * 512 + half * 8;
    const uint32_t* gBh = Whi + (size_t)(n0 + lm) * 512 + half * 8;
    const uint32_t* gBm = Wmid + (size_t)(n0 + lm) * 512 + half * 8;
    uint32_t dstrow = sb + lm * 80 + half * 32;

    float acc[4][4][4];
    #pragma unroll
    for (int i = 0; i < 4; i++)
        #pragma unroll
        for (int j = 0; j < 4; j++)
            #pragma unroll
            for (int q = 0; q < 4; q++) acc[i][j][q] = 0.f;

    // prologue: stage 0
    {
        uint32_t d = dstrow;
        cp16(d + OFF_AHI, gAh);       cp16(d + OFF_AHI + 16, gAh + 4);
        cp16(d + OFF_AMID, gAm);      cp16(d + OFF_AMID + 16, gAm + 4);
        cp16(d + OFF_BHI, gBh);       cp16(d + OFF_BHI + 16, gBh + 4);
        cp16(d + OFF_BMID, gBm);      cp16(d + OFF_BMID + 16, gBm + 4);
        asm volatile("cp.async.commit_group;");
    }

    for (int c = 0; c < NCHUNK; c++) {
        if (c + 1 < NCHUNK) {
            uint32_t d = dstrow + ((c + 1) & 1) * STG2;
            size_t go = (size_t)(c + 1) * 16;
            cp16(d + OFF_AHI, gAh + go);   cp16(d + OFF_AHI + 16, gAh + go + 4);
            cp16(d + OFF_AMID, gAm + go);  cp16(d + OFF_AMID + 16, gAm + go + 4);
            cp16(d + OFF_BHI, gBh + go);   cp16(d + OFF_BHI + 16, gBh + go + 4);
            cp16(d + OFF_BMID, gBm + go);  cp16(d + OFF_BMID + 16, gBm + go + 4);
            asm volatile("cp.async.commit_group;");
            asm volatile("cp.async.wait_group 1;");
        } else {
            asm volatile("cp.async.wait_group 0;");
        }
        __syncthreads();

        const char* stg = smem + (c & 1) * STG2;
        const uint32_t* Ah = (const uint32_t*)(stg + OFF_AHI);
        const uint32_t* Am = (const uint32_t*)(stg + OFF_AMID);
        const uint32_t* Bh = (const uint32_t*)(stg + OFF_BHI);
        const uint32_t* Bm = (const uint32_t*)(stg + OFF_BMID);
        #pragma unroll
        for (int ks = 0; ks < 2; ks++) {
            int kb = ks * 8 + tig;
            uint32_t ah[4][4], am[4][4];
            #pragma unroll
            for (int mt = 0; mt < 4; mt++) {
                int mb = wm * 64 + mt * 16 + g;
                ah[mt][0] = Ah[mb * SROW + kb];
                ah[mt][1] = Ah[(mb + 8) * SROW + kb];
                ah[mt][2] = Ah[mb * SROW + kb + 4];
                ah[mt][3] = Ah[(mb + 8) * SROW + kb + 4];
                am[mt][0] = Am[mb * SROW + kb];
                am[mt][1] = Am[(mb + 8) * SROW + kb];
                am[mt][2] = Am[mb * SROW + kb + 4];
                am[mt][3] = Am[(mb + 8) * SROW + kb + 4];
            }
            #pragma unroll
            for (int nt = 0; nt < 4; nt++) {
                int nb = wn * 32 + nt * 8 + g;
                uint32_t bh0 = Bh[nb * SROW + kb];
                uint32_t bh1 = Bh[nb * SROW + kb + 4];
                uint32_t bm0 = Bm[nb * SROW + kb];
                uint32_t bm1 = Bm[nb * SROW + kb + 4];
                #pragma unroll
                for (int mt = 0; mt < 4; mt++) {
                    mma_bf16(acc[mt][nt], ah[mt][0], ah[mt][1], ah[mt][2], ah[mt][3], bh0, bh1);
                    mma_bf16(acc[mt][nt], ah[mt][0], ah[mt][1], ah[mt][2], ah[mt][3], bm0, bm1);
                    mma_bf16(acc[mt][nt], am[mt][0], am[mt][1], am[mt][2], am[mt][3], bh0, bh1);
                }
            }
        }
        __syncthreads();
    }

    #pragma unroll
    for (int mt = 0; mt < 4; mt++) {
        int row0 = m0 + wm * 64 + mt * 16 + g;
        #pragma unroll
        for (int nt = 0; nt < 4; nt++) {
            int col = n0 + wn * 32 + nt * 8 + tig * 2;
            if (row0 < N_NODES)
                *(float2*)(g_T + (size_t)row0 * HC + col) = make_float2(acc[mt][nt][0], acc[mt][nt][1]);
            if (row0 + 8 < N_NODES)
                *(float2*)(g_T + (size_t)(row0 + 8) * HC + col) = make_float2(acc[mt][nt][2], acc[mt][nt][3]);
        }
    }
}

// ---------------- per-node alpha_src / alpha_dst (float4) ---------------------
__global__ void k_alpha(const float* __restrict__ att_src, const float* __restrict__ att_dst, int l) {
    int n = blockIdx.x;
    int warp = threadIdx.x >> 5, lane = threadIdx.x & 31;
    const float* hr = g_T + (size_t)n * HC + warp * CH;
    const float* as = att_src + (size_t)l * HC + warp * CH;
    const float* ad = att_dst + (size_t)l * HC + warp * CH;
    float s1 = 0.f, s2 = 0.f;
    #pragma unroll
    for (int it = 0; it < 2; it++) {
        int c = (lane + it * 32) * 4;
        float4 v = *(const float4*)(hr + c);
        float4 a = *(const float4*)(as + c);
        float4 d = *(const float4*)(ad + c);
        s1 += v.x * a.x + v.y * a.y + v.z * a.z + v.w * a.w;
        s2 += v.x * d.x + v.y * d.y + v.z * d.z + v.w * d.w;
    }
    #pragma unroll
    for (int o = 16; o > 0; o >>= 1) {
        s1 += __shfl_down_sync(0xffffffffu, s1, o);
        s2 += __shfl_down_sync(0xffffffffu, s2, o);
    }
    if (lane == 0) {
        g_asrc[n * 4 + warp] = s1;
        g_adst[n * 4 + warp] = s2;
    }
}

// ---------------- precompute softmax attention weights ------------------------
__global__ void k_attw(int l) {
    int n = blockIdx.x * blockDim.x + threadIdx.x;
    if (n >= N_NODES) return;
    const float* ae = g_ae_all + (size_t)l * N_EDGES * 4;
    int s = g_rowptr[n], t = g_rowptr[n + 1];

    float4 ad4 = *(const float4*)&g_adst[n * 4];
    float4 as4 = *(const float4*)&g_asrc[n * 4];
    float ad[4] = {ad4.x, ad4.y, ad4.z, ad4.w};
    float aself[4], m[4];
    #pragma unroll
    for (int h = 0; h < 4; h++) {
        aself[h] = lrelu(((const float*)&as4)[h] + ad[h] + g_ae_self[l * 4 + h]);
        m[h] = aself[h];
    }
    for (int i = s; i < t; i++) {
        int e = g_eid[i], src = g_esrc[i];
        float4 av = *(const float4*)&g_asrc[src * 4];
        float4 ev = *(const float4*)&ae[e * 4];
        #pragma unroll
        for (int h = 0; h < 4; h++) {
            float a = lrelu(((const float*)&av)[h] + ad[h] + ((const float*)&ev)[h]);
            m[h] = fmaxf(m[h], a);
        }
    }
    float sum[4];
    #pragma unroll
    for (int h = 0; h < 4; h++) sum[h] = expf(aself[h] - m[h]);
    for (int i = s; i < t; i++) {
        int e = g_eid[i], src = g_esrc[i];
        float4 av = *(const float4*)&g_asrc[src * 4];
        float4 ev = *(const float4*)&ae[e * 4];
        #pragma unroll
        for (int h = 0; h < 4; h++) {
            float a = lrelu(((const float*)&av)[h] + ad[h] + ((const float*)&ev)[h]);
            sum[h] += expf(a - m[h]);
        }
    }
    float inv[4];
    #pragma unroll
    for (int h = 0; h < 4; h++) inv[h] = 1.f / (sum[h] + 1e-16f);

    float4 ws;
    ((float*)&ws)[0] = expf(aself[0] - m[0]) * inv[0];
    ((float*)&ws)[1] = expf(aself[1] - m[1]) * inv[1];
    ((float*)&ws)[2] = expf(aself[2] - m[2]) * inv[2];
    ((float*)&ws)[3] = expf(aself[3] - m[3]) * inv[3];
    *(float4*)&g_wself[n * 4] = ws;

    for (int i = s; i < t; i++) {
        int e = g_eid[i], src = g_esrc[i];
        float4 av = *(const float4*)&g_asrc[src * 4];
        float4 ev = *(const float4*)&ae[e * 4];
        float4 w;
        #pragma unroll
        for (int h = 0; h < 4; h++) {
            float a = lrelu(((const float*)&av)[h] + ad[h] + ((const float*)&ev)[h]);
            ((float*)&w)[h] = expf(a - m[h]) * inv[h];
        }
        *(float4*)&g_wedge[i * 4] = w;
    }
}

// ---------------- weighted gather + bias (+BN+ReLU) ---------------------------
// concat layers: writes bf16 hi/mid split (GEMM input); last layer: fp32 g_X.
__global__ __launch_bounds__(256) void k_agg(
    int l, int concat,
    const float* __restrict__ bias012, const float* __restrict__ bias3,
    const float* __restrict__ gamma, const float* __restrict__ beta,
    const float* __restrict__ mean, const float* __restrict__ var) {
    int n = blockIdx.x;
    int tid = threadIdx.x;
    int s = g_rowptr[n], t = g_rowptr[n + 1];

    if (concat) {
        int head = tid >> 6;
        int c4 = (tid & 63) << 2;
        int f = head * CH + c4;
        float wself = g_wself[n * 4 + head];
        float4 acc = *(const float4*)(g_T + (size_t)n * HC + f);
        acc.x *= wself; acc.y *= wself; acc.z *= wself; acc.w *= wself;
        for (int i = s; i < t; i++) {
            int src = g_esrc[i];
            float w = g_wedge[i * 4 + head];
            float4 v = *(const float4*)(g_T + (size_t)src * HC + f);
            acc.x += w * v.x; acc.y += w * v.y; acc.z += w * v.z; acc.w += w * v.w;
        }
        size_t pf = (size_t)l * HC + f;
        float4 bv = *(const float4*)(bias012 + pf);
        float4 gv = *(const float4*)(gamma + pf);
        float4 be = *(const float4*)(beta + pf);
        float4 mn = *(const float4*)(mean + pf);
        float4 vr = *(const float4*)(var + pf);
        float4 o;
        o.x = fmaxf((acc.x + bv.x - mn.x) * (gv.x * rsqrtf(vr.x + 1e-5f)) + be.x, 0.f);
        o.y = fmaxf((acc.y + bv.y - mn.y) * (gv.y * rsqrtf(vr.y + 1e-5f)) + be.y, 0.f);
        o.z = fmaxf((acc.z + bv.z - mn.z) * (gv.z * rsqrtf(vr.z + 1e-5f)) + be.z, 0.f);
        o.w = fmaxf((acc.w + bv.w - mn.w) * (gv.w * rsqrtf(vr.w + 1e-5f)) + be.w, 0.f);
        uint32_t h0, m0, h1, m1;
        split2(o.x, o.y, h0, m0);
        split2(o.z, o.w, h1, m1);
        size_t pc = (size_t)n * 512 + (f >> 1);
        *(uint2*)&g_Xhi[pc] = make_uint2(h0, h1);
        *(uint2*)&g_Xmid[pc] = make_uint2(m0, m1);
    } else {
        int c = tid;
        float4 ws = *(const float4*)&g_wself[n * 4];
        const float* hn = g_T + (size_t)n * HC;
        float acc = ws.x * hn[c] + ws.y * hn[CH + c] + ws.z * hn[2 * CH + c] + ws.w * hn[3 * CH + c];
        for (int i = s; i < t; i++) {
            int src = g_esrc[i];
            float4 w = *(const float4*)&g_wedge[i * 4];
            const float* hs = g_T + (size_t)src * HC;
            acc += w.x * hs[c] + w.y * hs[CH + c] + w.z * hs[2 * CH + c] + w.w * hs[3 * CH + c];
        }
        g_X[(size_t)n * CH + c] = 0.25f * acc + bias3[c];
    }
}

// ---------------- gate scores -------------------------------------------------
__global__ void k_gate(const float* __restrict__ gate_w, const float* __restrict__ gate_b) {
    int warp = threadIdx.x >> 5, lane = threadIdx.x & 31;
    int n = blockIdx.x * 8 + warp;
    if (n >= N_NODES) return;
    const float* hr = g_X + (size_t)n * CH;
    float s = 0.f;
    #pragma unroll
    for (int it = 0; it < 2; it++) {
        int c = (lane + it * 32) * 4;
        float4 v = *(const float4*)(hr + c);
        float4 w = *(const float4*)(gate_w + c);
        s += v.x * w.x + v.y * w.y + v.z * w.z + v.w * w.w;
    }
    #pragma unroll
    for (int o = 16; o > 0; o >>= 1) s += __shfl_down_sync(0xffffffffu, s, o);
    if (lane == 0) g_gate[n] = s + gate_b[0];
}

// ---------------- per-graph softmax pooling -----------------------------------
__device__ __forceinline__ int lb_batch(const int* __restrict__ batch, int target) {
    int lo = 0, hi = N_NODES;
    while (lo < hi) {
        int mid = (lo + hi) >> 1;
        if (batch[mid] < target) lo = mid + 1; else hi = mid;
    }
    return lo;
}
__global__ void k_pool(const int* __restrict__ batch) {
    int b = blockIdx.x;
    int c = threadIdx.x;
    int s = lb_batch(batch, b);
    int e = lb_batch(batch, b + 1);
    if (s == e) { g_graph[b * CH + c] = 0.f; return; }
    float mx = -1e30f;
    for (int n = s; n < e; n++) mx = fmaxf(mx, g_gate[n]);
    float sum = 0.f;
    for (int n = s; n < e; n++) sum += expf(g_gate[n] - mx);
    float inv = 1.f / (sum + 1e-16f);
    float acc = 0.f;
    for (int n = s; n < e; n++)
        acc += expf(g_gate[n] - mx) * inv * g_X[(size_t)n * CH + c];
    g_graph[b * CH + c] = acc;
}

// ---------------- final projection --------------------------------------------
__global__ __launch_bounds__(256) void k_proj(const float* __restrict__ proj_w,
                                              const float* __restrict__ proj_b,
                                              float* __restrict__ out) {
    __shared__ float sg[8][CH];
    int b0 = blockIdx.x * 8;
    int tid = threadIdx.x;
    #pragma unroll
    for (int g = 0; g < 8; g++) sg[g][tid] = g_graph[(b0 + g) * CH + tid];
    __syncthreads();
    float acc[8][4];
    #pragma unroll
    for (int g = 0; g < 8; g++)
        #pragma unroll
        for (int j = 0; j < 4; j++) acc[g][j] = 0.f;
    for (int cIt = 0; cIt < CH; cIt++) {
        float w0 = proj_w[cIt * 1024 + tid];
        float w1 = proj_w[cIt * 1024 + tid + 256];
        float w2 = proj_w[cIt * 1024 + tid + 512];
        float w3 = proj_w[cIt * 1024 + tid + 768];
        #pragma unroll
        for (int g = 0; g < 8; g++) {
            float sv = sg[g][cIt];
            acc[g][0] += sv * w0;
            acc[g][1] += sv * w1;
            acc[g][2] += sv * w2;
            acc[g][3] += sv * w3;
        }
    }
    #pragma unroll
    for (int g = 0; g < 8; g++)
        #pragma unroll
        for (int j = 0; j < 4; j++)
            out[(size_t)(b0 + g) * 1024 + tid + j * 256] = acc[g][j] + proj_b[tid + j * 256];
}

// ---------------- host orchestration ------------------------------------------
extern "C" void kernel_launch(void* const* d_in, const int* in_sizes, int n_in,
                              void* d_out, int out_size) {
    (void)in_sizes; (void)n_in; (void)out_size;
    const float* x        = (const float*)d_in[0];
    const int*   ei       = (const int*)d_in[1];
    const float* ea       = (const float*)d_in[2];
    const int*   batch    = (const int*)d_in[3];
    const float* w0       = (const float*)d_in[4];
    const float* w_rest   = (const float*)d_in[5];
    const float* w_edge   = (const float*)d_in[6];
    const float* att_src  = (const float*)d_in[7];
    const float* att_dst  = (const float*)d_in[8];
    const float* att_edge = (const float*)d_in[9];
    const float* bias012  = (const float*)d_in[10];
    const float* bias3    = (const float*)d_in[11];
    const float* bn_gamma = (const float*)d_in[12];
    const float* bn_beta  = (const float*)d_in[13];
    const float* bn_mean  = (const float*)d_in[14];
    const float* bn_var   = (const float*)d_in[15];
    const float* gate_w   = (const float*)d_in[16];
    const float* gate_b   = (const float*)d_in[17];
    const float* proj_w   = (const float*)d_in[18];
    const float* proj_b   = (const float*)d_in[19];
    float* out = (float*)d_out;

    cudaFuncSetAttribute(k_mmagemm, cudaFuncAttributeMaxDynamicSharedMemorySize, GEMM_SMEM);

    k_zero_cnt<<<(N_NODES + 255) / 256, 256>>>();
    k_count<<<(N_EDGES + 255) / 256, 256>>>(ei);
    k_scan<<<1, 1024>>>();
    k_scatter<<<(N_EDGES + 255) / 256, 256>>>(ei);
    k_transpose<<<dim3(32, 32, 3), dim3(32, 8)>>>(w_rest);
    k_gemm0<<<N_NODES, 256>>>(x, w0);
    k_meanve<<<1, 256>>>(ea, w_edge, att_edge);
    k_ae_all<<<(N_EDGES + 127) / 128, 128>>>(ea);

    for (int l = 0; l < 4; l++) {
        if (l > 0) {
            k_mmagemm<<<dim3(8, (N_NODES + 127) / 128), 256, GEMM_SMEM>>>(l);
        }
        k_alpha<<<N_NODES, 128>>>(att_src, att_dst, l);
        k_attw<<<(N_NODES + 255) / 256, 256>>>(l);
        k_agg<<<N_NODES, 256>>>(l, l < 3 ? 1 : 0, bias012, bias3,
                                bn_gamma, bn_beta, bn_mean, bn_var);
    }

    k_gate<<<(N_NODES + 7) / 8, 256>>>(gate_w, gate_b);
    k_pool<<<N_GRAPH, 256>>>(batch);
    k_proj<<<N_GRAPH / 8, 256>>>(proj_w, proj_b, out);
}

// round 6
// speedup vs baseline: 2.4977x; 1.0510x over previous
#include <cuda_runtime.h>
#include <cuda_bf16.h>
#include <cstdint>
#include <math.h>

#define N_NODES 20000
#define N_PAD   20096            // 157 * 128
#define N_EDGES 60000
#define N_GRAPH 512
#define F_INP   7
#define HC      1024
#define NH      4
#define CH      256

// ---------------- scratch (static device globals; no allocation) -------------
__device__ float    g_X[(size_t)N_NODES * CH];     // final-layer output (l=3)
__device__ float    g_T[(size_t)N_NODES * HC];     // transformed h = X @ W
__device__ uint32_t g_Xhi[(size_t)N_PAD * 512];    // activation bf16-hi packed pairs
__device__ uint32_t g_Xmid[(size_t)N_PAD * 512];   // activation bf16-mid packed pairs
__device__ uint32_t g_WThi[3 * 1024 * 512];        // weight^T bf16-hi packed
__device__ uint32_t g_WTmid[3 * 1024 * 512];       // weight^T bf16-mid packed
__device__ float    g_asrc[N_NODES * NH];
__device__ float    g_adst[N_NODES * NH];
__device__ float    g_ae_all[4 * N_EDGES * NH];
__device__ float    g_ve[48];
__device__ float    g_ae_self[16];
__device__ float    g_eamean[3];
__device__ int      g_cnt[N_NODES];
__device__ int      g_rowptr[N_NODES + 1];
__device__ int      g_cursor[N_NODES];
__device__ int      g_eid[N_EDGES];
__device__ int      g_esrc[N_EDGES];
__device__ float    g_wedge[N_EDGES * NH];
__device__ float    g_wself[N_NODES * NH];
__device__ float    g_gate[N_NODES];
__device__ float    g_graph[N_GRAPH * CH];

__device__ __forceinline__ float lrelu(float a) { return a > 0.f ? a : 0.2f * a; }

__device__ __forceinline__ void split2(float x, float y, uint32_t& hi, uint32_t& mid) {
    __nv_bfloat16 hx = __float2bfloat16_rn(x);
    __nv_bfloat16 hy = __float2bfloat16_rn(y);
    __nv_bfloat16 mx = __float2bfloat16_rn(x - __bfloat162float(hx));
    __nv_bfloat16 my = __float2bfloat16_rn(y - __bfloat162float(hy));
    hi  = (uint32_t)__bfloat16_as_ushort(hx) | ((uint32_t)__bfloat16_as_ushort(hy) << 16);
    mid = (uint32_t)__bfloat16_as_ushort(mx) | ((uint32_t)__bfloat16_as_ushort(my) << 16);
}

__device__ __forceinline__ uint32_t smem_u32(const void* p) {
    uint32_t a;
    asm("{ .reg .u64 t; cvta.to.shared.u64 t, %1; cvt.u32.u64 %0, t; }" : "=r"(a) : "l"(p));
    return a;
}
__device__ __forceinline__ void cp16(uint32_t dst, const void* src) {
    asm volatile("cp.async.cg.shared.global [%0], [%1], 16;" :: "r"(dst), "l"(src));
}
__device__ __forceinline__ void ldsm4(uint32_t* d, uint32_t addr) {
    asm volatile("ldmatrix.sync.aligned.m8n8.x4.shared.b16 {%0,%1,%2,%3}, [%4];"
                 : "=r"(d[0]), "=r"(d[1]), "=r"(d[2]), "=r"(d[3]) : "r"(addr));
}
__device__ __forceinline__ void mma_bf16(float* c, uint32_t a0, uint32_t a1,
                                         uint32_t a2, uint32_t a3,
                                         uint32_t b0, uint32_t b1) {
    asm volatile(
        "mma.sync.aligned.m16n8k16.row.col.f32.bf16.bf16.f32 "
        "{%0,%1,%2,%3}, {%4,%5,%6,%7}, {%8,%9}, {%0,%1,%2,%3};"
        : "+f"(c[0]), "+f"(c[1]), "+f"(c[2]), "+f"(c[3])
        : "r"(a0), "r"(a1), "r"(a2), "r"(a3), "r"(b0), "r"(b1));
}

// ---------------- edge_attr mean + ve + self-loop attention (fused) ----------
__global__ void k_meanve(const float* __restrict__ ea,
                         const float* __restrict__ w_edge,
                         const float* __restrict__ att_edge) {
    __shared__ float red[3][256];
    int tid = threadIdx.x;
    float a0 = 0.f, a1 = 0.f, a2 = 0.f;
    for (int e = tid; e < N_EDGES; e += 256) {
        a0 += ea[e * 3 + 0]; a1 += ea[e * 3 + 1]; a2 += ea[e * 3 + 2];
    }
    red[0][tid] = a0; red[1][tid] = a1; red[2][tid] = a2;
    __syncthreads();
    for (int s = 128; s > 0; s >>= 1) {
        if (tid < s) {
            red[0][tid] += red[0][tid + s];
            red[1][tid] += red[1][tid + s];
            red[2][tid] += red[2][tid + s];
        }
        __syncthreads();
    }
    if (tid < 3) g_eamean[tid] = red[tid][0] * (1.f / (float)N_EDGES);
    __syncthreads();

    int warp = tid >> 5, lane = tid & 31;
    for (int idx = warp; idx < 48; idx += 8) {
        int l = idx / 12, r = idx % 12, d = r / 4, h = r % 4;
        const float* w = w_edge + (size_t)l * 3 * HC + (size_t)d * HC + h * CH;
        const float* a = att_edge + (size_t)l * HC + h * CH;
        float s = 0.f;
        for (int c = lane; c < CH; c += 32) s += w[c] * a[c];
        #pragma unroll
        for (int o = 16; o > 0; o >>= 1) s += __shfl_down_sync(0xffffffffu, s, o);
        if (lane == 0) g_ve[idx] = s;
    }
    __syncthreads();
    if (tid < 16) {
        int l = tid >> 2, h = tid & 3;
        float s = 0.f;
        for (int d = 0; d < 3; d++) s += g_eamean[d] * g_ve[l * 12 + d * 4 + h];
        g_ae_self[tid] = s;
    }
}

__global__ void k_ae_all(const float* __restrict__ ea) {
    int e = blockIdx.x * blockDim.x + threadIdx.x;
    if (e >= N_EDGES) return;
    float a0 = ea[e * 3 + 0], a1 = ea[e * 3 + 1], a2 = ea[e * 3 + 2];
    #pragma unroll
    for (int l = 0; l < 4; l++) {
        float4 v;
        v.x = a0 * g_ve[l * 12 + 0] + a1 * g_ve[l * 12 + 4] + a2 * g_ve[l * 12 + 8];
        v.y = a0 * g_ve[l * 12 + 1] + a1 * g_ve[l * 12 + 5] + a2 * g_ve[l * 12 + 9];
        v.z = a0 * g_ve[l * 12 + 2] + a1 * g_ve[l * 12 + 6] + a2 * g_ve[l * 12 + 10];
        v.w = a0 * g_ve[l * 12 + 3] + a1 * g_ve[l * 12 + 7] + a2 * g_ve[l * 12 + 11];
        *(float4*)&g_ae_all[(size_t)l * N_EDGES * 4 + e * 4] = v;
    }
}

// ---------------- CSR build ---------------------------------------------------
__global__ void k_zero_cnt() {
    int n = blockIdx.x * blockDim.x + threadIdx.x;
    if (n < N_NODES) g_cnt[n] = 0;
}
__global__ void k_count(const int* __restrict__ ei) {
    int e = blockIdx.x * blockDim.x + threadIdx.x;
    if (e >= N_EDGES) return;
    atomicAdd(&g_cnt[ei[N_EDGES + e]], 1);
}
__global__ void k_scan() {
    __shared__ int ssum[1024];
    const int SEG = 20;
    int tid = threadIdx.x;
    int base = tid * SEG;
    int cnts[SEG];
    int tot = 0;
    #pragma unroll
    for (int j = 0; j < SEG; j++) {
        int idx = base + j;
        cnts[j] = (idx < N_NODES) ? g_cnt[idx] : 0;
        tot += cnts[j];
    }
    ssum[tid] = tot;
    __syncthreads();
    for (int off = 1; off < 1024; off <<= 1) {
        int v = (tid >= off) ? ssum[tid - off] : 0;
        __syncthreads();
        ssum[tid] += v;
        __syncthreads();
    }
    int run = ssum[tid] - tot;
    #pragma unroll
    for (int j = 0; j < SEG; j++) {
        int idx = base + j;
        if (idx < N_NODES) {
            g_rowptr[idx] = run;
            g_cursor[idx] = run;
            run += cnts[j];
        } else if (idx == N_NODES) {
            g_rowptr[N_NODES] = run;
        }
    }
}
__global__ void k_scatter(const int* __restrict__ ei) {
    int e = blockIdx.x * blockDim.x + threadIdx.x;
    if (e >= N_EDGES) return;
    int src = ei[e];
    int dst = ei[N_EDGES + e];
    int pos = atomicAdd(&g_cursor[dst], 1);
    g_eid[pos] = e;
    g_esrc[pos] = src;
}

// ------- weight transpose + bf16 hi/mid split: WT[l][n][k/2 packed] ----------
__global__ void k_transpose(const float* __restrict__ W) {
    __shared__ float t[32][33];
    int l = blockIdx.z;
    int k0 = blockIdx.y * 32, n0 = blockIdx.x * 32;
    int tx = threadIdx.x, ty = threadIdx.y;
    const float* Wl = W + (size_t)l * 1024 * 1024;
    #pragma unroll
    for (int i = 0; i < 4; i++)
        t[ty + i * 8][tx] = Wl[(size_t)(k0 + ty + i * 8) * 1024 + n0 + tx];
    __syncthreads();
    if (tx < 16) {
        uint32_t* Hi = g_WThi + (size_t)l * 1024 * 512;
        uint32_t* Mi = g_WTmid + (size_t)l * 1024 * 512;
        #pragma unroll
        for (int i = 0; i < 4; i++) {
            int nl = ty + i * 8;
            int n = n0 + nl;
            uint32_t hi, mid;
            split2(t[2 * tx][nl], t[2 * tx + 1][nl], hi, mid);
            Hi[(size_t)n * 512 + (k0 >> 1) + tx] = hi;
            Mi[(size_t)n * 512 + (k0 >> 1) + tx] = mid;
        }
    }
}

// ---------------- layer-0 GEMM: T = x(N,7) @ w0(7,1024) ----------------------
__global__ void k_gemm0(const float* __restrict__ x, const float* __restrict__ w0) {
    __shared__ float xr[F_INP];
    int n = blockIdx.x, tid = threadIdx.x;
    if (tid < F_INP) xr[tid] = x[n * F_INP + tid];
    __syncthreads();
    #pragma unroll
    for (int j = 0; j < 4; j++) {
        int f = tid + j * 256;
        float acc = 0.f;
        #pragma unroll
        for (int d = 0; d < F_INP; d++) acc += xr[d] * w0[d * HC + f];
        g_T[(size_t)n * HC + f] = acc;
    }
}

// =============== mma.sync bf16x3 GEMM (presplit, cp.async, ldmatrix) ==========
// Block 128x128, warps 2x4, K chunk 32 (16 packed uint32), double-buffered.
#define NCHUNK 32
#define SROWB 80                       // byte stride per m/n row in smem
#define OFF_AHI  0
#define OFF_AMID 10240
#define OFF_BHI  20480
#define OFF_BMID 30720
#define STG2     40960
#define GEMM_SMEM (2 * STG2)           // 81920 B

__global__ void __launch_bounds__(256, 2) k_mmagemm(int layer) {
    extern __shared__ char smem[];
    uint32_t sb = smem_u32(smem);
    int tid = threadIdx.x;
    int wid = tid >> 5;
    int lane = tid & 31;
    int g = lane >> 2, tig = lane & 3;
    int wm = wid >> 2;
    int wn = wid & 3;
    int m0 = blockIdx.y * 128;
    int n0 = blockIdx.x * 128;

    const uint32_t* Whi = g_WThi + (size_t)(layer - 1) * 1024 * 512;
    const uint32_t* Wmid = g_WTmid + (size_t)(layer - 1) * 1024 * 512;

    // cp.async loader geometry
    int lm = tid >> 1;
    int half = tid & 1;
    const uint32_t* gAh = g_Xhi + (size_t)(m0 + lm) * 512 + half * 8;
    const uint32_t* gAm = g_Xmid + (size_t)(m0 + lm) * 512 + half * 8;
    const uint32_t* gBh = Whi + (size_t)(n0 + lm) * 512 + half * 8;
    const uint32_t* gBm = Wmid + (size_t)(n0 + lm) * 512 + half * 8;
    uint32_t dstrow = sb + lm * SROWB + half * 32;

    // ldmatrix per-thread base offsets
    int q = lane >> 3, r = lane & 7;
    uint32_t aoff[4], boff[2];
    {
        int arow = (q & 1) * 8 + r;
        int acol = (q >> 1) * 16;
        #pragma unroll
        for (int mt = 0; mt < 4; mt++)
            aoff[mt] = (uint32_t)((wm * 64 + mt * 16 + arow) * SROWB + acol);
        int brow = (q >> 1) * 8 + r;
        int bcol = (q & 1) * 16;
        #pragma unroll
        for (int ntp = 0; ntp < 2; ntp++)
            boff[ntp] = (uint32_t)((wn * 32 + ntp * 16 + brow) * SROWB + bcol);
    }

    float acc[4][4][4];
    #pragma unroll
    for (int i = 0; i < 4; i++)
        #pragma unroll
        for (int j = 0; j < 4; j++)
            #pragma unroll
            for (int qq = 0; qq < 4; qq++) acc[i][j][qq] = 0.f;

    // prologue: stage 0
    {
        uint32_t d = dstrow;
        cp16(d + OFF_AHI, gAh);       cp16(d + OFF_AHI + 16, gAh + 4);
        cp16(d + OFF_AMID, gAm);      cp16(d + OFF_AMID + 16, gAm + 4);
        cp16(d + OFF_BHI, gBh);       cp16(d + OFF_BHI + 16, gBh + 4);
        cp16(d + OFF_BMID, gBm);      cp16(d + OFF_BMID + 16, gBm + 4);
        asm volatile("cp.async.commit_group;");
    }

    for (int c = 0; c < NCHUNK; c++) {
        if (c + 1 < NCHUNK) {
            uint32_t d = dstrow + ((c + 1) & 1) * STG2;
            size_t go = (size_t)(c + 1) * 16;
            cp16(d + OFF_AHI, gAh + go);   cp16(d + OFF_AHI + 16, gAh + go + 4);
            cp16(d + OFF_AMID, gAm + go);  cp16(d + OFF_AMID + 16, gAm + go + 4);
            cp16(d + OFF_BHI, gBh + go);   cp16(d + OFF_BHI + 16, gBh + go + 4);
            cp16(d + OFF_BMID, gBm + go);  cp16(d + OFF_BMID + 16, gBm + go + 4);
            asm volatile("cp.async.commit_group;");
            asm volatile("cp.async.wait_group 1;");
        } else {
            asm volatile("cp.async.wait_group 0;");
        }
        __syncthreads();

        uint32_t stq = sb + (c & 1) * STG2;
        #pragma unroll
        for (int ks = 0; ks < 2; ks++) {
            uint32_t kso = (uint32_t)(ks * 32);
            uint32_t bh[2][4], bm[2][4];
            #pragma unroll
            for (int ntp = 0; ntp < 2; ntp++) {
                ldsm4(bh[ntp], stq + OFF_BHI + boff[ntp] + kso);
                ldsm4(bm[ntp], stq + OFF_BMID + boff[ntp] + kso);
            }
            #pragma unroll
            for (int mt = 0; mt < 4; mt++) {
                uint32_t ah[4], am[4];
                ldsm4(ah, stq + OFF_AHI + aoff[mt] + kso);
                ldsm4(am, stq + OFF_AMID + aoff[mt] + kso);
                #pragma unroll
                for (int nt = 0; nt < 4; nt++) {
                    uint32_t b0h = bh[nt >> 1][(nt & 1) * 2 + 0];
                    uint32_t b1h = bh[nt >> 1][(nt & 1) * 2 + 1];
                    uint32_t b0m = bm[nt >> 1][(nt & 1) * 2 + 0];
                    uint32_t b1m = bm[nt >> 1][(nt & 1) * 2 + 1];
                    mma_bf16(acc[mt][nt], ah[0], ah[1], ah[2], ah[3], b0h, b1h);
                    mma_bf16(acc[mt][nt], ah[0], ah[1], ah[2], ah[3], b0m, b1m);
                    mma_bf16(acc[mt][nt], am[0], am[1], am[2], am[3], b0h, b1h);
                }
            }
        }
        __syncthreads();
    }

    #pragma unroll
    for (int mt = 0; mt < 4; mt++) {
        int row0 = m0 + wm * 64 + mt * 16 + g;
        #pragma unroll
        for (int nt = 0; nt < 4; nt++) {
            int col = n0 + wn * 32 + nt * 8 + tig * 2;
            if (row0 < N_NODES)
                *(float2*)(g_T + (size_t)row0 * HC + col) = make_float2(acc[mt][nt][0], acc[mt][nt][1]);
            if (row0 + 8 < N_NODES)
                *(float2*)(g_T + (size_t)(row0 + 8) * HC + col) = make_float2(acc[mt][nt][2], acc[mt][nt][3]);
        }
    }
}

// ---------------- per-node alpha_src / alpha_dst (float4) ---------------------
__global__ void k_alpha(const float* __restrict__ att_src, const float* __restrict__ att_dst, int l) {
    int n = blockIdx.x;
    int warp = threadIdx.x >> 5, lane = threadIdx.x & 31;
    const float* hr = g_T + (size_t)n * HC + warp * CH;
    const float* as = att_src + (size_t)l * HC + warp * CH;
    const float* ad = att_dst + (size_t)l * HC + warp * CH;
    float s1 = 0.f, s2 = 0.f;
    #pragma unroll
    for (int it = 0; it < 2; it++) {
        int c = (lane + it * 32) * 4;
        float4 v = *(const float4*)(hr + c);
        float4 a = *(const float4*)(as + c);
        float4 d = *(const float4*)(ad + c);
        s1 += v.x * a.x + v.y * a.y + v.z * a.z + v.w * a.w;
        s2 += v.x * d.x + v.y * d.y + v.z * d.z + v.w * d.w;
    }
    #pragma unroll
    for (int o = 16; o > 0; o >>= 1) {
        s1 += __shfl_down_sync(0xffffffffu, s1, o);
        s2 += __shfl_down_sync(0xffffffffu, s2, o);
    }
    if (lane == 0) {
        g_asrc[n * 4 + warp] = s1;
        g_adst[n * 4 + warp] = s2;
    }
}

// ---------------- precompute softmax attention weights ------------------------
__global__ void k_attw(int l) {
    int n = blockIdx.x * blockDim.x + threadIdx.x;
    if (n >= N_NODES) return;
    const float* ae = g_ae_all + (size_t)l * N_EDGES * 4;
    int s = g_rowptr[n], t = g_rowptr[n + 1];

    float4 ad4 = *(const float4*)&g_adst[n * 4];
    float4 as4 = *(const float4*)&g_asrc[n * 4];
    float ad[4] = {ad4.x, ad4.y, ad4.z, ad4.w};
    float aself[4], m[4];
    #pragma unroll
    for (int h = 0; h < 4; h++) {
        aself[h] = lrelu(((const float*)&as4)[h] + ad[h] + g_ae_self[l * 4 + h]);
        m[h] = aself[h];
    }
    for (int i = s; i < t; i++) {
        int e = g_eid[i], src = g_esrc[i];
        float4 av = *(const float4*)&g_asrc[src * 4];
        float4 ev = *(const float4*)&ae[e * 4];
        #pragma unroll
        for (int h = 0; h < 4; h++) {
            float a = lrelu(((const float*)&av)[h] + ad[h] + ((const float*)&ev)[h]);
            m[h] = fmaxf(m[h], a);
        }
    }
    float sum[4];
    #pragma unroll
    for (int h = 0; h < 4; h++) sum[h] = expf(aself[h] - m[h]);
    for (int i = s; i < t; i++) {
        int e = g_eid[i], src = g_esrc[i];
        float4 av = *(const float4*)&g_asrc[src * 4];
        float4 ev = *(const float4*)&ae[e * 4];
        #pragma unroll
        for (int h = 0; h < 4; h++) {
            float a = lrelu(((const float*)&av)[h] + ad[h] + ((const float*)&ev)[h]);
            sum[h] += expf(a - m[h]);
        }
    }
    float inv[4];
    #pragma unroll
    for (int h = 0; h < 4; h++) inv[h] = 1.f / (sum[h] + 1e-16f);

    float4 ws;
    ((float*)&ws)[0] = expf(aself[0] - m[0]) * inv[0];
    ((float*)&ws)[1] = expf(aself[1] - m[1]) * inv[1];
    ((float*)&ws)[2] = expf(aself[2] - m[2]) * inv[2];
    ((float*)&ws)[3] = expf(aself[3] - m[3]) * inv[3];
    *(float4*)&g_wself[n * 4] = ws;

    for (int i = s; i < t; i++) {
        int e = g_eid[i], src = g_esrc[i];
        float4 av = *(const float4*)&g_asrc[src * 4];
        float4 ev = *(const float4*)&ae[e * 4];
        float4 w;
        #pragma unroll
        for (int h = 0; h < 4; h++) {
            float a = lrelu(((const float*)&av)[h] + ad[h] + ((const float*)&ev)[h]);
            ((float*)&w)[h] = expf(a - m[h]) * inv[h];
        }
        *(float4*)&g_wedge[i * 4] = w;
    }
}

// ---------------- weighted gather + bias (+BN+ReLU) ---------------------------
__global__ __launch_bounds__(256) void k_agg(
    int l, int concat,
    const float* __restrict__ bias012, const float* __restrict__ bias3,
    const float* __restrict__ gamma, const float* __restrict__ beta,
    const float* __restrict__ mean, const float* __restrict__ var) {
    int n = blockIdx.x;
    int tid = threadIdx.x;
    int s = g_rowptr[n], t = g_rowptr[n + 1];

    if (concat) {
        int head = tid >> 6;
        int c4 = (tid & 63) << 2;
        int f = head * CH + c4;
        float wself = g_wself[n * 4 + head];
        float4 acc = *(const float4*)(g_T + (size_t)n * HC + f);
        acc.x *= wself; acc.y *= wself; acc.z *= wself; acc.w *= wself;
        for (int i = s; i < t; i++) {
            int src = g_esrc[i];
            float w = g_wedge[i * 4 + head];
            float4 v = *(const float4*)(g_T + (size_t)src * HC + f);
            acc.x += w * v.x; acc.y += w * v.y; acc.z += w * v.z; acc.w += w * v.w;
        }
        size_t pf = (size_t)l * HC + f;
        float4 bv = *(const float4*)(bias012 + pf);
        float4 gv = *(const float4*)(gamma + pf);
        float4 be = *(const float4*)(beta + pf);
        float4 mn = *(const float4*)(mean + pf);
        float4 vr = *(const float4*)(var + pf);
        float4 o;
        o.x = fmaxf((acc.x + bv.x - mn.x) * (gv.x * rsqrtf(vr.x + 1e-5f)) + be.x, 0.f);
        o.y = fmaxf((acc.y + bv.y - mn.y) * (gv.y * rsqrtf(vr.y + 1e-5f)) + be.y, 0.f);
        o.z = fmaxf((acc.z + bv.z - mn.z) * (gv.z * rsqrtf(vr.z + 1e-5f)) + be.z, 0.f);
        o.w = fmaxf((acc.w + bv.w - mn.w) * (gv.w * rsqrtf(vr.w + 1e-5f)) + be.w, 0.f);
        uint32_t h0, m0, h1, m1;
        split2(o.x, o.y, h0, m0);
        split2(o.z, o.w, h1, m1);
        size_t pc = (size_t)n * 512 + (f >> 1);
        *(uint2*)&g_Xhi[pc] = make_uint2(h0, h1);
        *(uint2*)&g_Xmid[pc] = make_uint2(m0, m1);
    } else {
        int c = tid;
        float4 ws = *(const float4*)&g_wself[n * 4];
        const float* hn = g_T + (size_t)n * HC;
        float acc = ws.x * hn[c] + ws.y * hn[CH + c] + ws.z * hn[2 * CH + c] + ws.w * hn[3 * CH + c];
        for (int i = s; i < t; i++) {
            int src = g_esrc[i];
            float4 w = *(const float4*)&g_wedge[i * 4];
            const float* hs = g_T + (size_t)src * HC;
            acc += w.x * hs[c] + w.y * hs[CH + c] + w.z * hs[2 * CH + c] + w.w * hs[3 * CH + c];
        }
        g_X[(size_t)n * CH + c] = 0.25f * acc + bias3[c];
    }
}

// ---------------- gate scores -------------------------------------------------
__global__ void k_gate(const float* __restrict__ gate_w, const float* __restrict__ gate_b) {
    int warp = threadIdx.x >> 5, lane = threadIdx.x & 31;
    int n = blockIdx.x * 8 + warp;
    if (n >= N_NODES) return;
    const float* hr = g_X + (size_t)n * CH;
    float s = 0.f;
    #pragma unroll
    for (int it = 0; it < 2; it++) {
        int c = (lane + it * 32) * 4;
        float4 v = *(const float4*)(hr + c);
        float4 w = *(const float4*)(gate_w + c);
        s += v.x * w.x + v.y * w.y + v.z * w.z + v.w * w.w;
    }
    #pragma unroll
    for (int o = 16; o > 0; o >>= 1) s += __shfl_down_sync(0xffffffffu, s, o);
    if (lane == 0) g_gate[n] = s + gate_b[0];
}

// ---------------- per-graph softmax pooling -----------------------------------
__device__ __forceinline__ int lb_batch(const int* __restrict__ batch, int target) {
    int lo = 0, hi = N_NODES;
    while (lo < hi) {
        int mid = (lo + hi) >> 1;
        if (batch[mid] < target) lo = mid + 1; else hi = mid;
    }
    return lo;
}
__global__ void k_pool(const int* __restrict__ batch) {
    int b = blockIdx.x;
    int c = threadIdx.x;
    int s = lb_batch(batch, b);
    int e = lb_batch(batch, b + 1);
    if (s == e) { g_graph[b * CH + c] = 0.f; return; }
    float mx = -1e30f;
    for (int n = s; n < e; n++) mx = fmaxf(mx, g_gate[n]);
    float sum = 0.f;
    for (int n = s; n < e; n++) sum += expf(g_gate[n] - mx);
    float inv = 1.f / (sum + 1e-16f);
    float acc = 0.f;
    for (int n = s; n < e; n++)
        acc += expf(g_gate[n] - mx) * inv * g_X[(size_t)n * CH + c];
    g_graph[b * CH + c] = acc;
}

// ---------------- final projection --------------------------------------------
__global__ __launch_bounds__(256) void k_proj(const float* __restrict__ proj_w,
                                              const float* __restrict__ proj_b,
                                              float* __restrict__ out) {
    __shared__ float sg[8][CH];
    int b0 = blockIdx.x * 8;
    int tid = threadIdx.x;
    #pragma unroll
    for (int g = 0; g < 8; g++) sg[g][tid] = g_graph[(b0 + g) * CH + tid];
    __syncthreads();
    float acc[8][4];
    #pragma unroll
    for (int g = 0; g < 8; g++)
        #pragma unroll
        for (int j = 0; j < 4; j++) acc[g][j] = 0.f;
    for (int cIt = 0; cIt < CH; cIt++) {
        float w0 = proj_w[cIt * 1024 + tid];
        float w1 = proj_w[cIt * 1024 + tid + 256];
        float w2 = proj_w[cIt * 1024 + tid + 512];
        float w3 = proj_w[cIt * 1024 + tid + 768];
        #pragma unroll
        for (int g = 0; g < 8; g++) {
            float sv = sg[g][cIt];
            acc[g][0] += sv * w0;
            acc[g][1] += sv * w1;
            acc[g][2] += sv * w2;
            acc[g][3] += sv * w3;
        }
    }
    #pragma unroll
    for (int g = 0; g < 8; g++)
        #pragma unroll
        for (int j = 0; j < 4; j++)
            out[(size_t)(b0 + g) * 1024 + tid + j * 256] = acc[g][j] + proj_b[tid + j * 256];
}

// ---------------- host orchestration ------------------------------------------
extern "C" void kernel_launch(void* const* d_in, const int* in_sizes, int n_in,
                              void* d_out, int out_size) {
    (void)in_sizes; (void)n_in; (void)out_size;
    const float* x        = (const float*)d_in[0];
    const int*   ei       = (const int*)d_in[1];
    const float* ea       = (const float*)d_in[2];
    const int*   batch    = (const int*)d_in[3];
    const float* w0       = (const float*)d_in[4];
    const float* w_rest   = (const float*)d_in[5];
    const float* w_edge   = (const float*)d_in[6];
    const float* att_src  = (const float*)d_in[7];
    const float* att_dst  = (const float*)d_in[8];
    const float* att_edge = (const float*)d_in[9];
    const float* bias012  = (const float*)d_in[10];
    const float* bias3    = (const float*)d_in[11];
    const float* bn_gamma = (const float*)d_in[12];
    const float* bn_beta  = (const float*)d_in[13];
    const float* bn_mean  = (const float*)d_in[14];
    const float* bn_var   = (const float*)d_in[15];
    const float* gate_w   = (const float*)d_in[16];
    const float* gate_b   = (const float*)d_in[17];
    const float* proj_w   = (const float*)d_in[18];
    const float* proj_b   = (const float*)d_in[19];
    float* out = (float*)d_out;

    cudaFuncSetAttribute(k_mmagemm, cudaFuncAttributeMaxDynamicSharedMemorySize, GEMM_SMEM);

    k_zero_cnt<<<(N_NODES + 255) / 256, 256>>>();
    k_count<<<(N_EDGES + 255) / 256, 256>>>(ei);
    k_scan<<<1, 1024>>>();
    k_scatter<<<(N_EDGES + 255) / 256, 256>>>(ei);
    k_transpose<<<dim3(32, 32, 3), dim3(32, 8)>>>(w_rest);
    k_gemm0<<<N_NODES, 256>>>(x, w0);
    k_meanve<<<1, 256>>>(ea, w_edge, att_edge);
    k_ae_all<<<(N_EDGES + 127) / 128, 128>>>(ea);

    for (int l = 0; l < 4; l++) {
        if (l > 0) {
            k_mmagemm<<<dim3(8, (N_NODES + 127) / 128), 256, GEMM_SMEM>>>(l);
        }
        k_alpha<<<N_NODES, 128>>>(att_src, att_dst, l);
        k_attw<<<(N_NODES + 255) / 256, 256>>>(l);
        k_agg<<<N_NODES, 256>>>(l, l < 3 ? 1 : 0, bias012, bias3,
                                bn_gamma, bn_beta, bn_mean, bn_var);
    }

    k_gate<<<(N_NODES + 7) / 8, 256>>>(gate_w, gate_b);
    k_pool<<<N_GRAPH, 256>>>(batch);
    k_proj<<<N_GRAPH / 8, 256>>>(proj_w, proj_b, out);
}

// round 7
// speedup vs baseline: 3.6505x; 1.4615x over previous
#include <cuda_runtime.h>
#include <cuda_fp16.h>
#include <cstdint>
#include <math.h>

#define N_NODES 20000
#define N_PAD   20096            // 157 * 128
#define N_EDGES 60000
#define N_GRAPH 512
#define F_INP   7
#define HC      1024
#define NH      4
#define CH      256

// ---------------- scratch (static device globals; no allocation) -------------
__device__ float    g_X[(size_t)N_NODES * CH];     // final-layer output (l=3)
__device__ float    g_T[(size_t)N_NODES * HC];     // transformed h = X @ W
__device__ uint32_t g_Xh[(size_t)N_PAD * 512];     // activations fp16 packed pairs
__device__ uint32_t g_WTh[3 * 1024 * 512];         // weight^T fp16 packed pairs
__device__ float    g_asrc[N_NODES * NH];
__device__ float    g_adst[N_NODES * NH];
__device__ float    g_ae_all[4 * N_EDGES * NH];
__device__ float    g_ve[48];
__device__ float    g_ae_self[16];
__device__ float    g_eamean[3];
__device__ int      g_cnt[N_NODES];
__device__ int      g_rowptr[N_NODES + 1];
__device__ int      g_cursor[N_NODES];
__device__ int      g_eid[N_EDGES];
__device__ int      g_esrc[N_EDGES];
__device__ float    g_wedge[N_EDGES * NH];
__device__ float    g_wself[N_NODES * NH];
__device__ float    g_gate[N_NODES];
__device__ float    g_graph[N_GRAPH * CH];

__device__ __forceinline__ float lrelu(float a) { return a > 0.f ? a : 0.2f * a; }

__device__ __forceinline__ uint32_t packh2(float x, float y) {
    __half2 h = __floats2half2_rn(x, y);
    return *(uint32_t*)&h;
}

__device__ __forceinline__ uint32_t smem_u32(const void* p) {
    uint32_t a;
    asm("{ .reg .u64 t; cvta.to.shared.u64 t, %1; cvt.u32.u64 %0, t; }" : "=r"(a) : "l"(p));
    return a;
}
__device__ __forceinline__ void cp16(uint32_t dst, const void* src) {
    asm volatile("cp.async.cg.shared.global [%0], [%1], 16;" :: "r"(dst), "l"(src));
}
__device__ __forceinline__ void ldsm4(uint32_t* d, uint32_t addr) {
    asm volatile("ldmatrix.sync.aligned.m8n8.x4.shared.b16 {%0,%1,%2,%3}, [%4];"
                 : "=r"(d[0]), "=r"(d[1]), "=r"(d[2]), "=r"(d[3]) : "r"(addr));
}
__device__ __forceinline__ void mma_f16(float* c, uint32_t a0, uint32_t a1,
                                        uint32_t a2, uint32_t a3,
                                        uint32_t b0, uint32_t b1) {
    asm volatile(
        "mma.sync.aligned.m16n8k16.row.col.f32.f16.f16.f32 "
        "{%0,%1,%2,%3}, {%4,%5,%6,%7}, {%8,%9}, {%0,%1,%2,%3};"
        : "+f"(c[0]), "+f"(c[1]), "+f"(c[2]), "+f"(c[3])
        : "r"(a0), "r"(a1), "r"(a2), "r"(a3), "r"(b0), "r"(b1));
}

// ---------------- edge_attr mean + ve + self-loop attention (fused) ----------
__global__ void k_meanve(const float* __restrict__ ea,
                         const float* __restrict__ w_edge,
                         const float* __restrict__ att_edge) {
    __shared__ float red[3][256];
    int tid = threadIdx.x;
    float a0 = 0.f, a1 = 0.f, a2 = 0.f;
    for (int e = tid; e < N_EDGES; e += 256) {
        a0 += ea[e * 3 + 0]; a1 += ea[e * 3 + 1]; a2 += ea[e * 3 + 2];
    }
    red[0][tid] = a0; red[1][tid] = a1; red[2][tid] = a2;
    __syncthreads();
    for (int s = 128; s > 0; s >>= 1) {
        if (tid < s) {
            red[0][tid] += red[0][tid + s];
            red[1][tid] += red[1][tid + s];
            red[2][tid] += red[2][tid + s];
        }
        __syncthreads();
    }
    if (tid < 3) g_eamean[tid] = red[tid][0] * (1.f / (float)N_EDGES);
    __syncthreads();

    int warp = tid >> 5, lane = tid & 31;
    for (int idx = warp; idx < 48; idx += 8) {
        int l = idx / 12, r = idx % 12, d = r / 4, h = r % 4;
        const float* w = w_edge + (size_t)l * 3 * HC + (size_t)d * HC + h * CH;
        const float* a = att_edge + (size_t)l * HC + h * CH;
        float s = 0.f;
        for (int c = lane; c < CH; c += 32) s += w[c] * a[c];
        #pragma unroll
        for (int o = 16; o > 0; o >>= 1) s += __shfl_down_sync(0xffffffffu, s, o);
        if (lane == 0) g_ve[idx] = s;
    }
    __syncthreads();
    if (tid < 16) {
        int l = tid >> 2, h = tid & 3;
        float s = 0.f;
        for (int d = 0; d < 3; d++) s += g_eamean[d] * g_ve[l * 12 + d * 4 + h];
        g_ae_self[tid] = s;
    }
}

__global__ void k_ae_all(const float* __restrict__ ea) {
    int e = blockIdx.x * blockDim.x + threadIdx.x;
    if (e >= N_EDGES) return;
    float a0 = ea[e * 3 + 0], a1 = ea[e * 3 + 1], a2 = ea[e * 3 + 2];
    #pragma unroll
    for (int l = 0; l < 4; l++) {
        float4 v;
        v.x = a0 * g_ve[l * 12 + 0] + a1 * g_ve[l * 12 + 4] + a2 * g_ve[l * 12 + 8];
        v.y = a0 * g_ve[l * 12 + 1] + a1 * g_ve[l * 12 + 5] + a2 * g_ve[l * 12 + 9];
        v.z = a0 * g_ve[l * 12 + 2] + a1 * g_ve[l * 12 + 6] + a2 * g_ve[l * 12 + 10];
        v.w = a0 * g_ve[l * 12 + 3] + a1 * g_ve[l * 12 + 7] + a2 * g_ve[l * 12 + 11];
        *(float4*)&g_ae_all[(size_t)l * N_EDGES * 4 + e * 4] = v;
    }
}

// ---------------- CSR build ---------------------------------------------------
__global__ void k_zero_cnt() {
    int n = blockIdx.x * blockDim.x + threadIdx.x;
    if (n < N_NODES) g_cnt[n] = 0;
}
__global__ void k_count(const int* __restrict__ ei) {
    int e = blockIdx.x * blockDim.x + threadIdx.x;
    if (e >= N_EDGES) return;
    atomicAdd(&g_cnt[ei[N_EDGES + e]], 1);
}
__global__ void k_scan() {
    __shared__ int ssum[1024];
    const int SEG = 20;
    int tid = threadIdx.x;
    int base = tid * SEG;
    int cnts[SEG];
    int tot = 0;
    #pragma unroll
    for (int j = 0; j < SEG; j++) {
        int idx = base + j;
        cnts[j] = (idx < N_NODES) ? g_cnt[idx] : 0;
        tot += cnts[j];
    }
    ssum[tid] = tot;
    __syncthreads();
    for (int off = 1; off < 1024; off <<= 1) {
        int v = (tid >= off) ? ssum[tid - off] : 0;
        __syncthreads();
        ssum[tid] += v;
        __syncthreads();
    }
    int run = ssum[tid] - tot;
    #pragma unroll
    for (int j = 0; j < SEG; j++) {
        int idx = base + j;
        if (idx < N_NODES) {
            g_rowptr[idx] = run;
            g_cursor[idx] = run;
            run += cnts[j];
        } else if (idx == N_NODES) {
            g_rowptr[N_NODES] = run;
        }
    }
}
__global__ void k_scatter(const int* __restrict__ ei) {
    int e = blockIdx.x * blockDim.x + threadIdx.x;
    if (e >= N_EDGES) return;
    int src = ei[e];
    int dst = ei[N_EDGES + e];
    int pos = atomicAdd(&g_cursor[dst], 1);
    g_eid[pos] = e;
    g_esrc[pos] = src;
}

// ------- weight transpose + fp16 pack: WT[l][n][k/2 packed] ------------------
__global__ void k_transpose(const float* __restrict__ W) {
    __shared__ float t[32][33];
    int l = blockIdx.z;
    int k0 = blockIdx.y * 32, n0 = blockIdx.x * 32;
    int tx = threadIdx.x, ty = threadIdx.y;
    const float* Wl = W + (size_t)l * 1024 * 1024;
    #pragma unroll
    for (int i = 0; i < 4; i++)
        t[ty + i * 8][tx] = Wl[(size_t)(k0 + ty + i * 8) * 1024 + n0 + tx];
    __syncthreads();
    if (tx < 16) {
        uint32_t* Wh = g_WTh + (size_t)l * 1024 * 512;
        #pragma unroll
        for (int i = 0; i < 4; i++) {
            int nl = ty + i * 8;
            int n = n0 + nl;
            Wh[(size_t)n * 512 + (k0 >> 1) + tx] = packh2(t[2 * tx][nl], t[2 * tx + 1][nl]);
        }
    }
}

// ---------------- layer-0 GEMM: T = x(N,7) @ w0(7,1024) ----------------------
__global__ void k_gemm0(const float* __restrict__ x, const float* __restrict__ w0) {
    __shared__ float xr[F_INP];
    int n = blockIdx.x, tid = threadIdx.x;
    if (tid < F_INP) xr[tid] = x[n * F_INP + tid];
    __syncthreads();
    #pragma unroll
    for (int j = 0; j < 4; j++) {
        int f = tid + j * 256;
        float acc = 0.f;
        #pragma unroll
        for (int d = 0; d < F_INP; d++) acc += xr[d] * w0[d * HC + f];
        g_T[(size_t)n * HC + f] = acc;
    }
}

// =============== mma.sync fp16 GEMM (single term, cp.async, ldmatrix) =========
// Block 128x128, warps 2x4, K chunk 32 (16 packed uint32), double-buffered.
#define NCHUNK 32
#define SROWB 80                       // byte stride per m/n row in smem
#define OFF_A  0
#define OFF_B  10240
#define STG2   20480
#define GEMM_SMEM (2 * STG2)           // 40960 B

__global__ void __launch_bounds__(256, 2) k_mmagemm(int layer) {
    extern __shared__ char smem[];
    uint32_t sb = smem_u32(smem);
    int tid = threadIdx.x;
    int wid = tid >> 5;
    int lane = tid & 31;
    int g = lane >> 2, tig = lane & 3;
    int wm = wid >> 2;
    int wn = wid & 3;
    int m0 = blockIdx.y * 128;
    int n0 = blockIdx.x * 128;

    const uint32_t* Wh = g_WTh + (size_t)(layer - 1) * 1024 * 512;

    // cp.async loader geometry: one 64B chunk-row per thread
    int lrow = tid & 127;
    int isB = tid >> 7;
    const uint32_t* gsrc = isB ? (Wh + (size_t)(n0 + lrow) * 512)
                               : (g_Xh + (size_t)(m0 + lrow) * 512);
    uint32_t dstrow = sb + (isB ? OFF_B : OFF_A) + lrow * SROWB;

    // ldmatrix per-thread base offsets
    int q = lane >> 3, r = lane & 7;
    uint32_t aoff[4], boff[2];
    {
        int arow = (q & 1) * 8 + r;
        int acol = (q >> 1) * 16;
        #pragma unroll
        for (int mt = 0; mt < 4; mt++)
            aoff[mt] = (uint32_t)((wm * 64 + mt * 16 + arow) * SROWB + acol);
        int brow = (q >> 1) * 8 + r;
        int bcol = (q & 1) * 16;
        #pragma unroll
        for (int ntp = 0; ntp < 2; ntp++)
            boff[ntp] = (uint32_t)((wn * 32 + ntp * 16 + brow) * SROWB + bcol);
    }

    float acc[4][4][4];
    #pragma unroll
    for (int i = 0; i < 4; i++)
        #pragma unroll
        for (int j = 0; j < 4; j++)
            #pragma unroll
            for (int qq = 0; qq < 4; qq++) acc[i][j][qq] = 0.f;

    // prologue: stage 0
    {
        cp16(dstrow + 0, gsrc);
        cp16(dstrow + 16, gsrc + 4);
        cp16(dstrow + 32, gsrc + 8);
        cp16(dstrow + 48, gsrc + 12);
        asm volatile("cp.async.commit_group;");
    }

    for (int c = 0; c < NCHUNK; c++) {
        if (c + 1 < NCHUNK) {
            uint32_t d = dstrow + ((c + 1) & 1) * STG2;
            const uint32_t* p = gsrc + (size_t)(c + 1) * 16;
            cp16(d + 0, p);
            cp16(d + 16, p + 4);
            cp16(d + 32, p + 8);
            cp16(d + 48, p + 12);
            asm volatile("cp.async.commit_group;");
            asm volatile("cp.async.wait_group 1;");
        } else {
            asm volatile("cp.async.wait_group 0;");
        }
        __syncthreads();

        uint32_t stq = sb + (c & 1) * STG2;
        #pragma unroll
        for (int ks = 0; ks < 2; ks++) {
            uint32_t kso = (uint32_t)(ks * 32);
            uint32_t bh[2][4];
            #pragma unroll
            for (int ntp = 0; ntp < 2; ntp++)
                ldsm4(bh[ntp], stq + OFF_B + boff[ntp] + kso);
            #pragma unroll
            for (int mt = 0; mt < 4; mt++) {
                uint32_t ah[4];
                ldsm4(ah, stq + OFF_A + aoff[mt] + kso);
                #pragma unroll
                for (int nt = 0; nt < 4; nt++) {
                    uint32_t b0 = bh[nt >> 1][(nt & 1) * 2 + 0];
                    uint32_t b1 = bh[nt >> 1][(nt & 1) * 2 + 1];
                    mma_f16(acc[mt][nt], ah[0], ah[1], ah[2], ah[3], b0, b1);
                }
            }
        }
        __syncthreads();
    }

    #pragma unroll
    for (int mt = 0; mt < 4; mt++) {
        int row0 = m0 + wm * 64 + mt * 16 + g;
        #pragma unroll
        for (int nt = 0; nt < 4; nt++) {
            int col = n0 + wn * 32 + nt * 8 + tig * 2;
            if (row0 < N_NODES)
                *(float2*)(g_T + (size_t)row0 * HC + col) = make_float2(acc[mt][nt][0], acc[mt][nt][1]);
            if (row0 + 8 < N_NODES)
                *(float2*)(g_T + (size_t)(row0 + 8) * HC + col) = make_float2(acc[mt][nt][2], acc[mt][nt][3]);
        }
    }
}

// ---------------- per-node alpha_src / alpha_dst (float4) ---------------------
__global__ void k_alpha(const float* __restrict__ att_src, const float* __restrict__ att_dst, int l) {
    int n = blockIdx.x;
    int warp = threadIdx.x >> 5, lane = threadIdx.x & 31;
    const float* hr = g_T + (size_t)n * HC + warp * CH;
    const float* as = att_src + (size_t)l * HC + warp * CH;
    const float* ad = att_dst + (size_t)l * HC + warp * CH;
    float s1 = 0.f, s2 = 0.f;
    #pragma unroll
    for (int it = 0; it < 2; it++) {
        int c = (lane + it * 32) * 4;
        float4 v = *(const float4*)(hr + c);
        float4 a = *(const float4*)(as + c);
        float4 d = *(const float4*)(ad + c);
        s1 += v.x * a.x + v.y * a.y + v.z * a.z + v.w * a.w;
        s2 += v.x * d.x + v.y * d.y + v.z * d.z + v.w * d.w;
    }
    #pragma unroll
    for (int o = 16; o > 0; o >>= 1) {
        s1 += __shfl_down_sync(0xffffffffu, s1, o);
        s2 += __shfl_down_sync(0xffffffffu, s2, o);
    }
    if (lane == 0) {
        g_asrc[n * 4 + warp] = s1;
        g_adst[n * 4 + warp] = s2;
    }
}

// ---------------- precompute softmax attention weights ------------------------
__global__ void k_attw(int l) {
    int n = blockIdx.x * blockDim.x + threadIdx.x;
    if (n >= N_NODES) return;
    const float* ae = g_ae_all + (size_t)l * N_EDGES * 4;
    int s = g_rowptr[n], t = g_rowptr[n + 1];

    float4 ad4 = *(const float4*)&g_adst[n * 4];
    float4 as4 = *(const float4*)&g_asrc[n * 4];
    float ad[4] = {ad4.x, ad4.y, ad4.z, ad4.w};
    float aself[4], m[4];
    #pragma unroll
    for (int h = 0; h < 4; h++) {
        aself[h] = lrelu(((const float*)&as4)[h] + ad[h] + g_ae_self[l * 4 + h]);
        m[h] = aself[h];
    }
    for (int i = s; i < t; i++) {
        int e = g_eid[i], src = g_esrc[i];
        float4 av = *(const float4*)&g_asrc[src * 4];
        float4 ev = *(const float4*)&ae[e * 4];
        #pragma unroll
        for (int h = 0; h < 4; h++) {
            float a = lrelu(((const float*)&av)[h] + ad[h] + ((const float*)&ev)[h]);
            m[h] = fmaxf(m[h], a);
        }
    }
    float sum[4];
    #pragma unroll
    for (int h = 0; h < 4; h++) sum[h] = expf(aself[h] - m[h]);
    for (int i = s; i < t; i++) {
        int e = g_eid[i], src = g_esrc[i];
        float4 av = *(const float4*)&g_asrc[src * 4];
        float4 ev = *(const float4*)&ae[e * 4];
        #pragma unroll
        for (int h = 0; h < 4; h++) {
            float a = lrelu(((const float*)&av)[h] + ad[h] + ((const float*)&ev)[h]);
            sum[h] += expf(a - m[h]);
        }
    }
    float inv[4];
    #pragma unroll
    for (int h = 0; h < 4; h++) inv[h] = 1.f / (sum[h] + 1e-16f);

    float4 ws;
    ((float*)&ws)[0] = expf(aself[0] - m[0]) * inv[0];
    ((float*)&ws)[1] = expf(aself[1] - m[1]) * inv[1];
    ((float*)&ws)[2] = expf(aself[2] - m[2]) * inv[2];
    ((float*)&ws)[3] = expf(aself[3] - m[3]) * inv[3];
    *(float4*)&g_wself[n * 4] = ws;

    for (int i = s; i < t; i++) {
        int e = g_eid[i], src = g_esrc[i];
        float4 av = *(const float4*)&g_asrc[src * 4];
        float4 ev = *(const float4*)&ae[e * 4];
        float4 w;
        #pragma unroll
        for (int h = 0; h < 4; h++) {
            float a = lrelu(((const float*)&av)[h] + ad[h] + ((const float*)&ev)[h]);
            ((float*)&w)[h] = expf(a - m[h]) * inv[h];
        }
        *(float4*)&g_wedge[i * 4] = w;
    }
}

// ---------------- weighted gather + bias (+BN+ReLU) ---------------------------
// concat layers: writes fp16 packed activations (GEMM input); last layer: fp32.
__global__ __launch_bounds__(256) void k_agg(
    int l, int concat,
    const float* __restrict__ bias012, const float* __restrict__ bias3,
    const float* __restrict__ gamma, const float* __restrict__ beta,
    const float* __restrict__ mean, const float* __restrict__ var) {
    int n = blockIdx.x;
    int tid = threadIdx.x;
    int s = g_rowptr[n], t = g_rowptr[n + 1];

    if (concat) {
        int head = tid >> 6;
        int c4 = (tid & 63) << 2;
        int f = head * CH + c4;
        float wself = g_wself[n * 4 + head];
        float4 acc = *(const float4*)(g_T + (size_t)n * HC + f);
        acc.x *= wself; acc.y *= wself; acc.z *= wself; acc.w *= wself;
        for (int i = s; i < t; i++) {
            int src = g_esrc[i];
            float w = g_wedge[i * 4 + head];
            float4 v = *(const float4*)(g_T + (size_t)src * HC + f);
            acc.x += w * v.x; acc.y += w * v.y; acc.z += w * v.z; acc.w += w * v.w;
        }
        size_t pf = (size_t)l * HC + f;
        float4 bv = *(const float4*)(bias012 + pf);
        float4 gv = *(const float4*)(gamma + pf);
        float4 be = *(const float4*)(beta + pf);
        float4 mn = *(const float4*)(mean + pf);
        float4 vr = *(const float4*)(var + pf);
        float4 o;
        o.x = fmaxf((acc.x + bv.x - mn.x) * (gv.x * rsqrtf(vr.x + 1e-5f)) + be.x, 0.f);
        o.y = fmaxf((acc.y + bv.y - mn.y) * (gv.y * rsqrtf(vr.y + 1e-5f)) + be.y, 0.f);
        o.z = fmaxf((acc.z + bv.z - mn.z) * (gv.z * rsqrtf(vr.z + 1e-5f)) + be.z, 0.f);
        o.w = fmaxf((acc.w + bv.w - mn.w) * (gv.w * rsqrtf(vr.w + 1e-5f)) + be.w, 0.f);
        size_t pc = (size_t)n * 512 + (f >> 1);
        *(uint2*)&g_Xh[pc] = make_uint2(packh2(o.x, o.y), packh2(o.z, o.w));
    } else {
        int c = tid;
        float4 ws = *(const float4*)&g_wself[n * 4];
        const float* hn = g_T + (size_t)n * HC;
        float acc = ws.x * hn[c] + ws.y * hn[CH + c] + ws.z * hn[2 * CH + c] + ws.w * hn[3 * CH + c];
        for (int i = s; i < t; i++) {
            int src = g_esrc[i];
            float4 w = *(const float4*)&g_wedge[i * 4];
            const float* hs = g_T + (size_t)src * HC;
            acc += w.x * hs[c] + w.y * hs[CH + c] + w.z * hs[2 * CH + c] + w.w * hs[3 * CH + c];
        }
        g_X[(size_t)n * CH + c] = 0.25f * acc + bias3[c];
    }
}

// ---------------- gate scores -------------------------------------------------
__global__ void k_gate(const float* __restrict__ gate_w, const float* __restrict__ gate_b) {
    int warp = threadIdx.x >> 5, lane = threadIdx.x & 31;
    int n = blockIdx.x * 8 + warp;
    if (n >= N_NODES) return;
    const float* hr = g_X + (size_t)n * CH;
    float s = 0.f;
    #pragma unroll
    for (int it = 0; it < 2; it++) {
        int c = (lane + it * 32) * 4;
        float4 v = *(const float4*)(hr + c);
        float4 w = *(const float4*)(gate_w + c);
        s += v.x * w.x + v.y * w.y + v.z * w.z + v.w * w.w;
    }
    #pragma unroll
    for (int o = 16; o > 0; o >>= 1) s += __shfl_down_sync(0xffffffffu, s, o);
    if (lane == 0) g_gate[n] = s + gate_b[0];
}

// ---------------- per-graph softmax pooling -----------------------------------
__device__ __forceinline__ int lb_batch(const int* __restrict__ batch, int target) {
    int lo = 0, hi = N_NODES;
    while (lo < hi) {
        int mid = (lo + hi) >> 1;
        if (batch[mid] < target) lo = mid + 1; else hi = mid;
    }
    return lo;
}
__global__ void k_pool(const int* __restrict__ batch) {
    int b = blockIdx.x;
    int c = threadIdx.x;
    int s = lb_batch(batch, b);
    int e = lb_batch(batch, b + 1);
    if (s == e) { g_graph[b * CH + c] = 0.f; return; }
    float mx = -1e30f;
    for (int n = s; n < e; n++) mx = fmaxf(mx, g_gate[n]);
    float sum = 0.f;
    for (int n = s; n < e; n++) sum += expf(g_gate[n] - mx);
    float inv = 1.f / (sum + 1e-16f);
    float acc = 0.f;
    for (int n = s; n < e; n++)
        acc += expf(g_gate[n] - mx) * inv * g_X[(size_t)n * CH + c];
    g_graph[b * CH + c] = acc;
}

// ---------------- final projection --------------------------------------------
__global__ __launch_bounds__(256) void k_proj(const float* __restrict__ proj_w,
                                              const float* __restrict__ proj_b,
                                              float* __restrict__ out) {
    __shared__ float sg[8][CH];
    int b0 = blockIdx.x * 8;
    int tid = threadIdx.x;
    #pragma unroll
    for (int g = 0; g < 8; g++) sg[g][tid] = g_graph[(b0 + g) * CH + tid];
    __syncthreads();
    float acc[8][4];
    #pragma unroll
    for (int g = 0; g < 8; g++)
        #pragma unroll
        for (int j = 0; j < 4; j++) acc[g][j] = 0.f;
    for (int cIt = 0; cIt < CH; cIt++) {
        float w0 = proj_w[cIt * 1024 + tid];
        float w1 = proj_w[cIt * 1024 + tid + 256];
        float w2 = proj_w[cIt * 1024 + tid + 512];
        float w3 = proj_w[cIt * 1024 + tid + 768];
        #pragma unroll
        for (int g = 0; g < 8; g++) {
            float sv = sg[g][cIt];
            acc[g][0] += sv * w0;
            acc[g][1] += sv * w1;
            acc[g][2] += sv * w2;
            acc[g][3] += sv * w3;
        }
    }
    #pragma unroll
    for (int g = 0; g < 8; g++)
        #pragma unroll
        for (int j = 0; j < 4; j++)
            out[(size_t)(b0 + g) * 1024 + tid + j * 256] = acc[g][j] + proj_b[tid + j * 256];
}

// ---------------- host orchestration ------------------------------------------
extern "C" void kernel_launch(void* const* d_in, const int* in_sizes, int n_in,
                              void* d_out, int out_size) {
    (void)in_sizes; (void)n_in; (void)out_size;
    const float* x        = (const float*)d_in[0];
    const int*   ei       = (const int*)d_in[1];
    const float* ea       = (const float*)d_in[2];
    const int*   batch    = (const int*)d_in[3];
    const float* w0       = (const float*)d_in[4];
    const float* w_rest   = (const float*)d_in[5];
    const float* w_edge   = (const float*)d_in[6];
    const float* att_src  = (const float*)d_in[7];
    const float* att_dst  = (const float*)d_in[8];
    const float* att_edge = (const float*)d_in[9];
    const float* bias012  = (const float*)d_in[10];
    const float* bias3    = (const float*)d_in[11];
    const float* bn_gamma = (const float*)d_in[12];
    const float* bn_beta  = (const float*)d_in[13];
    const float* bn_mean  = (const float*)d_in[14];
    const float* bn_var   = (const float*)d_in[15];
    const float* gate_w   = (const float*)d_in[16];
    const float* gate_b   = (const float*)d_in[17];
    const float* proj_w   = (const float*)d_in[18];
    const float* proj_b   = (const float*)d_in[19];
    float* out = (float*)d_out;

    cudaFuncSetAttribute(k_mmagemm, cudaFuncAttributeMaxDynamicSharedMemorySize, GEMM_SMEM);

    k_zero_cnt<<<(N_NODES + 255) / 256, 256>>>();
    k_count<<<(N_EDGES + 255) / 256, 256>>>(ei);
    k_scan<<<1, 1024>>>();
    k_scatter<<<(N_EDGES + 255) / 256, 256>>>(ei);
    k_transpose<<<dim3(32, 32, 3), dim3(32, 8)>>>(w_rest);
    k_gemm0<<<N_NODES, 256>>>(x, w0);
    k_meanve<<<1, 256>>>(ea, w_edge, att_edge);
    k_ae_all<<<(N_EDGES + 127) / 128, 128>>>(ea);

    for (int l = 0; l < 4; l++) {
        if (l > 0) {
            k_mmagemm<<<dim3(8, (N_NODES + 127) / 128), 256, GEMM_SMEM>>>(l);
        }
        k_alpha<<<N_NODES, 128>>>(att_src, att_dst, l);
        k_attw<<<(N_NODES + 255) / 256, 256>>>(l);
        k_agg<<<N_NODES, 256>>>(l, l < 3 ? 1 : 0, bias012, bias3,
                                bn_gamma, bn_beta, bn_mean, bn_var);
    }

    k_gate<<<(N_NODES + 7) / 8, 256>>>(gate_w, gate_b);
    k_pool<<<N_GRAPH, 256>>>(batch);
    k_proj<<<N_GRAPH / 8, 256>>>(proj_w, proj_b, out);
}

// round 8
// speedup vs baseline: 3.7165x; 1.0181x over previous
#include <cuda_runtime.h>
#include <cuda_fp16.h>
#include <cstdint>
#include <math.h>

#define N_NODES 20000
#define N_PAD   20096            // 157 * 128
#define N_EDGES 60000
#define N_GRAPH 512
#define F_INP   7
#define HC      1024
#define NH      4
#define CH      256

// ---------------- scratch (static device globals; no allocation) -------------
__device__ float    g_X[(size_t)N_NODES * CH];     // final-layer output (l=3)
__device__ uint32_t g_Th[(size_t)N_PAD * 512];     // h = X@W, fp16 packed pairs
__device__ uint32_t g_Xh[(size_t)N_PAD * 512];     // next-layer GEMM input (fp16)
__device__ uint32_t g_WTh[3 * 1024 * 512];         // weight^T fp16 packed pairs
__device__ float    g_asrc[N_NODES * NH];
__device__ float    g_adst[N_NODES * NH];
__device__ float    g_ae_all[4 * N_EDGES * NH];
__device__ float    g_ve[48];
__device__ float    g_ae_self[16];
__device__ float    g_eamean[3];
__device__ int      g_cnt[N_NODES];
__device__ int      g_rowptr[N_NODES + 1];
__device__ int      g_cursor[N_NODES];
__device__ int      g_eid[N_EDGES];
__device__ int      g_esrc[N_EDGES];
__device__ float    g_wedge[N_EDGES * NH];
__device__ float    g_wself[N_NODES * NH];
__device__ float    g_gate[N_NODES];
__device__ float    g_graph[N_GRAPH * CH];

__device__ __forceinline__ float lrelu(float a) { return a > 0.f ? a : 0.2f * a; }

__device__ __forceinline__ uint32_t packh2(float x, float y) {
    __half2 h = __floats2half2_rn(x, y);
    return *(uint32_t*)&h;
}
__device__ __forceinline__ float2 unpackh2(uint32_t u) {
    return __half22float2(*(__half2*)&u);
}

__device__ __forceinline__ uint32_t smem_u32(const void* p) {
    uint32_t a;
    asm("{ .reg .u64 t; cvta.to.shared.u64 t, %1; cvt.u32.u64 %0, t; }" : "=r"(a) : "l"(p));
    return a;
}
__device__ __forceinline__ void cp16(uint32_t dst, const void* src) {
    asm volatile("cp.async.cg.shared.global [%0], [%1], 16;" :: "r"(dst), "l"(src));
}
__device__ __forceinline__ void ldsm4(uint32_t* d, uint32_t addr) {
    asm volatile("ldmatrix.sync.aligned.m8n8.x4.shared.b16 {%0,%1,%2,%3}, [%4];"
                 : "=r"(d[0]), "=r"(d[1]), "=r"(d[2]), "=r"(d[3]) : "r"(addr));
}
__device__ __forceinline__ void mma_f16(float* c, uint32_t a0, uint32_t a1,
                                        uint32_t a2, uint32_t a3,
                                        uint32_t b0, uint32_t b1) {
    asm volatile(
        "mma.sync.aligned.m16n8k16.row.col.f32.f16.f16.f32 "
        "{%0,%1,%2,%3}, {%4,%5,%6,%7}, {%8,%9}, {%0,%1,%2,%3};"
        : "+f"(c[0]), "+f"(c[1]), "+f"(c[2]), "+f"(c[3])
        : "r"(a0), "r"(a1), "r"(a2), "r"(a3), "r"(b0), "r"(b1));
}

// ---------------- edge_attr mean + ve + self-loop attention (fused) ----------
__global__ void k_meanve(const float* __restrict__ ea,
                         const float* __restrict__ w_edge,
                         const float* __restrict__ att_edge) {
    __shared__ float red[3][256];
    int tid = threadIdx.x;
    float a0 = 0.f, a1 = 0.f, a2 = 0.f;
    for (int e = tid; e < N_EDGES; e += 256) {
        a0 += ea[e * 3 + 0]; a1 += ea[e * 3 + 1]; a2 += ea[e * 3 + 2];
    }
    red[0][tid] = a0; red[1][tid] = a1; red[2][tid] = a2;
    __syncthreads();
    for (int s = 128; s > 0; s >>= 1) {
        if (tid < s) {
            red[0][tid] += red[0][tid + s];
            red[1][tid] += red[1][tid + s];
            red[2][tid] += red[2][tid + s];
        }
        __syncthreads();
    }
    if (tid < 3) g_eamean[tid] = red[tid][0] * (1.f / (float)N_EDGES);
    __syncthreads();

    int warp = tid >> 5, lane = tid & 31;
    for (int idx = warp; idx < 48; idx += 8) {
        int l = idx / 12, r = idx % 12, d = r / 4, h = r % 4;
        const float* w = w_edge + (size_t)l * 3 * HC + (size_t)d * HC + h * CH;
        const float* a = att_edge + (size_t)l * HC + h * CH;
        float s = 0.f;
        for (int c = lane; c < CH; c += 32) s += w[c] * a[c];
        #pragma unroll
        for (int o = 16; o > 0; o >>= 1) s += __shfl_down_sync(0xffffffffu, s, o);
        if (lane == 0) g_ve[idx] = s;
    }
    __syncthreads();
    if (tid < 16) {
        int l = tid >> 2, h = tid & 3;
        float s = 0.f;
        for (int d = 0; d < 3; d++) s += g_eamean[d] * g_ve[l * 12 + d * 4 + h];
        g_ae_self[tid] = s;
    }
}

__global__ void k_ae_all(const float* __restrict__ ea) {
    int e = blockIdx.x * blockDim.x + threadIdx.x;
    if (e >= N_EDGES) return;
    float a0 = ea[e * 3 + 0], a1 = ea[e * 3 + 1], a2 = ea[e * 3 + 2];
    #pragma unroll
    for (int l = 0; l < 4; l++) {
        float4 v;
        v.x = a0 * g_ve[l * 12 + 0] + a1 * g_ve[l * 12 + 4] + a2 * g_ve[l * 12 + 8];
        v.y = a0 * g_ve[l * 12 + 1] + a1 * g_ve[l * 12 + 5] + a2 * g_ve[l * 12 + 9];
        v.z = a0 * g_ve[l * 12 + 2] + a1 * g_ve[l * 12 + 6] + a2 * g_ve[l * 12 + 10];
        v.w = a0 * g_ve[l * 12 + 3] + a1 * g_ve[l * 12 + 7] + a2 * g_ve[l * 12 + 11];
        *(float4*)&g_ae_all[(size_t)l * N_EDGES * 4 + e * 4] = v;
    }
}

// ---------------- CSR build ---------------------------------------------------
__global__ void k_zero_cnt() {
    int n = blockIdx.x * blockDim.x + threadIdx.x;
    if (n < N_NODES) g_cnt[n] = 0;
}
__global__ void k_count(const int* __restrict__ ei) {
    int e = blockIdx.x * blockDim.x + threadIdx.x;
    if (e >= N_EDGES) return;
    atomicAdd(&g_cnt[ei[N_EDGES + e]], 1);
}
__global__ void k_scan() {
    __shared__ int ssum[1024];
    const int SEG = 20;
    int tid = threadIdx.x;
    int base = tid * SEG;
    int cnts[SEG];
    int tot = 0;
    #pragma unroll
    for (int j = 0; j < SEG; j++) {
        int idx = base + j;
        cnts[j] = (idx < N_NODES) ? g_cnt[idx] : 0;
        tot += cnts[j];
    }
    ssum[tid] = tot;
    __syncthreads();
    for (int off = 1; off < 1024; off <<= 1) {
        int v = (tid >= off) ? ssum[tid - off] : 0;
        __syncthreads();
        ssum[tid] += v;
        __syncthreads();
    }
    int run = ssum[tid] - tot;
    #pragma unroll
    for (int j = 0; j < SEG; j++) {
        int idx = base + j;
        if (idx < N_NODES) {
            g_rowptr[idx] = run;
            g_cursor[idx] = run;
            run += cnts[j];
        } else if (idx == N_NODES) {
            g_rowptr[N_NODES] = run;
        }
    }
}
__global__ void k_scatter(const int* __restrict__ ei) {
    int e = blockIdx.x * blockDim.x + threadIdx.x;
    if (e >= N_EDGES) return;
    int src = ei[e];
    int dst = ei[N_EDGES + e];
    int pos = atomicAdd(&g_cursor[dst], 1);
    g_eid[pos] = e;
    g_esrc[pos] = src;
}

// ------- weight transpose + fp16 pack: WT[l][n][k/2 packed] ------------------
__global__ void k_transpose(const float* __restrict__ W) {
    __shared__ float t[32][33];
    int l = blockIdx.z;
    int k0 = blockIdx.y * 32, n0 = blockIdx.x * 32;
    int tx = threadIdx.x, ty = threadIdx.y;
    const float* Wl = W + (size_t)l * 1024 * 1024;
    #pragma unroll
    for (int i = 0; i < 4; i++)
        t[ty + i * 8][tx] = Wl[(size_t)(k0 + ty + i * 8) * 1024 + n0 + tx];
    __syncthreads();
    if (tx < 16) {
        uint32_t* Wh = g_WTh + (size_t)l * 1024 * 512;
        #pragma unroll
        for (int i = 0; i < 4; i++) {
            int nl = ty + i * 8;
            int n = n0 + nl;
            Wh[(size_t)n * 512 + (k0 >> 1) + tx] = packh2(t[2 * tx][nl], t[2 * tx + 1][nl]);
        }
    }
}

// ---------------- layer-0 GEMM: Th = fp16(x(N,7) @ w0(7,1024)) ----------------
__global__ void k_gemm0(const float* __restrict__ x, const float* __restrict__ w0) {
    __shared__ float xr[F_INP];
    int n = blockIdx.x, tid = threadIdx.x;
    if (tid < F_INP) xr[tid] = x[n * F_INP + tid];
    __syncthreads();
    int c0 = tid * 4;
    float acc[4] = {0.f, 0.f, 0.f, 0.f};
    #pragma unroll
    for (int d = 0; d < F_INP; d++) {
        float xv = xr[d];
        float4 w = *(const float4*)(w0 + d * HC + c0);
        acc[0] += xv * w.x; acc[1] += xv * w.y; acc[2] += xv * w.z; acc[3] += xv * w.w;
    }
    *(uint2*)&g_Th[(size_t)n * 512 + tid * 2] =
        make_uint2(packh2(acc[0], acc[1]), packh2(acc[2], acc[3]));
}

// =============== mma.sync fp16 GEMM (single term, cp.async, ldmatrix) =========
#define NCHUNK 32
#define SROWB 80                       // byte stride per m/n row in smem
#define OFF_A  0
#define OFF_B  10240
#define STG2   20480
#define GEMM_SMEM (2 * STG2)           // 40960 B

__global__ void __launch_bounds__(256, 2) k_mmagemm(int layer) {
    extern __shared__ char smem[];
    uint32_t sb = smem_u32(smem);
    int tid = threadIdx.x;
    int wid = tid >> 5;
    int lane = tid & 31;
    int g = lane >> 2, tig = lane & 3;
    int wm = wid >> 2;
    int wn = wid & 3;
    int m0 = blockIdx.y * 128;
    int n0 = blockIdx.x * 128;

    const uint32_t* Wh = g_WTh + (size_t)(layer - 1) * 1024 * 512;

    int lrow = tid & 127;
    int isB = tid >> 7;
    const uint32_t* gsrc = isB ? (Wh + (size_t)(n0 + lrow) * 512)
                               : (g_Xh + (size_t)(m0 + lrow) * 512);
    uint32_t dstrow = sb + (isB ? OFF_B : OFF_A) + lrow * SROWB;

    int q = lane >> 3, r = lane & 7;
    uint32_t aoff[4], boff[2];
    {
        int arow = (q & 1) * 8 + r;
        int acol = (q >> 1) * 16;
        #pragma unroll
        for (int mt = 0; mt < 4; mt++)
            aoff[mt] = (uint32_t)((wm * 64 + mt * 16 + arow) * SROWB + acol);
        int brow = (q >> 1) * 8 + r;
        int bcol = (q & 1) * 16;
        #pragma unroll
        for (int ntp = 0; ntp < 2; ntp++)
            boff[ntp] = (uint32_t)((wn * 32 + ntp * 16 + brow) * SROWB + bcol);
    }

    float acc[4][4][4];
    #pragma unroll
    for (int i = 0; i < 4; i++)
        #pragma unroll
        for (int j = 0; j < 4; j++)
            #pragma unroll
            for (int qq = 0; qq < 4; qq++) acc[i][j][qq] = 0.f;

    {
        cp16(dstrow + 0, gsrc);
        cp16(dstrow + 16, gsrc + 4);
        cp16(dstrow + 32, gsrc + 8);
        cp16(dstrow + 48, gsrc + 12);
        asm volatile("cp.async.commit_group;");
    }

    for (int c = 0; c < NCHUNK; c++) {
        if (c + 1 < NCHUNK) {
            uint32_t d = dstrow + ((c + 1) & 1) * STG2;
            const uint32_t* p = gsrc + (size_t)(c + 1) * 16;
            cp16(d + 0, p);
            cp16(d + 16, p + 4);
            cp16(d + 32, p + 8);
            cp16(d + 48, p + 12);
            asm volatile("cp.async.commit_group;");
            asm volatile("cp.async.wait_group 1;");
        } else {
            asm volatile("cp.async.wait_group 0;");
        }
        __syncthreads();

        uint32_t stq = sb + (c & 1) * STG2;
        #pragma unroll
        for (int ks = 0; ks < 2; ks++) {
            uint32_t kso = (uint32_t)(ks * 32);
            uint32_t bh[2][4];
            #pragma unroll
            for (int ntp = 0; ntp < 2; ntp++)
                ldsm4(bh[ntp], stq + OFF_B + boff[ntp] + kso);
            #pragma unroll
            for (int mt = 0; mt < 4; mt++) {
                uint32_t ah[4];
                ldsm4(ah, stq + OFF_A + aoff[mt] + kso);
                #pragma unroll
                for (int nt = 0; nt < 4; nt++) {
                    uint32_t b0 = bh[nt >> 1][(nt & 1) * 2 + 0];
                    uint32_t b1 = bh[nt >> 1][(nt & 1) * 2 + 1];
                    mma_f16(acc[mt][nt], ah[0], ah[1], ah[2], ah[3], b0, b1);
                }
            }
        }
        __syncthreads();
    }

    // epilogue: pack fp16 pairs (cols tig*2, tig*2+1 adjacent)
    #pragma unroll
    for (int mt = 0; mt < 4; mt++) {
        int row0 = m0 + wm * 64 + mt * 16 + g;
        #pragma unroll
        for (int nt = 0; nt < 4; nt++) {
            int colp = (n0 + wn * 32 + nt * 8 + tig * 2) >> 1;
            if (row0 < N_NODES)
                g_Th[(size_t)row0 * 512 + colp] = packh2(acc[mt][nt][0], acc[mt][nt][1]);
            if (row0 + 8 < N_NODES)
                g_Th[(size_t)(row0 + 8) * 512 + colp] = packh2(acc[mt][nt][2], acc[mt][nt][3]);
        }
    }
}

// ---------------- per-node alpha_src / alpha_dst (fp16 h) ---------------------
__global__ void k_alpha(const float* __restrict__ att_src, const float* __restrict__ att_dst, int l) {
    int n = blockIdx.x;
    int warp = threadIdx.x >> 5, lane = threadIdx.x & 31;
    const uint32_t* hr = g_Th + (size_t)n * 512 + warp * 128;
    const float* as = att_src + (size_t)l * HC + warp * CH;
    const float* ad = att_dst + (size_t)l * HC + warp * CH;
    int c8 = lane * 8;
    uint4 hv = *(const uint4*)(hr + lane * 4);
    float2 h0 = unpackh2(hv.x), h1 = unpackh2(hv.y), h2 = unpackh2(hv.z), h3 = unpackh2(hv.w);
    float4 a0 = *(const float4*)(as + c8);
    float4 a1 = *(const float4*)(as + c8 + 4);
    float4 d0 = *(const float4*)(ad + c8);
    float4 d1 = *(const float4*)(ad + c8 + 4);
    float s1 = h0.x * a0.x + h0.y * a0.y + h1.x * a0.z + h1.y * a0.w
             + h2.x * a1.x + h2.y * a1.y + h3.x * a1.z + h3.y * a1.w;
    float s2 = h0.x * d0.x + h0.y * d0.y + h1.x * d0.z + h1.y * d0.w
             + h2.x * d1.x + h2.y * d1.y + h3.x * d1.z + h3.y * d1.w;
    #pragma unroll
    for (int o = 16; o > 0; o >>= 1) {
        s1 += __shfl_down_sync(0xffffffffu, s1, o);
        s2 += __shfl_down_sync(0xffffffffu, s2, o);
    }
    if (lane == 0) {
        g_asrc[n * 4 + warp] = s1;
        g_adst[n * 4 + warp] = s2;
    }
}

// ---------------- precompute softmax attention weights ------------------------
__global__ void k_attw(int l) {
    int n = blockIdx.x * blockDim.x + threadIdx.x;
    if (n >= N_NODES) return;
    const float* ae = g_ae_all + (size_t)l * N_EDGES * 4;
    int s = g_rowptr[n], t = g_rowptr[n + 1];

    float4 ad4 = *(const float4*)&g_adst[n * 4];
    float4 as4 = *(const float4*)&g_asrc[n * 4];
    float ad[4] = {ad4.x, ad4.y, ad4.z, ad4.w};
    float aself[4], m[4];
    #pragma unroll
    for (int h = 0; h < 4; h++) {
        aself[h] = lrelu(((const float*)&as4)[h] + ad[h] + g_ae_self[l * 4 + h]);
        m[h] = aself[h];
    }
    for (int i = s; i < t; i++) {
        int e = g_eid[i], src = g_esrc[i];
        float4 av = *(const float4*)&g_asrc[src * 4];
        float4 ev = *(const float4*)&ae[e * 4];
        #pragma unroll
        for (int h = 0; h < 4; h++) {
            float a = lrelu(((const float*)&av)[h] + ad[h] + ((const float*)&ev)[h]);
            m[h] = fmaxf(m[h], a);
        }
    }
    float sum[4];
    #pragma unroll
    for (int h = 0; h < 4; h++) sum[h] = expf(aself[h] - m[h]);
    for (int i = s; i < t; i++) {
        int e = g_eid[i], src = g_esrc[i];
        float4 av = *(const float4*)&g_asrc[src * 4];
        float4 ev = *(const float4*)&ae[e * 4];
        #pragma unroll
        for (int h = 0; h < 4; h++) {
            float a = lrelu(((const float*)&av)[h] + ad[h] + ((const float*)&ev)[h]);
            sum[h] += expf(a - m[h]);
        }
    }
    float inv[4];
    #pragma unroll
    for (int h = 0; h < 4; h++) inv[h] = 1.f / (sum[h] + 1e-16f);

    float4 ws;
    ((float*)&ws)[0] = expf(aself[0] - m[0]) * inv[0];
    ((float*)&ws)[1] = expf(aself[1] - m[1]) * inv[1];
    ((float*)&ws)[2] = expf(aself[2] - m[2]) * inv[2];
    ((float*)&ws)[3] = expf(aself[3] - m[3]) * inv[3];
    *(float4*)&g_wself[n * 4] = ws;

    for (int i = s; i < t; i++) {
        int e = g_eid[i], src = g_esrc[i];
        float4 av = *(const float4*)&g_asrc[src * 4];
        float4 ev = *(const float4*)&ae[e * 4];
        float4 w;
        #pragma unroll
        for (int h = 0; h < 4; h++) {
            float a = lrelu(((const float*)&av)[h] + ad[h] + ((const float*)&ev)[h]);
            ((float*)&w)[h] = expf(a - m[h]) * inv[h];
        }
        *(float4*)&g_wedge[i * 4] = w;
    }
}

// ---------------- weighted gather + bias (+BN+ReLU), fp16 h -------------------
__global__ __launch_bounds__(256) void k_agg(
    int l, int concat,
    const float* __restrict__ bias012, const float* __restrict__ bias3,
    const float* __restrict__ gamma, const float* __restrict__ beta,
    const float* __restrict__ mean, const float* __restrict__ var) {
    int n = blockIdx.x;
    int tid = threadIdx.x;
    int s = g_rowptr[n], t = g_rowptr[n + 1];

    if (concat) {
        int head = tid >> 6;
        int c4 = (tid & 63) << 2;
        int f = head * CH + c4;
        int fp = f >> 1;                 // uint32 index (2 per thread)
        float wself = g_wself[n * 4 + head];
        uint2 hv = *(const uint2*)&g_Th[(size_t)n * 512 + fp];
        float2 v0 = unpackh2(hv.x), v1 = unpackh2(hv.y);
        float4 acc = make_float4(wself * v0.x, wself * v0.y, wself * v1.x, wself * v1.y);
        for (int i = s; i < t; i++) {
            int src = g_esrc[i];
            float w = g_wedge[i * 4 + head];
            uint2 sv = *(const uint2*)&g_Th[(size_t)src * 512 + fp];
            float2 s0 = unpackh2(sv.x), s1 = unpackh2(sv.y);
            acc.x += w * s0.x; acc.y += w * s0.y; acc.z += w * s1.x; acc.w += w * s1.y;
        }
        size_t pf = (size_t)l * HC + f;
        float4 bv = *(const float4*)(bias012 + pf);
        float4 gv = *(const float4*)(gamma + pf);
        float4 be = *(const float4*)(beta + pf);
        float4 mn = *(const float4*)(mean + pf);
        float4 vr = *(const float4*)(var + pf);
        float4 o;
        o.x = fmaxf((acc.x + bv.x - mn.x) * (gv.x * rsqrtf(vr.x + 1e-5f)) + be.x, 0.f);
        o.y = fmaxf((acc.y + bv.y - mn.y) * (gv.y * rsqrtf(vr.y + 1e-5f)) + be.y, 0.f);
        o.z = fmaxf((acc.z + bv.z - mn.z) * (gv.z * rsqrtf(vr.z + 1e-5f)) + be.z, 0.f);
        o.w = fmaxf((acc.w + bv.w - mn.w) * (gv.w * rsqrtf(vr.w + 1e-5f)) + be.w, 0.f);
        size_t pc = (size_t)n * 512 + fp;
        *(uint2*)&g_Xh[pc] = make_uint2(packh2(o.x, o.y), packh2(o.z, o.w));
    } else {
        int c = tid;
        float4 ws = *(const float4*)&g_wself[n * 4];
        const uint32_t* hn = g_Th + (size_t)n * 512;
        int ci = c >> 1, par = c & 1;
        float acc;
        {
            float2 p0 = unpackh2(hn[ci]);
            float2 p1 = unpackh2(hn[128 + ci]);
            float2 p2 = unpackh2(hn[256 + ci]);
            float2 p3 = unpackh2(hn[384 + ci]);
            acc = ws.x * (par ? p0.y : p0.x) + ws.y * (par ? p1.y : p1.x)
                + ws.z * (par ? p2.y : p2.x) + ws.w * (par ? p3.y : p3.x);
        }
        for (int i = s; i < t; i++) {
            int src = g_esrc[i];
            float4 w = *(const float4*)&g_wedge[i * 4];
            const uint32_t* hs = g_Th + (size_t)src * 512;
            float2 p0 = unpackh2(hs[ci]);
            float2 p1 = unpackh2(hs[128 + ci]);
            float2 p2 = unpackh2(hs[256 + ci]);
            float2 p3 = unpackh2(hs[384 + ci]);
            acc += w.x * (par ? p0.y : p0.x) + w.y * (par ? p1.y : p1.x)
                 + w.z * (par ? p2.y : p2.x) + w.w * (par ? p3.y : p3.x);
        }
        g_X[(size_t)n * CH + c] = 0.25f * acc + bias3[c];
    }
}

// ---------------- gate scores -------------------------------------------------
__global__ void k_gate(const float* __restrict__ gate_w, const float* __restrict__ gate_b) {
    int warp = threadIdx.x >> 5, lane = threadIdx.x & 31;
    int n = blockIdx.x * 8 + warp;
    if (n >= N_NODES) return;
    const float* hr = g_X + (size_t)n * CH;
    float s = 0.f;
    #pragma unroll
    for (int it = 0; it < 2; it++) {
        int c = (lane + it * 32) * 4;
        float4 v = *(const float4*)(hr + c);
        float4 w = *(const float4*)(gate_w + c);
        s += v.x * w.x + v.y * w.y + v.z * w.z + v.w * w.w;
    }
    #pragma unroll
    for (int o = 16; o > 0; o >>= 1) s += __shfl_down_sync(0xffffffffu, s, o);
    if (lane == 0) g_gate[n] = s + gate_b[0];
}

// ---------------- per-graph softmax pooling -----------------------------------
__device__ __forceinline__ int lb_batch(const int* __restrict__ batch, int target) {
    int lo = 0, hi = N_NODES;
    while (lo < hi) {
        int mid = (lo + hi) >> 1;
        if (batch[mid] < target) lo = mid + 1; else hi = mid;
    }
    return lo;
}
__global__ void k_pool(const int* __restrict__ batch) {
    int b = blockIdx.x;
    int c = threadIdx.x;
    int s = lb_batch(batch, b);
    int e = lb_batch(batch, b + 1);
    if (s == e) { g_graph[b * CH + c] = 0.f; return; }
    float mx = -1e30f;
    for (int n = s; n < e; n++) mx = fmaxf(mx, g_gate[n]);
    float sum = 0.f;
    for (int n = s; n < e; n++) sum += expf(g_gate[n] - mx);
    float inv = 1.f / (sum + 1e-16f);
    float acc = 0.f;
    for (int n = s; n < e; n++)
        acc += expf(g_gate[n] - mx) * inv * g_X[(size_t)n * CH + c];
    g_graph[b * CH + c] = acc;
}

// ---------------- final projection --------------------------------------------
__global__ __launch_bounds__(256) void k_proj(const float* __restrict__ proj_w,
                                              const float* __restrict__ proj_b,
                                              float* __restrict__ out) {
    __shared__ float sg[8][CH];
    int b0 = blockIdx.x * 8;
    int tid = threadIdx.x;
    #pragma unroll
    for (int g = 0; g < 8; g++) sg[g][tid] = g_graph[(b0 + g) * CH + tid];
    __syncthreads();
    float acc[8][4];
    #pragma unroll
    for (int g = 0; g < 8; g++)
        #pragma unroll
        for (int j = 0; j < 4; j++) acc[g][j] = 0.f;
    for (int cIt = 0; cIt < CH; cIt++) {
        float w0 = proj_w[cIt * 1024 + tid];
        float w1 = proj_w[cIt * 1024 + tid + 256];
        float w2 = proj_w[cIt * 1024 + tid + 512];
        float w3 = proj_w[cIt * 1024 + tid + 768];
        #pragma unroll
        for (int g = 0; g < 8; g++) {
            float sv = sg[g][cIt];
            acc[g][0] += sv * w0;
            acc[g][1] += sv * w1;
            acc[g][2] += sv * w2;
            acc[g][3] += sv * w3;
        }
    }
    #pragma unroll
    for (int g = 0; g < 8; g++)
        #pragma unroll
        for (int j = 0; j < 4; j++)
            out[(size_t)(b0 + g) * 1024 + tid + j * 256] = acc[g][j] + proj_b[tid + j * 256];
}

// ---------------- host orchestration ------------------------------------------
extern "C" void kernel_launch(void* const* d_in, const int* in_sizes, int n_in,
                              void* d_out, int out_size) {
    (void)in_sizes; (void)n_in; (void)out_size;
    const float* x        = (const float*)d_in[0];
    const int*   ei       = (const int*)d_in[1];
    const float* ea       = (const float*)d_in[2];
    const int*   batch    = (const int*)d_in[3];
    const float* w0       = (const float*)d_in[4];
    const float* w_rest   = (const float*)d_in[5];
    const float* w_edge   = (const float*)d_in[6];
    const float* att_src  = (const float*)d_in[7];
    const float* att_dst  = (const float*)d_in[8];
    const float* att_edge = (const float*)d_in[9];
    const float* bias012  = (const float*)d_in[10];
    const float* bias3    = (const float*)d_in[11];
    const float* bn_gamma = (const float*)d_in[12];
    const float* bn_beta  = (const float*)d_in[13];
    const float* bn_mean  = (const float*)d_in[14];
    const float* bn_var   = (const float*)d_in[15];
    const float* gate_w   = (const float*)d_in[16];
    const float* gate_b   = (const float*)d_in[17];
    const float* proj_w   = (const float*)d_in[18];
    const float* proj_b   = (const float*)d_in[19];
    float* out = (float*)d_out;

    cudaFuncSetAttribute(k_mmagemm, cudaFuncAttributeMaxDynamicSharedMemorySize, GEMM_SMEM);

    k_zero_cnt<<<(N_NODES + 255) / 256, 256>>>();
    k_count<<<(N_EDGES + 255) / 256, 256>>>(ei);
    k_scan<<<1, 1024>>>();
    k_scatter<<<(N_EDGES + 255) / 256, 256>>>(ei);
    k_transpose<<<dim3(32, 32, 3), dim3(32, 8)>>>(w_rest);
    k_gemm0<<<N_NODES, 256>>>(x, w0);
    k_meanve<<<1, 256>>>(ea, w_edge, att_edge);
    k_ae_all<<<(N_EDGES + 127) / 128, 128>>>(ea);

    for (int l = 0; l < 4; l++) {
        if (l > 0) {
            k_mmagemm<<<dim3(8, (N_NODES + 127) / 128), 256, GEMM_SMEM>>>(l);
        }
        k_alpha<<<N_NODES, 128>>>(att_src, att_dst, l);
        k_attw<<<(N_NODES + 255) / 256, 256>>>(l);
        k_agg<<<N_NODES, 256>>>(l, l < 3 ? 1 : 0, bias012, bias3,
                                bn_gamma, bn_beta, bn_mean, bn_var);
    }

    k_gate<<<(N_NODES + 7) / 8, 256>>>(gate_w, gate_b);
    k_pool<<<N_GRAPH, 256>>>(batch);
    k_proj<<<N_GRAPH / 8, 256>>>(proj_w, proj_b, out);
}

// round 9
// speedup vs baseline: 4.0573x; 1.0917x over previous
#include <cuda_runtime.h>
#include <cuda_fp16.h>
#include <cstdint>
#include <math.h>

#define N_NODES 20000
#define N_PAD   20096            // 157 * 128
#define N_EDGES 60000
#define N_GRAPH 512
#define F_INP   7
#define HC      1024
#define NH      4
#define CH      256

// ---------------- scratch (static device globals; no allocation) -------------
__device__ float    g_X[(size_t)N_NODES * CH];     // final-layer output (l=3)
__device__ uint32_t g_Th[(size_t)N_PAD * 512];     // h = X@W, fp16 packed pairs
__device__ uint32_t g_Xh[(size_t)N_PAD * 512];     // next-layer GEMM input (fp16)
__device__ uint32_t g_WTh[3 * 1024 * 512];         // weight^T fp16 packed pairs
__device__ float    g_asrc[N_NODES * NH];
__device__ float    g_adst[N_NODES * NH];
__device__ float    g_ae_all[4 * N_EDGES * NH];
__device__ float    g_ve[48];
__device__ float    g_ae_self[16];
__device__ float    g_eamean[3];
__device__ int      g_cnt[N_NODES];
__device__ int      g_rowptr[N_NODES + 1];
__device__ int      g_cursor[N_NODES];
__device__ int      g_eid[N_EDGES];
__device__ int      g_esrc[N_EDGES];
__device__ float    g_wedge[N_EDGES * NH];
__device__ float    g_wself[N_NODES * NH];
__device__ float    g_gate[N_NODES];
__device__ float    g_graph[N_GRAPH * CH];

__device__ __forceinline__ float lrelu(float a) { return a > 0.f ? a : 0.2f * a; }

__device__ __forceinline__ uint32_t packh2(float x, float y) {
    __half2 h = __floats2half2_rn(x, y);
    return *(uint32_t*)&h;
}
__device__ __forceinline__ float2 unpackh2(uint32_t u) {
    return __half22float2(*(__half2*)&u);
}

__device__ __forceinline__ uint32_t smem_u32(const void* p) {
    uint32_t a;
    asm("{ .reg .u64 t; cvta.to.shared.u64 t, %1; cvt.u32.u64 %0, t; }" : "=r"(a) : "l"(p));
    return a;
}
__device__ __forceinline__ void cp16(uint32_t dst, const void* src) {
    asm volatile("cp.async.cg.shared.global [%0], [%1], 16;" :: "r"(dst), "l"(src));
}
__device__ __forceinline__ void ldsm4(uint32_t* d, uint32_t addr) {
    asm volatile("ldmatrix.sync.aligned.m8n8.x4.shared.b16 {%0,%1,%2,%3}, [%4];"
                 : "=r"(d[0]), "=r"(d[1]), "=r"(d[2]), "=r"(d[3]) : "r"(addr));
}
__device__ __forceinline__ void mma_f16(float* c, uint32_t a0, uint32_t a1,
                                        uint32_t a2, uint32_t a3,
                                        uint32_t b0, uint32_t b1) {
    asm volatile(
        "mma.sync.aligned.m16n8k16.row.col.f32.f16.f16.f32 "
        "{%0,%1,%2,%3}, {%4,%5,%6,%7}, {%8,%9}, {%0,%1,%2,%3};"
        : "+f"(c[0]), "+f"(c[1]), "+f"(c[2]), "+f"(c[3])
        : "r"(a0), "r"(a1), "r"(a2), "r"(a3), "r"(b0), "r"(b1));
}

// ---------------- edge_attr mean + ve + self-loop attention (fused) ----------
__global__ void k_meanve(const float* __restrict__ ea,
                         const float* __restrict__ w_edge,
                         const float* __restrict__ att_edge) {
    __shared__ float red[3][256];
    int tid = threadIdx.x;
    float a0 = 0.f, a1 = 0.f, a2 = 0.f;
    for (int e = tid; e < N_EDGES; e += 256) {
        a0 += ea[e * 3 + 0]; a1 += ea[e * 3 + 1]; a2 += ea[e * 3 + 2];
    }
    red[0][tid] = a0; red[1][tid] = a1; red[2][tid] = a2;
    __syncthreads();
    for (int s = 128; s > 0; s >>= 1) {
        if (tid < s) {
            red[0][tid] += red[0][tid + s];
            red[1][tid] += red[1][tid + s];
            red[2][tid] += red[2][tid + s];
        }
        __syncthreads();
    }
    if (tid < 3) g_eamean[tid] = red[tid][0] * (1.f / (float)N_EDGES);
    __syncthreads();

    int warp = tid >> 5, lane = tid & 31;
    for (int idx = warp; idx < 48; idx += 8) {
        int l = idx / 12, r = idx % 12, d = r / 4, h = r % 4;
        const float* w = w_edge + (size_t)l * 3 * HC + (size_t)d * HC + h * CH;
        const float* a = att_edge + (size_t)l * HC + h * CH;
        float s = 0.f;
        for (int c = lane; c < CH; c += 32) s += w[c] * a[c];
        #pragma unroll
        for (int o = 16; o > 0; o >>= 1) s += __shfl_down_sync(0xffffffffu, s, o);
        if (lane == 0) g_ve[idx] = s;
    }
    __syncthreads();
    if (tid < 16) {
        int l = tid >> 2, h = tid & 3;
        float s = 0.f;
        for (int d = 0; d < 3; d++) s += g_eamean[d] * g_ve[l * 12 + d * 4 + h];
        g_ae_self[tid] = s;
    }
}

__global__ void k_ae_all(const float* __restrict__ ea) {
    int e = blockIdx.x * blockDim.x + threadIdx.x;
    if (e >= N_EDGES) return;
    float a0 = ea[e * 3 + 0], a1 = ea[e * 3 + 1], a2 = ea[e * 3 + 2];
    #pragma unroll
    for (int l = 0; l < 4; l++) {
        float4 v;
        v.x = a0 * g_ve[l * 12 + 0] + a1 * g_ve[l * 12 + 4] + a2 * g_ve[l * 12 + 8];
        v.y = a0 * g_ve[l * 12 + 1] + a1 * g_ve[l * 12 + 5] + a2 * g_ve[l * 12 + 9];
        v.z = a0 * g_ve[l * 12 + 2] + a1 * g_ve[l * 12 + 6] + a2 * g_ve[l * 12 + 10];
        v.w = a0 * g_ve[l * 12 + 3] + a1 * g_ve[l * 12 + 7] + a2 * g_ve[l * 12 + 11];
        *(float4*)&g_ae_all[(size_t)l * N_EDGES * 4 + e * 4] = v;
    }
}

// ---------------- CSR build ---------------------------------------------------
__global__ void k_zero_cnt() {
    int n = blockIdx.x * blockDim.x + threadIdx.x;
    if (n < N_NODES) g_cnt[n] = 0;
}
__global__ void k_count(const int* __restrict__ ei) {
    int e = blockIdx.x * blockDim.x + threadIdx.x;
    if (e >= N_EDGES) return;
    atomicAdd(&g_cnt[ei[N_EDGES + e]], 1);
}
__global__ void k_scan() {
    __shared__ int ssum[1024];
    const int SEG = 20;
    int tid = threadIdx.x;
    int base = tid * SEG;
    int cnts[SEG];
    int tot = 0;
    #pragma unroll
    for (int j = 0; j < SEG; j++) {
        int idx = base + j;
        cnts[j] = (idx < N_NODES) ? g_cnt[idx] : 0;
        tot += cnts[j];
    }
    ssum[tid] = tot;
    __syncthreads();
    for (int off = 1; off < 1024; off <<= 1) {
        int v = (tid >= off) ? ssum[tid - off] : 0;
        __syncthreads();
        ssum[tid] += v;
        __syncthreads();
    }
    int run = ssum[tid] - tot;
    #pragma unroll
    for (int j = 0; j < SEG; j++) {
        int idx = base + j;
        if (idx < N_NODES) {
            g_rowptr[idx] = run;
            g_cursor[idx] = run;
            run += cnts[j];
        } else if (idx == N_NODES) {
            g_rowptr[N_NODES] = run;
        }
    }
}
__global__ void k_scatter(const int* __restrict__ ei) {
    int e = blockIdx.x * blockDim.x + threadIdx.x;
    if (e >= N_EDGES) return;
    int src = ei[e];
    int dst = ei[N_EDGES + e];
    int pos = atomicAdd(&g_cursor[dst], 1);
    g_eid[pos] = e;
    g_esrc[pos] = src;
}
__global__ void k_zero_alpha() {
    int i = blockIdx.x * blockDim.x + threadIdx.x;
    if (i < N_NODES * NH) { g_asrc[i] = 0.f; g_adst[i] = 0.f; }
}

// ------- weight transpose + fp16 pack: WT[l][n][k/2 packed] ------------------
__global__ void k_transpose(const float* __restrict__ W) {
    __shared__ float t[32][33];
    int l = blockIdx.z;
    int k0 = blockIdx.y * 32, n0 = blockIdx.x * 32;
    int tx = threadIdx.x, ty = threadIdx.y;
    const float* Wl = W + (size_t)l * 1024 * 1024;
    #pragma unroll
    for (int i = 0; i < 4; i++)
        t[ty + i * 8][tx] = Wl[(size_t)(k0 + ty + i * 8) * 1024 + n0 + tx];
    __syncthreads();
    if (tx < 16) {
        uint32_t* Wh = g_WTh + (size_t)l * 1024 * 512;
        #pragma unroll
        for (int i = 0; i < 4; i++) {
            int nl = ty + i * 8;
            int n = n0 + nl;
            Wh[(size_t)n * 512 + (k0 >> 1) + tx] = packh2(t[2 * tx][nl], t[2 * tx + 1][nl]);
        }
    }
}

// -------- layer-0 GEMM + fused alpha: Th = fp16(x @ w0); asrc/adst ------------
__global__ void k_gemm0(const float* __restrict__ x, const float* __restrict__ w0,
                        const float* __restrict__ att_src, const float* __restrict__ att_dst) {
    __shared__ float xr[F_INP];
    __shared__ float sa[8], sd[8];
    int n = blockIdx.x, tid = threadIdx.x;
    int warp = tid >> 5, lane = tid & 31;
    if (tid < F_INP) xr[tid] = x[n * F_INP + tid];
    __syncthreads();
    int c0 = tid * 4;
    float acc[4] = {0.f, 0.f, 0.f, 0.f};
    #pragma unroll
    for (int d = 0; d < F_INP; d++) {
        float xv = xr[d];
        float4 w = *(const float4*)(w0 + d * HC + c0);
        acc[0] += xv * w.x; acc[1] += xv * w.y; acc[2] += xv * w.z; acc[3] += xv * w.w;
    }
    *(uint2*)&g_Th[(size_t)n * 512 + tid * 2] =
        make_uint2(packh2(acc[0], acc[1]), packh2(acc[2], acc[3]));
    // fused alpha: warp w covers cols w*128..w*128+127 → head = w>>1
    float4 a = *(const float4*)(att_src + c0);
    float4 d = *(const float4*)(att_dst + c0);
    float s1 = acc[0] * a.x + acc[1] * a.y + acc[2] * a.z + acc[3] * a.w;
    float s2 = acc[0] * d.x + acc[1] * d.y + acc[2] * d.z + acc[3] * d.w;
    #pragma unroll
    for (int o = 16; o > 0; o >>= 1) {
        s1 += __shfl_down_sync(0xffffffffu, s1, o);
        s2 += __shfl_down_sync(0xffffffffu, s2, o);
    }
    if (lane == 0) { sa[warp] = s1; sd[warp] = s2; }
    __syncthreads();
    if (tid < 4) {
        g_asrc[n * 4 + tid] = sa[2 * tid] + sa[2 * tid + 1];
        g_adst[n * 4 + tid] = sd[2 * tid] + sd[2 * tid + 1];
    }
}

// ===== mma.sync fp16 GEMM, 4-stage cp.async ring, fused alpha epilogue ========
#define NCHUNK 32
#define SROWB 80                       // byte stride per m/n row in smem
#define OFF_A  0
#define OFF_B  10240
#define NSTAGE 4
#define STG    20480
#define GEMM_SMEM (NSTAGE * STG)       // 81920 B

__global__ void __launch_bounds__(256, 2) k_mmagemm(int layer,
                                                    const float* __restrict__ att_src,
                                                    const float* __restrict__ att_dst) {
    extern __shared__ char smem[];
    uint32_t sb = smem_u32(smem);
    int tid = threadIdx.x;
    int wid = tid >> 5;
    int lane = tid & 31;
    int g = lane >> 2, tig = lane & 3;
    int wm = wid >> 2;
    int wn = wid & 3;
    int m0 = blockIdx.y * 128;
    int n0 = blockIdx.x * 128;

    const uint32_t* Wh = g_WTh + (size_t)(layer - 1) * 1024 * 512;

    int lrow = tid & 127;
    int isB = tid >> 7;
    const uint32_t* gsrc = isB ? (Wh + (size_t)(n0 + lrow) * 512)
                               : (g_Xh + (size_t)(m0 + lrow) * 512);
    uint32_t dstrow = sb + (isB ? OFF_B : OFF_A) + lrow * SROWB;

    int q = lane >> 3, r = lane & 7;
    uint32_t aoff[4], boff[2];
    {
        int arow = (q & 1) * 8 + r;
        int acol = (q >> 1) * 16;
        #pragma unroll
        for (int mt = 0; mt < 4; mt++)
            aoff[mt] = (uint32_t)((wm * 64 + mt * 16 + arow) * SROWB + acol);
        int brow = (q >> 1) * 8 + r;
        int bcol = (q & 1) * 16;
        #pragma unroll
        for (int ntp = 0; ntp < 2; ntp++)
            boff[ntp] = (uint32_t)((wn * 32 + ntp * 16 + brow) * SROWB + bcol);
    }

    float acc[4][4][4];
    #pragma unroll
    for (int i = 0; i < 4; i++)
        #pragma unroll
        for (int j = 0; j < 4; j++)
            #pragma unroll
            for (int qq = 0; qq < 4; qq++) acc[i][j][qq] = 0.f;

    // prologue: fill stages 0..NSTAGE-2
    #pragma unroll
    for (int s = 0; s < NSTAGE - 1; s++) {
        uint32_t d = dstrow + s * STG;
        const uint32_t* p = gsrc + (size_t)s * 16;
        cp16(d + 0, p);
        cp16(d + 16, p + 4);
        cp16(d + 32, p + 8);
        cp16(d + 48, p + 12);
        asm volatile("cp.async.commit_group;");
    }

    for (int c = 0; c < NCHUNK; c++) {
        asm volatile("cp.async.wait_group %0;" :: "n"(NSTAGE - 2));
        __syncthreads();
        int cn = c + NSTAGE - 1;
        if (cn < NCHUNK) {
            uint32_t d = dstrow + (cn & (NSTAGE - 1)) * STG;
            const uint32_t* p = gsrc + (size_t)cn * 16;
            cp16(d + 0, p);
            cp16(d + 16, p + 4);
            cp16(d + 32, p + 8);
            cp16(d + 48, p + 12);
        }
        asm volatile("cp.async.commit_group;");

        uint32_t stq = sb + (c & (NSTAGE - 1)) * STG;
        #pragma unroll
        for (int ks = 0; ks < 2; ks++) {
            uint32_t kso = (uint32_t)(ks * 32);
            uint32_t bh[2][4];
            #pragma unroll
            for (int ntp = 0; ntp < 2; ntp++)
                ldsm4(bh[ntp], stq + OFF_B + boff[ntp] + kso);
            #pragma unroll
            for (int mt = 0; mt < 4; mt++) {
                uint32_t ah[4];
                ldsm4(ah, stq + OFF_A + aoff[mt] + kso);
                #pragma unroll
                for (int nt = 0; nt < 4; nt++) {
                    uint32_t b0 = bh[nt >> 1][(nt & 1) * 2 + 0];
                    uint32_t b1 = bh[nt >> 1][(nt & 1) * 2 + 1];
                    mma_f16(acc[mt][nt], ah[0], ah[1], ah[2], ah[3], b0, b1);
                }
            }
        }
    }

    // ---- epilogue: store fp16 h and fused alpha partials -----------------
    int head = n0 >> 8;
    const float* as = att_src + (size_t)layer * HC;
    const float* ad = att_dst + (size_t)layer * HC;

    float pa[4] = {0, 0, 0, 0}, pd[4] = {0, 0, 0, 0};
    float pa8[4] = {0, 0, 0, 0}, pd8[4] = {0, 0, 0, 0};
    #pragma unroll
    for (int nt = 0; nt < 4; nt++) {
        int col = n0 + wn * 32 + nt * 8 + tig * 2;
        float2 a2 = *(const float2*)(as + col);
        float2 d2 = *(const float2*)(ad + col);
        #pragma unroll
        for (int mt = 0; mt < 4; mt++) {
            pa[mt]  += acc[mt][nt][0] * a2.x + acc[mt][nt][1] * a2.y;
            pd[mt]  += acc[mt][nt][0] * d2.x + acc[mt][nt][1] * d2.y;
            pa8[mt] += acc[mt][nt][2] * a2.x + acc[mt][nt][3] * a2.y;
            pd8[mt] += acc[mt][nt][2] * d2.x + acc[mt][nt][3] * d2.y;
        }
    }
    #pragma unroll
    for (int mt = 0; mt < 4; mt++) {
        #pragma unroll
        for (int o = 1; o <= 2; o <<= 1) {
            pa[mt]  += __shfl_xor_sync(0xffffffffu, pa[mt], o);
            pd[mt]  += __shfl_xor_sync(0xffffffffu, pd[mt], o);
            pa8[mt] += __shfl_xor_sync(0xffffffffu, pa8[mt], o);
            pd8[mt] += __shfl_xor_sync(0xffffffffu, pd8[mt], o);
        }
    }

    #pragma unroll
    for (int mt = 0; mt < 4; mt++) {
        int row0 = m0 + wm * 64 + mt * 16 + g;
        #pragma unroll
        for (int nt = 0; nt < 4; nt++) {
            int colp = (n0 + wn * 32 + nt * 8 + tig * 2) >> 1;
            if (row0 < N_NODES)
                g_Th[(size_t)row0 * 512 + colp] = packh2(acc[mt][nt][0], acc[mt][nt][1]);
            if (row0 + 8 < N_NODES)
                g_Th[(size_t)(row0 + 8) * 512 + colp] = packh2(acc[mt][nt][2], acc[mt][nt][3]);
        }
        if (tig == 0) {
            if (row0 < N_NODES) {
                atomicAdd(&g_asrc[row0 * 4 + head], pa[mt]);
                atomicAdd(&g_adst[row0 * 4 + head], pd[mt]);
            }
            if (row0 + 8 < N_NODES) {
                atomicAdd(&g_asrc[(row0 + 8) * 4 + head], pa8[mt]);
                atomicAdd(&g_adst[(row0 + 8) * 4 + head], pd8[mt]);
            }
        }
    }
}

// ---------------- precompute softmax attention weights ------------------------
__global__ void k_attw(int l) {
    int n = blockIdx.x * blockDim.x + threadIdx.x;
    if (n >= N_NODES) return;
    const float* ae = g_ae_all + (size_t)l * N_EDGES * 4;
    int s = g_rowptr[n], t = g_rowptr[n + 1];

    float4 ad4 = *(const float4*)&g_adst[n * 4];
    float4 as4 = *(const float4*)&g_asrc[n * 4];
    float ad[4] = {ad4.x, ad4.y, ad4.z, ad4.w};
    float aself[4], m[4];
    #pragma unroll
    for (int h = 0; h < 4; h++) {
        aself[h] = lrelu(((const float*)&as4)[h] + ad[h] + g_ae_self[l * 4 + h]);
        m[h] = aself[h];
    }
    for (int i = s; i < t; i++) {
        int e = g_eid[i], src = g_esrc[i];
        float4 av = *(const float4*)&g_asrc[src * 4];
        float4 ev = *(const float4*)&ae[e * 4];
        #pragma unroll
        for (int h = 0; h < 4; h++) {
            float a = lrelu(((const float*)&av)[h] + ad[h] + ((const float*)&ev)[h]);
            m[h] = fmaxf(m[h], a);
        }
    }
    float sum[4];
    #pragma unroll
    for (int h = 0; h < 4; h++) sum[h] = expf(aself[h] - m[h]);
    for (int i = s; i < t; i++) {
        int e = g_eid[i], src = g_esrc[i];
        float4 av = *(const float4*)&g_asrc[src * 4];
        float4 ev = *(const float4*)&ae[e * 4];
        #pragma unroll
        for (int h = 0; h < 4; h++) {
            float a = lrelu(((const float*)&av)[h] + ad[h] + ((const float*)&ev)[h]);
            sum[h] += expf(a - m[h]);
        }
    }
    float inv[4];
    #pragma unroll
    for (int h = 0; h < 4; h++) inv[h] = 1.f / (sum[h] + 1e-16f);

    float4 ws;
    ((float*)&ws)[0] = expf(aself[0] - m[0]) * inv[0];
    ((float*)&ws)[1] = expf(aself[1] - m[1]) * inv[1];
    ((float*)&ws)[2] = expf(aself[2] - m[2]) * inv[2];
    ((float*)&ws)[3] = expf(aself[3] - m[3]) * inv[3];
    *(float4*)&g_wself[n * 4] = ws;

    for (int i = s; i < t; i++) {
        int e = g_eid[i], src = g_esrc[i];
        float4 av = *(const float4*)&g_asrc[src * 4];
        float4 ev = *(const float4*)&ae[e * 4];
        float4 w;
        #pragma unroll
        for (int h = 0; h < 4; h++) {
            float a = lrelu(((const float*)&av)[h] + ad[h] + ((const float*)&ev)[h]);
            ((float*)&w)[h] = expf(a - m[h]) * inv[h];
        }
        *(float4*)&g_wedge[i * 4] = w;
    }
}

// ---------------- weighted gather + bias (+BN+ReLU), fp16 h -------------------
__global__ __launch_bounds__(256) void k_agg(
    int l, int concat,
    const float* __restrict__ bias012, const float* __restrict__ bias3,
    const float* __restrict__ gamma, const float* __restrict__ beta,
    const float* __restrict__ mean, const float* __restrict__ var) {
    int n = blockIdx.x;
    int tid = threadIdx.x;
    int s = g_rowptr[n], t = g_rowptr[n + 1];

    if (concat) {
        int head = tid >> 6;
        int c4 = (tid & 63) << 2;
        int f = head * CH + c4;
        int fp = f >> 1;
        float wself = g_wself[n * 4 + head];
        uint2 hv = *(const uint2*)&g_Th[(size_t)n * 512 + fp];
        float2 v0 = unpackh2(hv.x), v1 = unpackh2(hv.y);
        float4 acc = make_float4(wself * v0.x, wself * v0.y, wself * v1.x, wself * v1.y);
        for (int i = s; i < t; i++) {
            int src = g_esrc[i];
            float w = g_wedge[i * 4 + head];
            uint2 sv = *(const uint2*)&g_Th[(size_t)src * 512 + fp];
            float2 s0 = unpackh2(sv.x), s1 = unpackh2(sv.y);
            acc.x += w * s0.x; acc.y += w * s0.y; acc.z += w * s1.x; acc.w += w * s1.y;
        }
        size_t pf = (size_t)l * HC + f;
        float4 bv = *(const float4*)(bias012 + pf);
        float4 gv = *(const float4*)(gamma + pf);
        float4 be = *(const float4*)(beta + pf);
        float4 mn = *(const float4*)(mean + pf);
        float4 vr = *(const float4*)(var + pf);
        float4 o;
        o.x = fmaxf((acc.x + bv.x - mn.x) * (gv.x * rsqrtf(vr.x + 1e-5f)) + be.x, 0.f);
        o.y = fmaxf((acc.y + bv.y - mn.y) * (gv.y * rsqrtf(vr.y + 1e-5f)) + be.y, 0.f);
        o.z = fmaxf((acc.z + bv.z - mn.z) * (gv.z * rsqrtf(vr.z + 1e-5f)) + be.z, 0.f);
        o.w = fmaxf((acc.w + bv.w - mn.w) * (gv.w * rsqrtf(vr.w + 1e-5f)) + be.w, 0.f);
        size_t pc = (size_t)n * 512 + fp;
        *(uint2*)&g_Xh[pc] = make_uint2(packh2(o.x, o.y), packh2(o.z, o.w));
    } else {
        int c = tid;
        float4 ws = *(const float4*)&g_wself[n * 4];
        const uint32_t* hn = g_Th + (size_t)n * 512;
        int ci = c >> 1, par = c & 1;
        float acc;
        {
            float2 p0 = unpackh2(hn[ci]);
            float2 p1 = unpackh2(hn[128 + ci]);
            float2 p2 = unpackh2(hn[256 + ci]);
            float2 p3 = unpackh2(hn[384 + ci]);
            acc = ws.x * (par ? p0.y : p0.x) + ws.y * (par ? p1.y : p1.x)
                + ws.z * (par ? p2.y : p2.x) + ws.w * (par ? p3.y : p3.x);
        }
        for (int i = s; i < t; i++) {
            int src = g_esrc[i];
            float4 w = *(const float4*)&g_wedge[i * 4];
            const uint32_t* hs = g_Th + (size_t)src * 512;
            float2 p0 = unpackh2(hs[ci]);
            float2 p1 = unpackh2(hs[128 + ci]);
            float2 p2 = unpackh2(hs[256 + ci]);
            float2 p3 = unpackh2(hs[384 + ci]);
            acc += w.x * (par ? p0.y : p0.x) + w.y * (par ? p1.y : p1.x)
                 + w.z * (par ? p2.y : p2.x) + w.w * (par ? p3.y : p3.x);
        }
        g_X[(size_t)n * CH + c] = 0.25f * acc + bias3[c];
    }
}

// ---------------- gate scores -------------------------------------------------
__global__ void k_gate(const float* __restrict__ gate_w, const float* __restrict__ gate_b) {
    int warp = threadIdx.x >> 5, lane = threadIdx.x & 31;
    int n = blockIdx.x * 8 + warp;
    if (n >= N_NODES) return;
    const float* hr = g_X + (size_t)n * CH;
    float s = 0.f;
    #pragma unroll
    for (int it = 0; it < 2; it++) {
        int c = (lane + it * 32) * 4;
        float4 v = *(const float4*)(hr + c);
        float4 w = *(const float4*)(gate_w + c);
        s += v.x * w.x + v.y * w.y + v.z * w.z + v.w * w.w;
    }
    #pragma unroll
    for (int o = 16; o > 0; o >>= 1) s += __shfl_down_sync(0xffffffffu, s, o);
    if (lane == 0) g_gate[n] = s + gate_b[0];
}

// ---------------- per-graph softmax pooling -----------------------------------
__device__ __forceinline__ int lb_batch(const int* __restrict__ batch, int target) {
    int lo = 0, hi = N_NODES;
    while (lo < hi) {
        int mid = (lo + hi) >> 1;
        if (batch[mid] < target) lo = mid + 1; else hi = mid;
    }
    return lo;
}
__global__ void k_pool(const int* __restrict__ batch) {
    int b = blockIdx.x;
    int c = threadIdx.x;
    int s = lb_batch(batch, b);
    int e = lb_batch(batch, b + 1);
    if (s == e) { g_graph[b * CH + c] = 0.f; return; }
    float mx = -1e30f;
    for (int n = s; n < e; n++) mx = fmaxf(mx, g_gate[n]);
    float sum = 0.f;
    for (int n = s; n < e; n++) sum += expf(g_gate[n] - mx);
    float inv = 1.f / (sum + 1e-16f);
    float acc = 0.f;
    for (int n = s; n < e; n++)
        acc += expf(g_gate[n] - mx) * inv * g_X[(size_t)n * CH + c];
    g_graph[b * CH + c] = acc;
}

// ---------------- final projection --------------------------------------------
__global__ __launch_bounds__(256) void k_proj(const float* __restrict__ proj_w,
                                              const float* __restrict__ proj_b,
                                              float* __restrict__ out) {
    __shared__ float sg[8][CH];
    int b0 = blockIdx.x * 8;
    int tid = threadIdx.x;
    #pragma unroll
    for (int g = 0; g < 8; g++) sg[g][tid] = g_graph[(b0 + g) * CH + tid];
    __syncthreads();
    float acc[8][4];
    #pragma unroll
    for (int g = 0; g < 8; g++)
        #pragma unroll
        for (int j = 0; j < 4; j++) acc[g][j] = 0.f;
    for (int cIt = 0; cIt < CH; cIt++) {
        float w0 = proj_w[cIt * 1024 + tid];
        float w1 = proj_w[cIt * 1024 + tid + 256];
        float w2 = proj_w[cIt * 1024 + tid + 512];
        float w3 = proj_w[cIt * 1024 + tid + 768];
        #pragma unroll
        for (int g = 0; g < 8; g++) {
            float sv = sg[g][cIt];
            acc[g][0] += sv * w0;
            acc[g][1] += sv * w1;
            acc[g][2] += sv * w2;
            acc[g][3] += sv * w3;
        }
    }
    #pragma unroll
    for (int g = 0; g < 8; g++)
        #pragma unroll
        for (int j = 0; j < 4; j++)
            out[(size_t)(b0 + g) * 1024 + tid + j * 256] = acc[g][j] + proj_b[tid + j * 256];
}

// ---------------- host orchestration ------------------------------------------
extern "C" void kernel_launch(void* const* d_in, const int* in_sizes, int n_in,
                              void* d_out, int out_size) {
    (void)in_sizes; (void)n_in; (void)out_size;
    const float* x        = (const float*)d_in[0];
    const int*   ei       = (const int*)d_in[1];
    const float* ea       = (const float*)d_in[2];
    const int*   batch    = (const int*)d_in[3];
    const float* w0       = (const float*)d_in[4];
    const float* w_rest   = (const float*)d_in[5];
    const float* w_edge   = (const float*)d_in[6];
    const float* att_src  = (const float*)d_in[7];
    const float* att_dst  = (const float*)d_in[8];
    const float* att_edge = (const float*)d_in[9];
    const float* bias012  = (const float*)d_in[10];
    const float* bias3    = (const float*)d_in[11];
    const float* bn_gamma = (const float*)d_in[12];
    const float* bn_beta  = (const float*)d_in[13];
    const float* bn_mean  = (const float*)d_in[14];
    const float* bn_var   = (const float*)d_in[15];
    const float* gate_w   = (const float*)d_in[16];
    const float* gate_b   = (const float*)d_in[17];
    const float* proj_w   = (const float*)d_in[18];
    const float* proj_b   = (const float*)d_in[19];
    float* out = (float*)d_out;

    cudaFuncSetAttribute(k_mmagemm, cudaFuncAttributeMaxDynamicSharedMemorySize, GEMM_SMEM);

    k_zero_cnt<<<(N_NODES + 255) / 256, 256>>>();
    k_count<<<(N_EDGES + 255) / 256, 256>>>(ei);
    k_scan<<<1, 1024>>>();
    k_scatter<<<(N_EDGES + 255) / 256, 256>>>(ei);
    k_transpose<<<dim3(32, 32, 3), dim3(32, 8)>>>(w_rest);
    k_gemm0<<<N_NODES, 256>>>(x, w0, att_src, att_dst);
    k_meanve<<<1, 256>>>(ea, w_edge, att_edge);
    k_ae_all<<<(N_EDGES + 127) / 128, 128>>>(ea);

    for (int l = 0; l < 4; l++) {
        if (l > 0) {
            k_zero_alpha<<<(N_NODES * NH + 255) / 256, 256>>>();
            k_mmagemm<<<dim3(8, (N_NODES + 127) / 128), 256, GEMM_SMEM>>>(l, att_src, att_dst);
        }
        k_attw<<<(N_NODES + 255) / 256, 256>>>(l);
        k_agg<<<N_NODES, 256>>>(l, l < 3 ? 1 : 0, bias012, bias3,
                                bn_gamma, bn_beta, bn_mean, bn_var);
    }

    k_gate<<<(N_NODES + 7) / 8, 256>>>(gate_w, gate_b);
    k_pool<<<N_GRAPH, 256>>>(batch);
    k_proj<<<N_GRAPH / 8, 256>>>(proj_w, proj_b, out);
}